// round 10
// baseline (speedup 1.0000x reference)
#include <cuda_runtime.h>
#include <cuda_bf16.h>
#include <cstdint>

#define NV 20000
#define NC 84000
#define NG 200
#define NE 252000
#define RNDS 8
#define CEILDIV(a,b) (((a)+(b)-1)/(b))
#define SB 20    // staged-B row stride (words)
#define SAW 68   // full-width A row stride (words)
#define GC 657   // CEILDIV(NC,128)
#define GV 157   // CEILDIV(NV,128)
#define VGB 2500 // CEILDIV(NV*32,256): warp-per-variable blocks

// ---------------- scratch (device globals) ----------------
__device__ __align__(16) float d_variables[NV*64];
__device__ __align__(16) float d_clause_state[NC*64];
__device__ __align__(16) float d_query[NV*64];
__device__ __align__(16) float d_closs[NC*64];
__device__ __align__(16) float d_cdata[NC*128];
__device__ __align__(16) float d_unit[NV*256];
__device__ __align__(16) float d_uout[NV*64];
__device__ float d_logits[NV];
__device__ float d_last_logits[NV];

__device__ __align__(16) uint32_t d_wh[52224];
__device__ __align__(16) uint32_t d_wl[52224];

__device__ float d_var_sum[2*NV];
__device__ float d_lit_deg[2*NV];
__device__ float d_degw[2*NV];
__device__ float d_vdw[NV];
__device__ float d_vmask[NV];
__device__ float d_vg_norm[NV];
__device__ float d_cg_norm[NC];
__device__ float d_vmask_gsum[NG];
__device__ float d_wsig_gsum[NG];
__device__ float d_loss_sum[NG];
__device__ float d_pg[NG];
__device__ float d_mean[NG*64];
__device__ float d_varred[NG];

__device__ int d_counts[2*NV];
__device__ int d_csroff[2*NV+1];
__device__ int d_cursor[2*NV];
__device__ int d_csrclause[NE];
__device__ int d_cstart[NG+1];
__device__ int d_vstart[NG+1];
__device__ int d_done;
__device__ int d_allsat;
__device__ int d_step;
__device__ int d_fc_count;

// ---------------- helpers ----------------
__device__ __forceinline__ float sp_f(float x){ return fmaxf(x,0.f)+log1pf(expf(-fabsf(x))); }
__device__ __forceinline__ float sigm(float x){ return 1.f/(1.f+expf(-x)); }

__device__ __forceinline__ void pack2(float x0, float x1, uint32_t* ph, uint32_t* pl){
    __nv_bfloat16 h0 = __float2bfloat16_rn(x0);
    __nv_bfloat16 h1 = __float2bfloat16_rn(x1);
    float r0 = x0 - __bfloat162float(h0);
    float r1 = x1 - __bfloat162float(h1);
    __nv_bfloat16 l0 = __float2bfloat16_rn(r0);
    __nv_bfloat16 l1 = __float2bfloat16_rn(r1);
    *ph = ((uint32_t)__bfloat16_as_ushort(h1)<<16) | __bfloat16_as_ushort(h0);
    *pl = ((uint32_t)__bfloat16_as_ushort(l1)<<16) | __bfloat16_as_ushort(l0);
}

#define MMA_BF16(c, a, b0, b1) \
  asm volatile("mma.sync.aligned.m16n8k16.row.col.f32.bf16.bf16.f32 " \
    "{%0,%1,%2,%3}, {%4,%5,%6,%7}, {%8,%9}, {%0,%1,%2,%3};" \
    : "+f"((c)[0]), "+f"((c)[1]), "+f"((c)[2]), "+f"((c)[3]) \
    : "r"((a)[0]), "r"((a)[1]), "r"((a)[2]), "r"((a)[3]), "r"(b0), "r"(b1))

__device__ __forceinline__ void stageB128(uint32_t* Bh, uint32_t* Bl,
    const uint32_t* Wh, const uint32_t* Wl, int hw, int k0, int tid){
    int n = tid>>1, qq = tid&1;
    const uint4* sh = (const uint4*)(Wh + (size_t)n*hw + (k0>>1)) + qq*2;
    const uint4* sl = (const uint4*)(Wl + (size_t)n*hw + (k0>>1)) + qq*2;
    uint4 h0=sh[0], h1=sh[1], l0=sl[0], l1=sl[1];
    uint32_t* dh = &Bh[n*SB + qq*8];
    uint32_t* dl = &Bl[n*SB + qq*8];
    dh[0]=h0.x; dh[1]=h0.y; dh[2]=h0.z; dh[3]=h0.w;
    dh[4]=h1.x; dh[5]=h1.y; dh[6]=h1.z; dh[7]=h1.w;
    dl[0]=l0.x; dl[1]=l0.y; dl[2]=l0.z; dl[3]=l0.w;
    dl[4]=l1.x; dl[5]=l1.y; dl[6]=l1.z; dl[7]=l1.w;
}

__device__ __forceinline__ void stageB64(uint32_t* Bh, uint32_t* Bl,
    const uint32_t* Wh, const uint32_t* Wl, int hw, int k0, int tid){
    int n = tid>>2, qq = tid&3;
    const uint4* sh = (const uint4*)(Wh + (size_t)n*hw + (k0>>1)) + qq;
    const uint4* sl = (const uint4*)(Wl + (size_t)n*hw + (k0>>1)) + qq;
    uint4 h0=sh[0], l0=sl[0];
    uint32_t* dh = &Bh[n*SB + qq*4];
    uint32_t* dl = &Bl[n*SB + qq*4];
    dh[0]=h0.x; dh[1]=h0.y; dh[2]=h0.z; dh[3]=h0.w;
    dl[0]=l0.x; dl[1]=l0.y; dl[2]=l0.z; dl[3]=l0.w;
}

__device__ __forceinline__ void fragA(const uint32_t* A, int row, int bw, int ks, int tig,
                                      int saw, uint32_t* a){
    int r0 = row*saw + bw + ks*8 + tig;
    int r1 = r0 + 8*saw;
    a[0]=A[r0]; a[1]=A[r1]; a[2]=A[r0+4]; a[3]=A[r1+4];
}

// ---------------- init / precompute ----------------
__global__ void k_init(){
    int i = blockIdx.x*blockDim.x + threadIdx.x;
    if (i < 2*NV){ d_var_sum[i]=0.f; d_lit_deg[i]=0.f; d_counts[i]=0; d_cursor[i]=0; }
    if (i < NG){ d_vmask_gsum[i]=0.f; d_wsig_gsum[i]=0.f; d_loss_sum[i]=0.f; }
    if (i <= NG){ d_cstart[i]=NC; d_vstart[i]=NV; }
    if (i == 0){ d_done=0; d_allsat=1; d_step=0; d_fc_count=0; d_csroff[2*NV]=NE; }
}

__global__ void k_init_state(){
    int i = blockIdx.x*blockDim.x + threadIdx.x;
    if (i < NC*64) d_clause_state[i]=1.f;
    if (i < NV*64) d_variables[i]=1.f;
}

__global__ void k_edge_scatter(const int* __restrict__ elit, const int* __restrict__ eclause,
                               const float* __restrict__ wsig, const float* __restrict__ wsp){
    int e = blockIdx.x*blockDim.x + threadIdx.x;
    if (e >= NE) return;
    int c = eclause[e];
    int l = elit[e];
    float w = wsig[c];
    atomicAdd(&d_var_sum[l], w*wsp[c]);
    atomicAdd(&d_lit_deg[l], w);
    atomicAdd(&d_counts[l], 1);
}

__global__ void k_scan(){
    int tid = threadIdx.x, lane = tid&31, wid = tid>>5;
    const int PER = 40;
    int base = tid*PER;
    int sum = 0;
    for (int i=base; i<base+PER && i<2*NV; i++) sum += d_counts[i];
    int v = sum;
    #pragma unroll
    for (int o=1;o<32;o<<=1){ int t=__shfl_up_sync(0xffffffffu, v, o); if (lane>=o) v+=t; }
    __shared__ int ws[32];
    if (lane==31) ws[wid]=v;
    __syncthreads();
    if (wid==0){
        int w = ws[lane];
        #pragma unroll
        for (int o=1;o<32;o<<=1){ int t=__shfl_up_sync(0xffffffffu, w, o); if (lane>=o) w+=t; }
        ws[lane]=w;
    }
    __syncthreads();
    int run = v - sum + (wid>0? ws[wid-1]:0);
    for (int i=base; i<base+PER && i<2*NV; i++){ d_csroff[i]=run; run+=d_counts[i]; }
}

__global__ void k_fill(const int* __restrict__ elit){
    int e = blockIdx.x*blockDim.x + threadIdx.x;
    if (e >= NE) return;
    int l = elit[e];
    int p = atomicAdd(&d_cursor[l], 1);
    d_csrclause[d_csroff[l]+p] = e/3;
}

__global__ void k_segmin(const int* __restrict__ cgid, const int* __restrict__ vgid){
    int i = blockIdx.x*blockDim.x + threadIdx.x;
    if (i < NC) atomicMin(&d_cstart[cgid[i]], i);
    if (i < NV) atomicMin(&d_vstart[vgid[i]], i);
}

__global__ void k_segfix(){
    if (threadIdx.x==0){
        d_cstart[NG]=NC;
        for (int g=NG-1; g>=0; g--) d_cstart[g]=min(d_cstart[g], d_cstart[g+1]);
    }
    if (threadIdx.x==1){
        d_vstart[NG]=NV;
        for (int g=NG-1; g>=0; g--) d_vstart[g]=min(d_vstart[g], d_vstart[g+1]);
    }
}

__global__ void k_var_pre(const int* __restrict__ vgid){
    int v = blockIdx.x*blockDim.x + threadIdx.x;
    if (v >= NV) return;
    float m = 1.f - expf(-(d_var_sum[v] + d_var_sum[v+NV]));
    d_vmask[v] = m;
    atomicAdd(&d_vmask_gsum[vgid[v]], m);
    float dp = d_lit_deg[v], dn = d_lit_deg[v+NV];
    d_degw[v]    = rsqrtf(fmaxf(dp,1.f));
    d_degw[v+NV] = rsqrtf(fmaxf(dn,1.f));
    d_vdw[v]     = 4.f*rsqrtf(fmaxf(dp+dn,1.f));
}

__global__ void k_clause_pre(const int* __restrict__ cgid, const float* __restrict__ wsig){
    int c = blockIdx.x*blockDim.x + threadIdx.x;
    if (c >= NC) return;
    atomicAdd(&d_wsig_gsum[cgid[c]], wsig[c]);
}

__global__ void k_norms(const int* __restrict__ cgid, const int* __restrict__ vgid,
                        const float* __restrict__ wsig){
    int i = blockIdx.x*blockDim.x + threadIdx.x;
    if (i < NC){
        float s = d_wsig_gsum[cgid[i]];
        d_cg_norm[i] = wsig[i] * (s>0.f ? 1.f/s : 0.f);
    }
    if (i < NV){
        float s = d_vmask_gsum[vgid[i]];
        d_vg_norm[i] = d_vmask[i] * (s>0.f ? 1.f/s : 0.f);
    }
}

__global__ void k_pack_w(const float* __restrict__ W, int Ktrue, int N, int Kp,
                         uint32_t* __restrict__ Wh, uint32_t* __restrict__ Wl){
    int idx = blockIdx.x*blockDim.x + threadIdx.x;
    int hw = Kp>>1;
    if (idx >= N*hw) return;
    int n = idx/hw, kp = idx-n*hw;
    int k0 = 2*kp;
    float x0 = (k0   < Ktrue)? W[(size_t)k0*N+n]     : 0.f;
    float x1 = (k0+1 < Ktrue)? W[(size_t)(k0+1)*N+n] : 0.f;
    pack2(x0, x1, &Wh[idx], &Wl[idx]);
}

// ============== fused MLP kernels ==============

// q-MLP: [variables|noise](K=68,p96) -> relu 64 -> 64, writes d_query
__global__ void __launch_bounds__(256,2)
k_qmlp(const float* __restrict__ X1, const float* __restrict__ X2,
       const uint32_t* __restrict__ W1h, const uint32_t* __restrict__ W1l, const float* __restrict__ B1,
       const uint32_t* __restrict__ W2h, const uint32_t* __restrict__ W2l, const float* __restrict__ B2,
       float* __restrict__ Y)
{
    extern __shared__ uint32_t sm[];
    uint32_t *Ah=sm, *Al=sm+8704, *Bh=sm+17408, *Bl=sm+18688;
    int tid=threadIdx.x, lane=tid&31, wid=tid>>5;
    int g=lane>>2, tig=lane&3;
    int m0=blockIdx.x*128;

    {
        int m=tid>>1, q=tid&1, gm=m0+m;
        #pragma unroll
        for (int h=0; h<12; h++){
            int c=(q*12+h)*4;
            float4 v={0.f,0.f,0.f,0.f};
            if (gm<NV){
                if (c<64) v=*(const float4*)(X1+(size_t)gm*64+c);
                else if (c<68) v=*(const float4*)(X2+(size_t)gm*4);
            }
            int w=m*SAW+(c>>1);
            pack2(v.x,v.y,&Ah[w],&Al[w]);
            pack2(v.z,v.w,&Ah[w+1],&Al[w+1]);
        }
    }
    float acc[8][4];
    #pragma unroll
    for (int b=0;b<8;b++){ acc[b][0]=0.f; acc[b][1]=0.f; acc[b][2]=0.f; acc[b][3]=0.f; }
    for (int k0=0;k0<96;k0+=32){
        stageB64(Bh,Bl,W1h,W1l,48,k0,tid);
        __syncthreads();
        int bw=k0>>1;
        #pragma unroll
        for (int ks=0;ks<2;ks++){
            uint32_t ah[4], al[4];
            fragA(Ah, wid*16+g, bw, ks, tig, SAW, ah);
            fragA(Al, wid*16+g, bw, ks, tig, SAW, al);
            #pragma unroll
            for (int nt=0;nt<8;nt++){
                int nb=(nt*8+g)*SB + ks*8 + tig;
                uint32_t bh0=Bh[nb], bh1=Bh[nb+4], bl0=Bl[nb], bl1=Bl[nb+4];
                MMA_BF16(acc[nt], ah, bh0, bh1);
                MMA_BF16(acc[nt], ah, bl0, bl1);
                MMA_BF16(acc[nt], al, bh0, bh1);
            }
        }
        __syncthreads();
    }
    {
        int lm0 = wid*16+g;
        #pragma unroll
        for (int nt=0;nt<8;nt++){
            int col = nt*8 + 2*tig;
            float bb0=__ldg(B1+col), bb1=__ldg(B1+col+1);
            float o0=fmaxf(acc[nt][0]+bb0,0.f), o1=fmaxf(acc[nt][1]+bb1,0.f);
            float o2=fmaxf(acc[nt][2]+bb0,0.f), o3=fmaxf(acc[nt][3]+bb1,0.f);
            int wcol = nt*4+tig;
            pack2(o0,o1,&Ah[lm0*SAW+wcol],&Al[lm0*SAW+wcol]);
            pack2(o2,o3,&Ah[(lm0+8)*SAW+wcol],&Al[(lm0+8)*SAW+wcol]);
        }
    }
    #pragma unroll
    for (int b=0;b<8;b++){ acc[b][0]=0.f; acc[b][1]=0.f; acc[b][2]=0.f; acc[b][3]=0.f; }
    __syncthreads();
    for (int k0=0;k0<64;k0+=32){
        stageB64(Bh,Bl,W2h,W2l,32,k0,tid);
        __syncthreads();
        int bw=k0>>1;
        #pragma unroll
        for (int ks=0;ks<2;ks++){
            uint32_t ah[4], al[4];
            fragA(Ah, wid*16+g, bw, ks, tig, SAW, ah);
            fragA(Al, wid*16+g, bw, ks, tig, SAW, al);
            #pragma unroll
            for (int nt=0;nt<8;nt++){
                int nb=(nt*8+g)*SB + ks*8 + tig;
                uint32_t bh0=Bh[nb], bh1=Bh[nb+4], bl0=Bl[nb], bl1=Bl[nb+4];
                MMA_BF16(acc[nt], ah, bh0, bh1);
                MMA_BF16(acc[nt], ah, bl0, bl1);
                MMA_BF16(acc[nt], al, bh0, bh1);
            }
        }
        __syncthreads();
    }
    int rm0 = m0 + wid*16 + g, rm1 = rm0 + 8;
    #pragma unroll
    for (int nt=0;nt<8;nt++){
        int col = nt*8 + 2*tig;
        float bb0=__ldg(B2+col), bb1=__ldg(B2+col+1);
        if (rm0<NV) *(float2*)(Y+(size_t)rm0*64+col) = make_float2(acc[nt][0]+bb0, acc[nt][1]+bb1);
        if (rm1<NV) *(float2*)(Y+(size_t)rm1*64+col) = make_float2(acc[nt][2]+bb0, acc[nt][3]+bb1);
    }
}

// UNION: c-MLP (blocks [0,GC)) + var_grad (blocks [GC, GC+VGB))
__global__ void __launch_bounds__(256,2)
k_cmlp_vg(const float* __restrict__ X1, const float* __restrict__ X2,
          const uint32_t* __restrict__ W1h, const uint32_t* __restrict__ W1l, const float* __restrict__ B1,
          const uint32_t* __restrict__ W2h, const uint32_t* __restrict__ W2l, const float* __restrict__ B2,
          float* __restrict__ Y, const float* __restrict__ wsig)
{
    extern __shared__ uint32_t sm[];
    int tid=threadIdx.x, lane=tid&31, wid=tid>>5;

    if (blockIdx.x >= GC){
        // ---- var_grad path ----
        int gw = (blockIdx.x-GC)*8 + wid;
        if (gw >= NV) return;
        int v = gw;
        float2 ap={0.f,0.f}, an={0.f,0.f};
        int s0=d_csroff[v], e0=d_csroff[v+1];
        for (int i=s0;i<e0;i++){
            int c = d_csrclause[i];
            float w=wsig[c];
            float2 cl=*(const float2*)(d_closs+(size_t)c*64+lane*2);
            ap.x += w*cl.x; ap.y += w*cl.y;
        }
        int s1=d_csroff[NV+v], e1=d_csroff[NV+v+1];
        for (int i=s1;i<e1;i++){
            int c = d_csrclause[i];
            float w=wsig[c];
            float2 cl=*(const float2*)(d_closs+(size_t)c*64+lane*2);
            an.x += w*cl.x; an.y += w*cl.y;
        }
        float2 qv = *(const float2*)(d_query + (size_t)v*64 + lane*2);
        float vd = d_vdw[v];
        float2 gg;
        gg.x = (-ap.x*sigm(qv.x) + an.x*sigm(-qv.x)) * vd;
        gg.y = (-ap.y*sigm(qv.y) + an.y*sigm(-qv.y)) * vd;
        *(float2*)(d_unit + (size_t)v*256 + lane*2) = gg;
        float2 vv = *(const float2*)(d_variables + (size_t)v*64 + lane*2);
        *(float2*)(d_unit + (size_t)v*256 + 64 + lane*2) = vv;
        return;
    }

    // ---- c-MLP path ----
    uint32_t *Ah=sm, *Al=sm+8704, *Bh=sm+17408, *Bl=sm+19968;
    int warp_m=wid>>1, warp_n=wid&1, g=lane>>2, tig=lane&3;
    int m0=blockIdx.x*128;

    {
        int m=tid>>1, q=tid&1, gm=m0+m;
        #pragma unroll
        for (int h=0; h<16; h++){
            int c=(q*16+h)*4;
            float4 v={0.f,0.f,0.f,0.f};
            if (gm<NC){
                if (c<64) v=*(const float4*)(X1+(size_t)gm*64+c);
                else {
                    v=*(const float4*)(X2+(size_t)gm*64+(c-64));
                    v.x*=4.f; v.y*=4.f; v.z*=4.f; v.w*=4.f;
                }
            }
            int w=m*SAW+(c>>1);
            pack2(v.x,v.y,&Ah[w],&Al[w]);
            pack2(v.z,v.w,&Ah[w+1],&Al[w+1]);
        }
    }
    float acc[2][8][4];
    #pragma unroll
    for (int a=0;a<2;a++)
        #pragma unroll
        for (int b=0;b<8;b++){ acc[a][b][0]=0.f; acc[a][b][1]=0.f; acc[a][b][2]=0.f; acc[a][b][3]=0.f; }
    for (int k0=0;k0<128;k0+=32){
        stageB128(Bh,Bl,W1h,W1l,64,k0,tid);
        __syncthreads();
        int bw=k0>>1;
        #pragma unroll
        for (int ks=0;ks<2;ks++){
            uint32_t ah[2][4], al[2][4];
            #pragma unroll
            for (int mt=0;mt<2;mt++){
                fragA(Ah, warp_m*32+mt*16+g, bw, ks, tig, SAW, ah[mt]);
                fragA(Al, warp_m*32+mt*16+g, bw, ks, tig, SAW, al[mt]);
            }
            #pragma unroll
            for (int nt=0;nt<8;nt++){
                int nb=(warp_n*64+nt*8+g)*SB + ks*8 + tig;
                uint32_t bh0=Bh[nb], bh1=Bh[nb+4], bl0=Bl[nb], bl1=Bl[nb+4];
                #pragma unroll
                for (int mt=0;mt<2;mt++){
                    MMA_BF16(acc[mt][nt], ah[mt], bh0, bh1);
                    MMA_BF16(acc[mt][nt], ah[mt], bl0, bl1);
                    MMA_BF16(acc[mt][nt], al[mt], bh0, bh1);
                }
            }
        }
        __syncthreads();
    }
    #pragma unroll
    for (int mt=0;mt<2;mt++){
        int lm0 = warp_m*32+mt*16+g;
        #pragma unroll
        for (int nt=0;nt<8;nt++){
            int col = warp_n*64 + nt*8 + 2*tig;
            float bb0=__ldg(B1+col), bb1=__ldg(B1+col+1);
            float o0=fmaxf(acc[mt][nt][0]+bb0,0.f), o1=fmaxf(acc[mt][nt][1]+bb1,0.f);
            float o2=fmaxf(acc[mt][nt][2]+bb0,0.f), o3=fmaxf(acc[mt][nt][3]+bb1,0.f);
            int wcol = warp_n*32 + nt*4 + tig;
            pack2(o0,o1,&Ah[lm0*SAW+wcol],&Al[lm0*SAW+wcol]);
            pack2(o2,o3,&Ah[(lm0+8)*SAW+wcol],&Al[(lm0+8)*SAW+wcol]);
            acc[mt][nt][0]=0.f; acc[mt][nt][1]=0.f; acc[mt][nt][2]=0.f; acc[mt][nt][3]=0.f;
        }
    }
    __syncthreads();
    for (int k0=0;k0<128;k0+=32){
        stageB128(Bh,Bl,W2h,W2l,64,k0,tid);
        __syncthreads();
        int bw=k0>>1;
        #pragma unroll
        for (int ks=0;ks<2;ks++){
            uint32_t ah[2][4], al[2][4];
            #pragma unroll
            for (int mt=0;mt<2;mt++){
                fragA(Ah, warp_m*32+mt*16+g, bw, ks, tig, SAW, ah[mt]);
                fragA(Al, warp_m*32+mt*16+g, bw, ks, tig, SAW, al[mt]);
            }
            #pragma unroll
            for (int nt=0;nt<8;nt++){
                int nb=(warp_n*64+nt*8+g)*SB + ks*8 + tig;
                uint32_t bh0=Bh[nb], bh1=Bh[nb+4], bl0=Bl[nb], bl1=Bl[nb+4];
                #pragma unroll
                for (int mt=0;mt<2;mt++){
                    MMA_BF16(acc[mt][nt], ah[mt], bh0, bh1);
                    MMA_BF16(acc[mt][nt], ah[mt], bl0, bl1);
                    MMA_BF16(acc[mt][nt], al[mt], bh0, bh1);
                }
            }
        }
        __syncthreads();
    }
    #pragma unroll
    for (int mt=0;mt<2;mt++){
        int rm0 = m0 + warp_m*32 + mt*16 + g, rm1 = rm0 + 8;
        #pragma unroll
        for (int nt=0;nt<8;nt++){
            int col = warp_n*64 + nt*8 + 2*tig;
            float bb0=__ldg(B2+col), bb1=__ldg(B2+col+1);
            if (rm0<NC) *(float2*)(Y+(size_t)rm0*128+col) = make_float2(acc[mt][nt][0]+bb0, acc[mt][nt][1]+bb1);
            if (rm1<NC) *(float2*)(Y+(size_t)rm1*128+col) = make_float2(acc[mt][nt][2]+bb0, acc[mt][nt][3]+bb1);
        }
    }
}

// u-MLP: unit(K=256) -> relu 128 -> relu 128 -> 64, writes d_uout
__global__ void __launch_bounds__(256,2)
k_umlp(const float* __restrict__ X1,
       const uint32_t* __restrict__ W1h, const uint32_t* __restrict__ W1l, const float* __restrict__ B1,
       const uint32_t* __restrict__ W2h, const uint32_t* __restrict__ W2l, const float* __restrict__ B2,
       const uint32_t* __restrict__ W3h, const uint32_t* __restrict__ W3l, const float* __restrict__ B3,
       float* __restrict__ Y)
{
    extern __shared__ uint32_t sm[];
    uint32_t *Ah=sm, *Al=sm+8704, *Bh=sm+17408, *Bl=sm+19968;
    int tid=threadIdx.x, lane=tid&31, wid=tid>>5;
    int warp_m=wid>>1, warp_n=wid&1, g=lane>>2, tig=lane&3;
    int m0=blockIdx.x*128;

    float acc[2][8][4];
    #pragma unroll
    for (int a=0;a<2;a++)
        #pragma unroll
        for (int b=0;b<8;b++){ acc[a][b][0]=0.f; acc[a][b][1]=0.f; acc[a][b][2]=0.f; acc[a][b][3]=0.f; }

    int m=tid>>1, q=tid&1, gm=m0+m;
    for (int k0=0;k0<256;k0+=32){
        #pragma unroll
        for (int h=0;h<4;h++){
            int c = k0 + (q*4+h)*4;
            float4 v={0.f,0.f,0.f,0.f};
            if (gm<NV) v=*(const float4*)(X1+(size_t)gm*256+c);
            int kp=(q*4+h)*2;
            pack2(v.x,v.y,&Ah[m*SAW+kp],  &Al[m*SAW+kp]);
            pack2(v.z,v.w,&Ah[m*SAW+kp+1],&Al[m*SAW+kp+1]);
        }
        stageB128(Bh,Bl,W1h,W1l,128,k0,tid);
        __syncthreads();
        #pragma unroll
        for (int ks=0;ks<2;ks++){
            uint32_t ah[2][4], al[2][4];
            #pragma unroll
            for (int mt=0;mt<2;mt++){
                fragA(Ah, warp_m*32+mt*16+g, 0, ks, tig, SAW, ah[mt]);
                fragA(Al, warp_m*32+mt*16+g, 0, ks, tig, SAW, al[mt]);
            }
            #pragma unroll
            for (int nt=0;nt<8;nt++){
                int nb=(warp_n*64+nt*8+g)*SB + ks*8 + tig;
                uint32_t bh0=Bh[nb], bh1=Bh[nb+4], bl0=Bl[nb], bl1=Bl[nb+4];
                #pragma unroll
                for (int mt=0;mt<2;mt++){
                    MMA_BF16(acc[mt][nt], ah[mt], bh0, bh1);
                    MMA_BF16(acc[mt][nt], ah[mt], bl0, bl1);
                    MMA_BF16(acc[mt][nt], al[mt], bh0, bh1);
                }
            }
        }
        __syncthreads();
    }
    #pragma unroll
    for (int mt=0;mt<2;mt++){
        int lm0 = warp_m*32+mt*16+g;
        #pragma unroll
        for (int nt=0;nt<8;nt++){
            int col = warp_n*64 + nt*8 + 2*tig;
            float bb0=__ldg(B1+col), bb1=__ldg(B1+col+1);
            float o0=fmaxf(acc[mt][nt][0]+bb0,0.f), o1=fmaxf(acc[mt][nt][1]+bb1,0.f);
            float o2=fmaxf(acc[mt][nt][2]+bb0,0.f), o3=fmaxf(acc[mt][nt][3]+bb1,0.f);
            int wcol = warp_n*32 + nt*4 + tig;
            pack2(o0,o1,&Ah[lm0*SAW+wcol],&Al[lm0*SAW+wcol]);
            pack2(o2,o3,&Ah[(lm0+8)*SAW+wcol],&Al[(lm0+8)*SAW+wcol]);
            acc[mt][nt][0]=0.f; acc[mt][nt][1]=0.f; acc[mt][nt][2]=0.f; acc[mt][nt][3]=0.f;
        }
    }
    __syncthreads();
    for (int k0=0;k0<128;k0+=32){
        stageB128(Bh,Bl,W2h,W2l,64,k0,tid);
        __syncthreads();
        int bw=k0>>1;
        #pragma unroll
        for (int ks=0;ks<2;ks++){
            uint32_t ah[2][4], al[2][4];
            #pragma unroll
            for (int mt=0;mt<2;mt++){
                fragA(Ah, warp_m*32+mt*16+g, bw, ks, tig, SAW, ah[mt]);
                fragA(Al, warp_m*32+mt*16+g, bw, ks, tig, SAW, al[mt]);
            }
            #pragma unroll
            for (int nt=0;nt<8;nt++){
                int nb=(warp_n*64+nt*8+g)*SB + ks*8 + tig;
                uint32_t bh0=Bh[nb], bh1=Bh[nb+4], bl0=Bl[nb], bl1=Bl[nb+4];
                #pragma unroll
                for (int mt=0;mt<2;mt++){
                    MMA_BF16(acc[mt][nt], ah[mt], bh0, bh1);
                    MMA_BF16(acc[mt][nt], ah[mt], bl0, bl1);
                    MMA_BF16(acc[mt][nt], al[mt], bh0, bh1);
                }
            }
        }
        __syncthreads();
    }
    #pragma unroll
    for (int mt=0;mt<2;mt++){
        int lm0 = warp_m*32+mt*16+g;
        #pragma unroll
        for (int nt=0;nt<8;nt++){
            int col = warp_n*64 + nt*8 + 2*tig;
            float bb0=__ldg(B2+col), bb1=__ldg(B2+col+1);
            float o0=fmaxf(acc[mt][nt][0]+bb0,0.f), o1=fmaxf(acc[mt][nt][1]+bb1,0.f);
            float o2=fmaxf(acc[mt][nt][2]+bb0,0.f), o3=fmaxf(acc[mt][nt][3]+bb1,0.f);
            int wcol = warp_n*32 + nt*4 + tig;
            pack2(o0,o1,&Ah[lm0*SAW+wcol],&Al[lm0*SAW+wcol]);
            pack2(o2,o3,&Ah[(lm0+8)*SAW+wcol],&Al[(lm0+8)*SAW+wcol]);
        }
    }
    __syncthreads();
    float acc3[8][4];
    #pragma unroll
    for (int b=0;b<8;b++){ acc3[b][0]=0.f; acc3[b][1]=0.f; acc3[b][2]=0.f; acc3[b][3]=0.f; }
    for (int k0=0;k0<128;k0+=32){
        stageB64(Bh,Bl,W3h,W3l,64,k0,tid);
        __syncthreads();
        int bw=k0>>1;
        #pragma unroll
        for (int ks=0;ks<2;ks++){
            uint32_t ah[4], al[4];
            fragA(Ah, wid*16+g, bw, ks, tig, SAW, ah);
            fragA(Al, wid*16+g, bw, ks, tig, SAW, al);
            #pragma unroll
            for (int nt=0;nt<8;nt++){
                int nb=(nt*8+g)*SB + ks*8 + tig;
                uint32_t bh0=Bh[nb], bh1=Bh[nb+4], bl0=Bl[nb], bl1=Bl[nb+4];
                MMA_BF16(acc3[nt], ah, bh0, bh1);
                MMA_BF16(acc3[nt], ah, bl0, bl1);
                MMA_BF16(acc3[nt], al, bh0, bh1);
            }
        }
        __syncthreads();
    }
    int rm0 = m0 + wid*16 + g, rm1 = rm0 + 8;
    #pragma unroll
    for (int nt=0;nt<8;nt++){
        int col = nt*8 + 2*tig;
        float bb0=__ldg(B3+col), bb1=__ldg(B3+col+1);
        if (rm0<NV) *(float2*)(Y+(size_t)rm0*64+col) = make_float2(acc3[nt][0]+bb0, acc3[nt][1]+bb1);
        if (rm1<NV) *(float2*)(Y+(size_t)rm1*64+col) = make_float2(acc3[nt][2]+bb0, acc3[nt][3]+bb1);
    }
}

// fused o-MLP (static smem)
__global__ void __launch_bounds__(256,2)
k_fused_o(const int* __restrict__ vgid,
          const uint32_t* __restrict__ Wh, const uint32_t* __restrict__ Wl,
          const float* __restrict__ Bias,
          const float* __restrict__ ow2, const float* __restrict__ ob2)
{
    __shared__ uint32_t Ah[128*SB], Al[128*SB], Bh[64*SB], Bl[64*SB];
    int tid = threadIdx.x, lane = tid&31, wid = tid>>5;
    int g = lane>>2, tig = lane&3;
    int m0 = blockIdx.x*128;
    if (blockIdx.x==0 && tid==0) d_allsat = 1;
    int done = d_done;

    float acc[8][4];
    #pragma unroll
    for (int b=0;b<8;b++){ acc[b][0]=0.f; acc[b][1]=0.f; acc[b][2]=0.f; acc[b][3]=0.f; }

    int m = tid>>1, q = tid&1, gm = m0+m;
    float rs = 0.f; const float* mrow = nullptr;
    if (gm < NV){
        int gg = vgid[gm];
        rs = rsqrtf(d_varred[gg]+1e-6f)*0.25f;
        mrow = &d_mean[gg*64];
    }

    for (int k0=0; k0<64; k0+=32){
        #pragma unroll
        for (int h=0; h<4; h++){
            int c = k0 + (q*4+h)*4;
            float4 v = {0.f,0.f,0.f,0.f};
            if (gm < NV){
                float4 vv = *(const float4*)(d_variables + (size_t)gm*64 + c);
                if (done) v = vv;
                else {
                    float4 u = *(const float4*)(d_uout + (size_t)gm*64 + c);
                    v.x = (u.x - mrow[c  ])*rs + 0.1f*vv.x;
                    v.y = (u.y - mrow[c+1])*rs + 0.1f*vv.y;
                    v.z = (u.z - mrow[c+2])*rs + 0.1f*vv.z;
                    v.w = (u.w - mrow[c+3])*rs + 0.1f*vv.w;
                    *(float4*)(d_variables + (size_t)gm*64 + c) = v;
                }
            }
            int kp = (q*4+h)*2;
            pack2(v.x,v.y,&Ah[m*SB+kp],  &Al[m*SB+kp]);
            pack2(v.z,v.w,&Ah[m*SB+kp+1],&Al[m*SB+kp+1]);
        }
        stageB64(Bh,Bl,Wh,Wl,32,k0,tid);
        __syncthreads();
        #pragma unroll
        for (int ks=0; ks<2; ks++){
            uint32_t ah[4], al[4];
            fragA(Ah, wid*16+g, 0, ks, tig, SB, ah);
            fragA(Al, wid*16+g, 0, ks, tig, SB, al);
            #pragma unroll
            for (int nt=0; nt<8; nt++){
                int nb = (nt*8+g)*SB + ks*8 + tig;
                uint32_t bh0=Bh[nb], bh1=Bh[nb+4], bl0=Bl[nb], bl1=Bl[nb+4];
                MMA_BF16(acc[nt], ah, bh0, bh1);
                MMA_BF16(acc[nt], ah, bl0, bl1);
                MMA_BF16(acc[nt], al, bh0, bh1);
            }
        }
        __syncthreads();
    }
    float p0=0.f, p1=0.f;
    #pragma unroll
    for (int nt=0; nt<8; nt++){
        int col = nt*8 + 2*tig;
        float bb0 = __ldg(Bias+col), bb1 = __ldg(Bias+col+1);
        float w0 = __ldg(ow2+col),  w1 = __ldg(ow2+col+1);
        float o0=fmaxf(acc[nt][0]+bb0,0.f), o1=fmaxf(acc[nt][1]+bb1,0.f);
        float o2=fmaxf(acc[nt][2]+bb0,0.f), o3=fmaxf(acc[nt][3]+bb1,0.f);
        p0 += o0*w0 + o1*w1;
        p1 += o2*w0 + o3*w1;
    }
    p0 += __shfl_xor_sync(0xffffffffu, p0, 1);
    p0 += __shfl_xor_sync(0xffffffffu, p0, 2);
    p1 += __shfl_xor_sync(0xffffffffu, p1, 1);
    p1 += __shfl_xor_sync(0xffffffffu, p1, 2);
    if (tig==0){
        float ob = __ldg(ob2);
        int rm0 = m0 + wid*16 + g, rm1 = rm0 + 8;
        if (rm0 < NV){
            float lg = p0 + ob;
            d_logits[rm0] = lg;
            if (!done) d_last_logits[rm0] = lg;
        }
        if (rm1 < NV){
            float lg = p1 + ob;
            d_logits[rm1] = lg;
            if (!done) d_last_logits[rm1] = lg;
        }
    }
}

// ---------------- per-round kernels ----------------
__global__ void k_clause_cval(const int* __restrict__ elit, const float* __restrict__ wsig){
    int gw = (blockIdx.x*blockDim.x + threadIdx.x)>>5;
    int lane = threadIdx.x & 31;
    if (gw >= NC) return;
    float w = wsig[gw];
    float2 acc = {0.f,0.f};
    #pragma unroll
    for (int j=0;j<3;j++){
        int l = elit[3*gw+j];
        int v = (l<NV)? l : l-NV;
        float sgn = (l<NV)? 1.f : -1.f;
        float2 qv = *(const float2*)(d_query + (size_t)v*64 + lane*2);
        acc.x += sp_f(sgn*qv.x);
        acc.y += sp_f(sgn*qv.y);
    }
    float2 cl = { expf(-w*acc.x), expf(-w*acc.y) };
    *(float2*)(d_closs + (size_t)gw*64 + lane*2) = cl;
}

// UNION: pn_c (blocks [0,NG)) + var_loss (blocks [NG, NG+VGB))
__global__ void k_pnc_vl(const float* __restrict__ wsig){
    int tid=threadIdx.x, lane=tid&31, wid=tid>>5;

    if (blockIdx.x >= NG){
        // ---- var_loss path ----
        int gw = (blockIdx.x-NG)*8 + wid;
        if (gw >= NV) return;
        int v = gw;
        float2 ap={0.f,0.f}, an={0.f,0.f};
        int s0=d_csroff[v], e0=d_csroff[v+1];
        for (int i=s0;i<e0;i++){
            int c = d_csrclause[i];
            float w=wsig[c];
            float2 cl=*(const float2*)(d_cdata+(size_t)c*128+lane*2);
            ap.x += w*cl.x; ap.y += w*cl.y;
        }
        int s1=d_csroff[NV+v], e1=d_csroff[NV+v+1];
        for (int i=s1;i<e1;i++){
            int c = d_csrclause[i];
            float w=wsig[c];
            float2 cl=*(const float2*)(d_cdata+(size_t)c*128+lane*2);
            an.x += w*cl.x; an.y += w*cl.y;
        }
        float dp = d_degw[v], dn = d_degw[NV+v];
        *(float2*)(d_unit + (size_t)v*256 + 128 + lane*2) = make_float2(ap.x*dp, ap.y*dp);
        *(float2*)(d_unit + (size_t)v*256 + 192 + lane*2) = make_float2(an.x*dn, an.y*dn);
        return;
    }

    // ---- pn_c path ----
    int g=blockIdx.x;
    int s=d_cstart[g], e=d_cstart[g+1];
    int f=tid&63, grp=tid>>6;
    float s1=0.f, s2=0.f;
    for (int r=s+grp; r<e; r+=4){
        float wr = d_cg_norm[r];
        float xv = d_cdata[(size_t)r*128 + 64 + f];
        float wx = wr*xv;
        s1 += wx; s2 += wx*xv;
    }
    __shared__ float r1[256], r2[256];
    __shared__ float smean[64];
    __shared__ float srs;
    r1[tid]=s1; r2[tid]=s2; __syncthreads();
    if (tid<64){
        float S1 = r1[f]+r1[64+f]+r1[128+f]+r1[192+f];
        float S2 = r2[f]+r2[64+f]+r2[128+f]+r2[192+f];
        smean[f]=S1;
        r1[f] = S2 - S1*S1;
    }
    __syncthreads();
    if (tid<32){
        float v = r1[tid]+r1[tid+32];
        for (int o=16;o;o>>=1) v += __shfl_down_sync(0xffffffffu, v, o);
        if (tid==0) srs = rsqrtf(v*(1.f/64.f)+1e-6f)*0.25f;
    }
    __syncthreads();
    if (d_done) return;
    float rs = srs;
    int total = (e-s)*64;
    for (int idx=tid; idx<total; idx+=256){
        int r = s + (idx>>6);
        int ff = idx&63;
        float xc = d_cdata[(size_t)r*128 + 64 + ff] - smean[ff];
        size_t o = (size_t)r*64 + ff;
        d_clause_state[o] = xc*rs + 0.1f*d_clause_state[o];
    }
}

__global__ void k_pn_stats_v(){
    int g=blockIdx.x;
    int s=d_vstart[g], e=d_vstart[g+1];
    int f=threadIdx.x&63, grp=threadIdx.x>>6;
    float s1=0.f, s2=0.f;
    for (int r=s+grp; r<e; r+=4){
        float wr = d_vg_norm[r];
        float xv = d_uout[(size_t)r*64+f];
        float wx = wr*xv;
        s1 += wx; s2 += wx*xv;
    }
    __shared__ float r1[256], r2[256];
    r1[threadIdx.x]=s1; r2[threadIdx.x]=s2; __syncthreads();
    if (threadIdx.x<64){
        float S1 = r1[f]+r1[64+f]+r1[128+f]+r1[192+f];
        float S2 = r2[f]+r2[64+f]+r2[128+f]+r2[192+f];
        d_mean[g*64+f]=S1;
        r1[f] = S2 - S1*S1;
    }
    __syncthreads();
    if (threadIdx.x<32){
        float v = r1[threadIdx.x]+r1[threadIdx.x+32];
        for (int o=16;o;o>>=1) v += __shfl_down_sync(0xffffffffu, v, o);
        if (threadIdx.x==0) d_varred[g]=v*(1.f/64.f);
    }
}

// final clause loss + sat + folded finish (last-block ticket)
__global__ void k_final_clause(const int* __restrict__ elit, const float* __restrict__ wsig){
    __shared__ float sred[256];
    __shared__ int ssat[256];
    __shared__ int slast;
    int g = blockIdx.x;
    int s = d_cstart[g], e = d_cstart[g+1];
    float lsum=0.f; int sat=1;
    for (int c=s+threadIdx.x; c<e; c+=blockDim.x){
        float w = wsig[c];
        float cvs=0.f, csat=0.f;
        #pragma unroll
        for (int j=0;j<3;j++){
            int l = elit[3*c+j];
            int v = (l<NV)? l : l-NV;
            float sgn = (l<NV)? 1.f : -1.f;
            float lg = d_logits[v];
            cvs += sp_f(sgn*lg);
            float a = (lg>0.f)? 1.f : 0.f;
            float lit01 = (l<NV)? a : 1.f-a;
            csat += w*lit01;
        }
        float cv = expf(-w*cvs);
        float pc = cv * (-logf(1.f - cv + 1e-10f));
        lsum += pc*w;
        if (csat < 1.f) sat = 0;
    }
    sred[threadIdx.x]=lsum; ssat[threadIdx.x]=sat; __syncthreads();
    for (int o=128;o;o>>=1){
        if (threadIdx.x<o){ sred[threadIdx.x]+=sred[threadIdx.x+o]; ssat[threadIdx.x]&=ssat[threadIdx.x+o]; }
        __syncthreads();
    }
    if (threadIdx.x==0){
        d_pg[g]=sred[0];
        if (!ssat[0]) d_allsat = 0;
        __threadfence();
        slast = (atomicAdd(&d_fc_count,1) == NG-1);
    }
    __syncthreads();
    if (slast){
        __threadfence();
        int done0 = d_done;
        if (!done0 && threadIdx.x < NG)
            d_loss_sum[threadIdx.x] += sqrtf(d_pg[threadIdx.x]+1e-6f) - 0.001f;
        __syncthreads();
        if (threadIdx.x==0){
            if (!done0){
                d_step++;
                if (d_allsat) d_done = 1;
            }
            d_fc_count = 0;
        }
    }
}

__global__ void k_output(float* __restrict__ out, int n){
    int i = blockIdx.x*blockDim.x + threadIdx.x;
    if (i >= n) return;
    float v;
    if (i < NV)            v = d_last_logits[i];
    else if (i < NV+NG)    v = d_loss_sum[i-NV]*(1.f/(float)RNDS);
    else if (i == NV+NG)   v = (float)d_step;
    else                   v = 0.f;
    out[i] = v;
}

// ---------------- host ----------------
extern "C" void kernel_launch(void* const* d_in, const int* in_sizes, int n_in,
                              void* d_out, int out_size){
    const float* wsig   = (const float*)d_in[0];
    const float* wsp    = (const float*)d_in[1];
    const float* noise  = (const float*)d_in[2];
    const int*   elit   = (const int*)d_in[3];
    const int*   eclause= (const int*)d_in[4];
    const int*   cgid   = (const int*)d_in[5];
    const int*   vgid   = (const int*)d_in[6];
    const float* P[18];
    for (int i=0;i<18;i++) P[i]=(const float*)d_in[7+i];
    const float *qw1=P[0],*qb1=P[1],*qw2=P[2],*qb2=P[3];
    const float *cw1=P[4],*cb1=P[5],*cw2=P[6],*cb2=P[7];
    const float *uw1=P[8],*ub1=P[9],*uw2=P[10],*ub2=P[11],*uw3=P[12],*ub3=P[13];
    const float *ow1=P[14],*ob1=P[15],*ow2=P[16],*ob2=P[17];

    float *p_query,*p_cdata,*p_unit,*p_uout,*p_vars,*p_cs,*p_closs;
    uint32_t *p_wh, *p_wl;
    cudaGetSymbolAddress((void**)&p_query, d_query);
    cudaGetSymbolAddress((void**)&p_cdata, d_cdata);
    cudaGetSymbolAddress((void**)&p_unit,  d_unit);
    cudaGetSymbolAddress((void**)&p_uout,  d_uout);
    cudaGetSymbolAddress((void**)&p_vars,  d_variables);
    cudaGetSymbolAddress((void**)&p_cs,    d_clause_state);
    cudaGetSymbolAddress((void**)&p_closs, d_closs);
    cudaGetSymbolAddress((void**)&p_wh,    d_wh);
    cudaGetSymbolAddress((void**)&p_wl,    d_wl);

    const int OQ1=0, OQ2=3072, OC1=5120, OC2=13312, OU1=21504, OU2=37888, OU3=46080, OO1=50176;

    const int QSMEM = 19968*4;   // 79872 B
    const int CSMEM = 22528*4;   // 90112 B
    cudaFuncSetAttribute(k_qmlp,    cudaFuncAttributeMaxDynamicSharedMemorySize, QSMEM);
    cudaFuncSetAttribute(k_cmlp_vg, cudaFuncAttributeMaxDynamicSharedMemorySize, CSMEM);
    cudaFuncSetAttribute(k_umlp,    cudaFuncAttributeMaxDynamicSharedMemorySize, CSMEM);

    // ---- init / precompute ----
    k_init<<<CEILDIV(2*NV,256),256>>>();
    k_init_state<<<CEILDIV(NC*64,256),256>>>();
    k_edge_scatter<<<CEILDIV(NE,256),256>>>(elit, eclause, wsig, wsp);
    k_scan<<<1,1024>>>();
    k_fill<<<CEILDIV(NE,256),256>>>(elit);
    k_segmin<<<CEILDIV(NC,256),256>>>(cgid, vgid);
    k_segfix<<<1,32>>>();
    k_var_pre<<<CEILDIV(NV,256),256>>>(vgid);
    k_clause_pre<<<CEILDIV(NC,256),256>>>(cgid, wsig);
    k_norms<<<CEILDIV(NC,256),256>>>(cgid, vgid, wsig);

    // ---- pack weights ----
    k_pack_w<<<CEILDIV(64*48,256),256>>>(qw1,  68, 64, 96, p_wh+OQ1, p_wl+OQ1);
    k_pack_w<<<CEILDIV(64*32,256),256>>>(qw2,  64, 64, 64, p_wh+OQ2, p_wl+OQ2);
    k_pack_w<<<CEILDIV(128*64,256),256>>>(cw1, 128,128,128, p_wh+OC1, p_wl+OC1);
    k_pack_w<<<CEILDIV(128*64,256),256>>>(cw2, 128,128,128, p_wh+OC2, p_wl+OC2);
    k_pack_w<<<CEILDIV(128*128,256),256>>>(uw1,256,128,256, p_wh+OU1, p_wl+OU1);
    k_pack_w<<<CEILDIV(128*64,256),256>>>(uw2, 128,128,128, p_wh+OU2, p_wl+OU2);
    k_pack_w<<<CEILDIV(64*64,256),256>>>(uw3, 128, 64,128, p_wh+OU3, p_wl+OU3);
    k_pack_w<<<CEILDIV(64*32,256),256>>>(ow1,  64, 64, 64, p_wh+OO1, p_wl+OO1);

    // ---- rounds ----
    for (int t=0; t<RNDS; t++){
        const float* nt = noise + (size_t)t*NV*4;
        k_qmlp<<<GV,256,QSMEM>>>(p_vars, nt, p_wh+OQ1, p_wl+OQ1, qb1,
                                 p_wh+OQ2, p_wl+OQ2, qb2, p_query);
        k_clause_cval<<<CEILDIV(NC*32,256),256>>>(elit, wsig);
        k_cmlp_vg<<<GC+VGB,256,CSMEM>>>(p_cs, p_closs, p_wh+OC1, p_wl+OC1, cb1,
                                        p_wh+OC2, p_wl+OC2, cb2, p_cdata, wsig);
        k_pnc_vl<<<NG+VGB,256>>>(wsig);
        k_umlp<<<GV,256,CSMEM>>>(p_unit, p_wh+OU1, p_wl+OU1, ub1,
                                 p_wh+OU2, p_wl+OU2, ub2,
                                 p_wh+OU3, p_wl+OU3, ub3, p_uout);
        k_pn_stats_v<<<NG,256>>>();
        k_fused_o<<<GV,256>>>(vgid, p_wh+OO1, p_wl+OO1, ob1, ow2, ob2);
        k_final_clause<<<NG,256>>>(elit, wsig);
    }

    k_output<<<CEILDIV(out_size>0?out_size:1,256),256>>>((float*)d_out, out_size);
}

// round 11
// speedup vs baseline: 1.0842x; 1.0842x over previous
#include <cuda_runtime.h>
#include <cuda_bf16.h>
#include <cstdint>

#define NV 20000
#define NC 84000
#define NG 200
#define NE 252000
#define RNDS 8
#define CEILDIV(a,b) (((a)+(b)-1)/(b))
#define SB 20    // staged-B row stride (words)
#define SAW 68   // full-width A row stride (words)
#define NL 40000          // 2*NV literals
#define SCB 157           // CEILDIV(NL,256)

// ---------------- scratch (device globals) ----------------
__device__ __align__(16) float d_variables[NV*64];
__device__ __align__(16) float d_clause_state[NC*64];
__device__ __align__(16) float d_query[NV*64];
__device__ __align__(16) float d_closs[NC*64];
__device__ __align__(16) float d_cdata[NC*128];
__device__ __align__(16) float d_unit[NV*256];
__device__ __align__(16) float d_uout[NV*64];
__device__ float d_logits[NV];
__device__ float d_last_logits[NV];

__device__ __align__(16) uint32_t d_wh[52224];
__device__ __align__(16) uint32_t d_wl[52224];

__device__ float d_var_sum[2*NV];
__device__ float d_lit_deg[2*NV];
__device__ float d_degw[2*NV];
__device__ float d_vdw[NV];
__device__ float d_vmask[NV];
__device__ float d_vg_norm[NV];
__device__ float d_cg_norm[NC];
__device__ float d_vmask_gsum[NG];
__device__ float d_wsig_gsum[NG];
__device__ float d_loss_sum[NG];
__device__ float d_pg[NG];
__device__ float d_mean[NG*64];
__device__ float d_varred[NG];

__device__ int d_counts[2*NV];
__device__ int d_csroff[2*NV+1];
__device__ int d_scanex[2*NV];
__device__ int d_bsum[SCB];
__device__ int d_boff[SCB];
__device__ int d_cursor[2*NV];
__device__ int d_csrclause[NE];
__device__ int d_cstart[NG+1];
__device__ int d_vstart[NG+1];
__device__ int d_done;
__device__ int d_allsat;
__device__ int d_step;
__device__ int d_fc_count;

// ---------------- helpers ----------------
__device__ __forceinline__ float sp_f(float x){ return fmaxf(x,0.f)+log1pf(expf(-fabsf(x))); }
__device__ __forceinline__ float sigm(float x){ return 1.f/(1.f+expf(-x)); }

__device__ __forceinline__ void pack2(float x0, float x1, uint32_t* ph, uint32_t* pl){
    __nv_bfloat16 h0 = __float2bfloat16_rn(x0);
    __nv_bfloat16 h1 = __float2bfloat16_rn(x1);
    float r0 = x0 - __bfloat162float(h0);
    float r1 = x1 - __bfloat162float(h1);
    __nv_bfloat16 l0 = __float2bfloat16_rn(r0);
    __nv_bfloat16 l1 = __float2bfloat16_rn(r1);
    *ph = ((uint32_t)__bfloat16_as_ushort(h1)<<16) | __bfloat16_as_ushort(h0);
    *pl = ((uint32_t)__bfloat16_as_ushort(l1)<<16) | __bfloat16_as_ushort(l0);
}

#define MMA_BF16(c, a, b0, b1) \
  asm volatile("mma.sync.aligned.m16n8k16.row.col.f32.bf16.bf16.f32 " \
    "{%0,%1,%2,%3}, {%4,%5,%6,%7}, {%8,%9}, {%0,%1,%2,%3};" \
    : "+f"((c)[0]), "+f"((c)[1]), "+f"((c)[2]), "+f"((c)[3]) \
    : "r"((a)[0]), "r"((a)[1]), "r"((a)[2]), "r"((a)[3]), "r"(b0), "r"(b1))

__device__ __forceinline__ void stageB128(uint32_t* Bh, uint32_t* Bl,
    const uint32_t* Wh, const uint32_t* Wl, int hw, int k0, int tid){
    int n = tid>>1, qq = tid&1;
    const uint4* sh = (const uint4*)(Wh + (size_t)n*hw + (k0>>1)) + qq*2;
    const uint4* sl = (const uint4*)(Wl + (size_t)n*hw + (k0>>1)) + qq*2;
    uint4 h0=sh[0], h1=sh[1], l0=sl[0], l1=sl[1];
    uint32_t* dh = &Bh[n*SB + qq*8];
    uint32_t* dl = &Bl[n*SB + qq*8];
    dh[0]=h0.x; dh[1]=h0.y; dh[2]=h0.z; dh[3]=h0.w;
    dh[4]=h1.x; dh[5]=h1.y; dh[6]=h1.z; dh[7]=h1.w;
    dl[0]=l0.x; dl[1]=l0.y; dl[2]=l0.z; dl[3]=l0.w;
    dl[4]=l1.x; dl[5]=l1.y; dl[6]=l1.z; dl[7]=l1.w;
}

__device__ __forceinline__ void stageB64(uint32_t* Bh, uint32_t* Bl,
    const uint32_t* Wh, const uint32_t* Wl, int hw, int k0, int tid){
    int n = tid>>2, qq = tid&3;
    const uint4* sh = (const uint4*)(Wh + (size_t)n*hw + (k0>>1)) + qq;
    const uint4* sl = (const uint4*)(Wl + (size_t)n*hw + (k0>>1)) + qq;
    uint4 h0=sh[0], l0=sl[0];
    uint32_t* dh = &Bh[n*SB + qq*4];
    uint32_t* dl = &Bl[n*SB + qq*4];
    dh[0]=h0.x; dh[1]=h0.y; dh[2]=h0.z; dh[3]=h0.w;
    dl[0]=l0.x; dl[1]=l0.y; dl[2]=l0.z; dl[3]=l0.w;
}

__device__ __forceinline__ void fragA(const uint32_t* A, int row, int bw, int ks, int tig,
                                      int saw, uint32_t* a){
    int r0 = row*saw + bw + ks*8 + tig;
    int r1 = r0 + 8*saw;
    a[0]=A[r0]; a[1]=A[r1]; a[2]=A[r0+4]; a[3]=A[r1+4];
}

// ---------------- init / precompute ----------------
__global__ void k_init(){
    int i = blockIdx.x*blockDim.x + threadIdx.x;
    if (i < 2*NV){ d_var_sum[i]=0.f; d_lit_deg[i]=0.f; d_counts[i]=0; d_cursor[i]=0; }
    if (i < NG){ d_vmask_gsum[i]=0.f; d_wsig_gsum[i]=0.f; d_loss_sum[i]=0.f; }
    if (i <= NG){ d_cstart[i]=NC; d_vstart[i]=NV; }
    if (i == 0){ d_done=0; d_allsat=1; d_step=0; d_fc_count=0; d_csroff[2*NV]=NE; }
}

__global__ void k_init_state(){
    int i = blockIdx.x*blockDim.x + threadIdx.x;
    if (i < NC*64) d_clause_state[i]=1.f;
    if (i < NV*64) d_variables[i]=1.f;
}

__global__ void k_edge_scatter(const int* __restrict__ elit, const int* __restrict__ eclause,
                               const float* __restrict__ wsig, const float* __restrict__ wsp){
    int e = blockIdx.x*blockDim.x + threadIdx.x;
    if (e >= NE) return;
    int c = eclause[e];
    int l = elit[e];
    float w = wsig[c];
    atomicAdd(&d_var_sum[l], w*wsp[c]);
    atomicAdd(&d_lit_deg[l], w);
    atomicAdd(&d_counts[l], 1);
}

// ---- parallel 3-phase scan of d_counts -> d_csroff ----
__global__ void k_scan_a(){
    int tid = threadIdx.x, lane = tid&31, wid = tid>>5;
    int i = blockIdx.x*256 + tid;
    int v = (i < NL)? d_counts[i] : 0;
    int x = v;
    #pragma unroll
    for (int o=1;o<32;o<<=1){ int t=__shfl_up_sync(0xffffffffu, x, o); if (lane>=o) x+=t; }
    __shared__ int ws[8];
    if (lane==31) ws[wid]=x;
    __syncthreads();
    if (wid==0 && lane<8){
        int w = ws[lane];
        #pragma unroll
        for (int o=1;o<8;o<<=1){ int t=__shfl_up_sync(0xffu, w, o); if (lane>=o) w+=t; }
        ws[lane]=w;
    }
    __syncthreads();
    int ex = x - v + (wid>0? ws[wid-1]:0);
    if (i < NL) d_scanex[i] = ex;
    if (tid==255) d_bsum[blockIdx.x] = ex + v;
}
__global__ void k_scan_b(){
    int tid = threadIdx.x, lane = tid&31, wid = tid>>5;
    int v = (tid < SCB)? d_bsum[tid] : 0;
    int x = v;
    #pragma unroll
    for (int o=1;o<32;o<<=1){ int t=__shfl_up_sync(0xffffffffu, x, o); if (lane>=o) x+=t; }
    __shared__ int ws[8];
    if (lane==31) ws[wid]=x;
    __syncthreads();
    if (wid==0 && lane<8){
        int w = ws[lane];
        #pragma unroll
        for (int o=1;o<8;o<<=1){ int t=__shfl_up_sync(0xffu, w, o); if (lane>=o) w+=t; }
        ws[lane]=w;
    }
    __syncthreads();
    if (tid < SCB) d_boff[tid] = x - v + (wid>0? ws[wid-1]:0);
}
__global__ void k_scan_c(){
    int i = blockIdx.x*256 + threadIdx.x;
    if (i < NL) d_csroff[i] = d_scanex[i] + d_boff[blockIdx.x];
}

__global__ void k_fill(const int* __restrict__ elit){
    int e = blockIdx.x*blockDim.x + threadIdx.x;
    if (e >= NE) return;
    int l = elit[e];
    int p = atomicAdd(&d_cursor[l], 1);
    d_csrclause[d_csroff[l]+p] = e/3;
}

__global__ void k_segmin(const int* __restrict__ cgid, const int* __restrict__ vgid){
    int i = blockIdx.x*blockDim.x + threadIdx.x;
    if (i < NC) atomicMin(&d_cstart[cgid[i]], i);
    if (i < NV) atomicMin(&d_vstart[vgid[i]], i);
}

__global__ void k_segfix(){
    if (threadIdx.x==0){
        d_cstart[NG]=NC;
        for (int g=NG-1; g>=0; g--) d_cstart[g]=min(d_cstart[g], d_cstart[g+1]);
    }
    if (threadIdx.x==1){
        d_vstart[NG]=NV;
        for (int g=NG-1; g>=0; g--) d_vstart[g]=min(d_vstart[g], d_vstart[g+1]);
    }
}

__global__ void k_var_pre(const int* __restrict__ vgid){
    int v = blockIdx.x*blockDim.x + threadIdx.x;
    if (v >= NV) return;
    float m = 1.f - expf(-(d_var_sum[v] + d_var_sum[v+NV]));
    d_vmask[v] = m;
    atomicAdd(&d_vmask_gsum[vgid[v]], m);
    float dp = d_lit_deg[v], dn = d_lit_deg[v+NV];
    d_degw[v]    = rsqrtf(fmaxf(dp,1.f));
    d_degw[v+NV] = rsqrtf(fmaxf(dn,1.f));
    d_vdw[v]     = 4.f*rsqrtf(fmaxf(dp+dn,1.f));
}

__global__ void k_clause_pre(const int* __restrict__ cgid, const float* __restrict__ wsig){
    int c = blockIdx.x*blockDim.x + threadIdx.x;
    if (c >= NC) return;
    atomicAdd(&d_wsig_gsum[cgid[c]], wsig[c]);
}

__global__ void k_norms(const int* __restrict__ cgid, const int* __restrict__ vgid,
                        const float* __restrict__ wsig){
    int i = blockIdx.x*blockDim.x + threadIdx.x;
    if (i < NC){
        float s = d_wsig_gsum[cgid[i]];
        d_cg_norm[i] = wsig[i] * (s>0.f ? 1.f/s : 0.f);
    }
    if (i < NV){
        float s = d_vmask_gsum[vgid[i]];
        d_vg_norm[i] = d_vmask[i] * (s>0.f ? 1.f/s : 0.f);
    }
}

__global__ void k_pack_w(const float* __restrict__ W, int Ktrue, int N, int Kp,
                         uint32_t* __restrict__ Wh, uint32_t* __restrict__ Wl){
    int idx = blockIdx.x*blockDim.x + threadIdx.x;
    int hw = Kp>>1;
    if (idx >= N*hw) return;
    int n = idx/hw, kp = idx-n*hw;
    int k0 = 2*kp;
    float x0 = (k0   < Ktrue)? W[(size_t)k0*N+n]     : 0.f;
    float x1 = (k0+1 < Ktrue)? W[(size_t)(k0+1)*N+n] : 0.f;
    pack2(x0, x1, &Wh[idx], &Wl[idx]);
}

// ============== fused MLP kernels ==============

// q-MLP
__global__ void __launch_bounds__(256,2)
k_qmlp(const float* __restrict__ X1, const float* __restrict__ X2,
       const uint32_t* __restrict__ W1h, const uint32_t* __restrict__ W1l, const float* __restrict__ B1,
       const uint32_t* __restrict__ W2h, const uint32_t* __restrict__ W2l, const float* __restrict__ B2,
       float* __restrict__ Y)
{
    extern __shared__ uint32_t sm[];
    uint32_t *Ah=sm, *Al=sm+8704, *Bh=sm+17408, *Bl=sm+18688;
    int tid=threadIdx.x, lane=tid&31, wid=tid>>5;
    int g=lane>>2, tig=lane&3;
    int m0=blockIdx.x*128;

    {
        int m=tid>>1, q=tid&1, gm=m0+m;
        #pragma unroll
        for (int h=0; h<12; h++){
            int c=(q*12+h)*4;
            float4 v={0.f,0.f,0.f,0.f};
            if (gm<NV){
                if (c<64) v=*(const float4*)(X1+(size_t)gm*64+c);
                else if (c<68) v=*(const float4*)(X2+(size_t)gm*4);
            }
            int w=m*SAW+(c>>1);
            pack2(v.x,v.y,&Ah[w],&Al[w]);
            pack2(v.z,v.w,&Ah[w+1],&Al[w+1]);
        }
    }
    float acc[8][4];
    #pragma unroll
    for (int b=0;b<8;b++){ acc[b][0]=0.f; acc[b][1]=0.f; acc[b][2]=0.f; acc[b][3]=0.f; }
    for (int k0=0;k0<96;k0+=32){
        stageB64(Bh,Bl,W1h,W1l,48,k0,tid);
        __syncthreads();
        int bw=k0>>1;
        #pragma unroll
        for (int ks=0;ks<2;ks++){
            uint32_t ah[4], al[4];
            fragA(Ah, wid*16+g, bw, ks, tig, SAW, ah);
            fragA(Al, wid*16+g, bw, ks, tig, SAW, al);
            #pragma unroll
            for (int nt=0;nt<8;nt++){
                int nb=(nt*8+g)*SB + ks*8 + tig;
                uint32_t bh0=Bh[nb], bh1=Bh[nb+4], bl0=Bl[nb], bl1=Bl[nb+4];
                MMA_BF16(acc[nt], ah, bh0, bh1);
                MMA_BF16(acc[nt], ah, bl0, bl1);
                MMA_BF16(acc[nt], al, bh0, bh1);
            }
        }
        __syncthreads();
    }
    {
        int lm0 = wid*16+g;
        #pragma unroll
        for (int nt=0;nt<8;nt++){
            int col = nt*8 + 2*tig;
            float bb0=__ldg(B1+col), bb1=__ldg(B1+col+1);
            float o0=fmaxf(acc[nt][0]+bb0,0.f), o1=fmaxf(acc[nt][1]+bb1,0.f);
            float o2=fmaxf(acc[nt][2]+bb0,0.f), o3=fmaxf(acc[nt][3]+bb1,0.f);
            int wcol = nt*4+tig;
            pack2(o0,o1,&Ah[lm0*SAW+wcol],&Al[lm0*SAW+wcol]);
            pack2(o2,o3,&Ah[(lm0+8)*SAW+wcol],&Al[(lm0+8)*SAW+wcol]);
        }
    }
    #pragma unroll
    for (int b=0;b<8;b++){ acc[b][0]=0.f; acc[b][1]=0.f; acc[b][2]=0.f; acc[b][3]=0.f; }
    __syncthreads();
    for (int k0=0;k0<64;k0+=32){
        stageB64(Bh,Bl,W2h,W2l,32,k0,tid);
        __syncthreads();
        int bw=k0>>1;
        #pragma unroll
        for (int ks=0;ks<2;ks++){
            uint32_t ah[4], al[4];
            fragA(Ah, wid*16+g, bw, ks, tig, SAW, ah);
            fragA(Al, wid*16+g, bw, ks, tig, SAW, al);
            #pragma unroll
            for (int nt=0;nt<8;nt++){
                int nb=(nt*8+g)*SB + ks*8 + tig;
                uint32_t bh0=Bh[nb], bh1=Bh[nb+4], bl0=Bl[nb], bl1=Bl[nb+4];
                MMA_BF16(acc[nt], ah, bh0, bh1);
                MMA_BF16(acc[nt], ah, bl0, bl1);
                MMA_BF16(acc[nt], al, bh0, bh1);
            }
        }
        __syncthreads();
    }
    int rm0 = m0 + wid*16 + g, rm1 = rm0 + 8;
    #pragma unroll
    for (int nt=0;nt<8;nt++){
        int col = nt*8 + 2*tig;
        float bb0=__ldg(B2+col), bb1=__ldg(B2+col+1);
        if (rm0<NV) *(float2*)(Y+(size_t)rm0*64+col) = make_float2(acc[nt][0]+bb0, acc[nt][1]+bb1);
        if (rm1<NV) *(float2*)(Y+(size_t)rm1*64+col) = make_float2(acc[nt][2]+bb0, acc[nt][3]+bb1);
    }
}

// c-MLP
__global__ void __launch_bounds__(256,2)
k_cmlp(const float* __restrict__ X1, const float* __restrict__ X2,
       const uint32_t* __restrict__ W1h, const uint32_t* __restrict__ W1l, const float* __restrict__ B1,
       const uint32_t* __restrict__ W2h, const uint32_t* __restrict__ W2l, const float* __restrict__ B2,
       float* __restrict__ Y)
{
    extern __shared__ uint32_t sm[];
    uint32_t *Ah=sm, *Al=sm+8704, *Bh=sm+17408, *Bl=sm+19968;
    int tid=threadIdx.x, lane=tid&31, wid=tid>>5;
    int warp_m=wid>>1, warp_n=wid&1, g=lane>>2, tig=lane&3;
    int m0=blockIdx.x*128;

    {
        int m=tid>>1, q=tid&1, gm=m0+m;
        #pragma unroll
        for (int h=0; h<16; h++){
            int c=(q*16+h)*4;
            float4 v={0.f,0.f,0.f,0.f};
            if (gm<NC){
                if (c<64) v=*(const float4*)(X1+(size_t)gm*64+c);
                else {
                    v=*(const float4*)(X2+(size_t)gm*64+(c-64));
                    v.x*=4.f; v.y*=4.f; v.z*=4.f; v.w*=4.f;
                }
            }
            int w=m*SAW+(c>>1);
            pack2(v.x,v.y,&Ah[w],&Al[w]);
            pack2(v.z,v.w,&Ah[w+1],&Al[w+1]);
        }
    }
    float acc[2][8][4];
    #pragma unroll
    for (int a=0;a<2;a++)
        #pragma unroll
        for (int b=0;b<8;b++){ acc[a][b][0]=0.f; acc[a][b][1]=0.f; acc[a][b][2]=0.f; acc[a][b][3]=0.f; }
    for (int k0=0;k0<128;k0+=32){
        stageB128(Bh,Bl,W1h,W1l,64,k0,tid);
        __syncthreads();
        int bw=k0>>1;
        #pragma unroll
        for (int ks=0;ks<2;ks++){
            uint32_t ah[2][4], al[2][4];
            #pragma unroll
            for (int mt=0;mt<2;mt++){
                fragA(Ah, warp_m*32+mt*16+g, bw, ks, tig, SAW, ah[mt]);
                fragA(Al, warp_m*32+mt*16+g, bw, ks, tig, SAW, al[mt]);
            }
            #pragma unroll
            for (int nt=0;nt<8;nt++){
                int nb=(warp_n*64+nt*8+g)*SB + ks*8 + tig;
                uint32_t bh0=Bh[nb], bh1=Bh[nb+4], bl0=Bl[nb], bl1=Bl[nb+4];
                #pragma unroll
                for (int mt=0;mt<2;mt++){
                    MMA_BF16(acc[mt][nt], ah[mt], bh0, bh1);
                    MMA_BF16(acc[mt][nt], ah[mt], bl0, bl1);
                    MMA_BF16(acc[mt][nt], al[mt], bh0, bh1);
                }
            }
        }
        __syncthreads();
    }
    #pragma unroll
    for (int mt=0;mt<2;mt++){
        int lm0 = warp_m*32+mt*16+g;
        #pragma unroll
        for (int nt=0;nt<8;nt++){
            int col = warp_n*64 + nt*8 + 2*tig;
            float bb0=__ldg(B1+col), bb1=__ldg(B1+col+1);
            float o0=fmaxf(acc[mt][nt][0]+bb0,0.f), o1=fmaxf(acc[mt][nt][1]+bb1,0.f);
            float o2=fmaxf(acc[mt][nt][2]+bb0,0.f), o3=fmaxf(acc[mt][nt][3]+bb1,0.f);
            int wcol = warp_n*32 + nt*4 + tig;
            pack2(o0,o1,&Ah[lm0*SAW+wcol],&Al[lm0*SAW+wcol]);
            pack2(o2,o3,&Ah[(lm0+8)*SAW+wcol],&Al[(lm0+8)*SAW+wcol]);
            acc[mt][nt][0]=0.f; acc[mt][nt][1]=0.f; acc[mt][nt][2]=0.f; acc[mt][nt][3]=0.f;
        }
    }
    __syncthreads();
    for (int k0=0;k0<128;k0+=32){
        stageB128(Bh,Bl,W2h,W2l,64,k0,tid);
        __syncthreads();
        int bw=k0>>1;
        #pragma unroll
        for (int ks=0;ks<2;ks++){
            uint32_t ah[2][4], al[2][4];
            #pragma unroll
            for (int mt=0;mt<2;mt++){
                fragA(Ah, warp_m*32+mt*16+g, bw, ks, tig, SAW, ah[mt]);
                fragA(Al, warp_m*32+mt*16+g, bw, ks, tig, SAW, al[mt]);
            }
            #pragma unroll
            for (int nt=0;nt<8;nt++){
                int nb=(warp_n*64+nt*8+g)*SB + ks*8 + tig;
                uint32_t bh0=Bh[nb], bh1=Bh[nb+4], bl0=Bl[nb], bl1=Bl[nb+4];
                #pragma unroll
                for (int mt=0;mt<2;mt++){
                    MMA_BF16(acc[mt][nt], ah[mt], bh0, bh1);
                    MMA_BF16(acc[mt][nt], ah[mt], bl0, bl1);
                    MMA_BF16(acc[mt][nt], al[mt], bh0, bh1);
                }
            }
        }
        __syncthreads();
    }
    #pragma unroll
    for (int mt=0;mt<2;mt++){
        int rm0 = m0 + warp_m*32 + mt*16 + g, rm1 = rm0 + 8;
        #pragma unroll
        for (int nt=0;nt<8;nt++){
            int col = warp_n*64 + nt*8 + 2*tig;
            float bb0=__ldg(B2+col), bb1=__ldg(B2+col+1);
            if (rm0<NC) *(float2*)(Y+(size_t)rm0*128+col) = make_float2(acc[mt][nt][0]+bb0, acc[mt][nt][1]+bb1);
            if (rm1<NC) *(float2*)(Y+(size_t)rm1*128+col) = make_float2(acc[mt][nt][2]+bb0, acc[mt][nt][3]+bb1);
        }
    }
}

// u-MLP
__global__ void __launch_bounds__(256,2)
k_umlp(const float* __restrict__ X1,
       const uint32_t* __restrict__ W1h, const uint32_t* __restrict__ W1l, const float* __restrict__ B1,
       const uint32_t* __restrict__ W2h, const uint32_t* __restrict__ W2l, const float* __restrict__ B2,
       const uint32_t* __restrict__ W3h, const uint32_t* __restrict__ W3l, const float* __restrict__ B3,
       float* __restrict__ Y)
{
    extern __shared__ uint32_t sm[];
    uint32_t *Ah=sm, *Al=sm+8704, *Bh=sm+17408, *Bl=sm+19968;
    int tid=threadIdx.x, lane=tid&31, wid=tid>>5;
    int warp_m=wid>>1, warp_n=wid&1, g=lane>>2, tig=lane&3;
    int m0=blockIdx.x*128;

    float acc[2][8][4];
    #pragma unroll
    for (int a=0;a<2;a++)
        #pragma unroll
        for (int b=0;b<8;b++){ acc[a][b][0]=0.f; acc[a][b][1]=0.f; acc[a][b][2]=0.f; acc[a][b][3]=0.f; }

    int m=tid>>1, q=tid&1, gm=m0+m;
    for (int k0=0;k0<256;k0+=32){
        #pragma unroll
        for (int h=0;h<4;h++){
            int c = k0 + (q*4+h)*4;
            float4 v={0.f,0.f,0.f,0.f};
            if (gm<NV) v=*(const float4*)(X1+(size_t)gm*256+c);
            int kp=(q*4+h)*2;
            pack2(v.x,v.y,&Ah[m*SAW+kp],  &Al[m*SAW+kp]);
            pack2(v.z,v.w,&Ah[m*SAW+kp+1],&Al[m*SAW+kp+1]);
        }
        stageB128(Bh,Bl,W1h,W1l,128,k0,tid);
        __syncthreads();
        #pragma unroll
        for (int ks=0;ks<2;ks++){
            uint32_t ah[2][4], al[2][4];
            #pragma unroll
            for (int mt=0;mt<2;mt++){
                fragA(Ah, warp_m*32+mt*16+g, 0, ks, tig, SAW, ah[mt]);
                fragA(Al, warp_m*32+mt*16+g, 0, ks, tig, SAW, al[mt]);
            }
            #pragma unroll
            for (int nt=0;nt<8;nt++){
                int nb=(warp_n*64+nt*8+g)*SB + ks*8 + tig;
                uint32_t bh0=Bh[nb], bh1=Bh[nb+4], bl0=Bl[nb], bl1=Bl[nb+4];
                #pragma unroll
                for (int mt=0;mt<2;mt++){
                    MMA_BF16(acc[mt][nt], ah[mt], bh0, bh1);
                    MMA_BF16(acc[mt][nt], ah[mt], bl0, bl1);
                    MMA_BF16(acc[mt][nt], al[mt], bh0, bh1);
                }
            }
        }
        __syncthreads();
    }
    #pragma unroll
    for (int mt=0;mt<2;mt++){
        int lm0 = warp_m*32+mt*16+g;
        #pragma unroll
        for (int nt=0;nt<8;nt++){
            int col = warp_n*64 + nt*8 + 2*tig;
            float bb0=__ldg(B1+col), bb1=__ldg(B1+col+1);
            float o0=fmaxf(acc[mt][nt][0]+bb0,0.f), o1=fmaxf(acc[mt][nt][1]+bb1,0.f);
            float o2=fmaxf(acc[mt][nt][2]+bb0,0.f), o3=fmaxf(acc[mt][nt][3]+bb1,0.f);
            int wcol = warp_n*32 + nt*4 + tig;
            pack2(o0,o1,&Ah[lm0*SAW+wcol],&Al[lm0*SAW+wcol]);
            pack2(o2,o3,&Ah[(lm0+8)*SAW+wcol],&Al[(lm0+8)*SAW+wcol]);
            acc[mt][nt][0]=0.f; acc[mt][nt][1]=0.f; acc[mt][nt][2]=0.f; acc[mt][nt][3]=0.f;
        }
    }
    __syncthreads();
    for (int k0=0;k0<128;k0+=32){
        stageB128(Bh,Bl,W2h,W2l,64,k0,tid);
        __syncthreads();
        int bw=k0>>1;
        #pragma unroll
        for (int ks=0;ks<2;ks++){
            uint32_t ah[2][4], al[2][4];
            #pragma unroll
            for (int mt=0;mt<2;mt++){
                fragA(Ah, warp_m*32+mt*16+g, bw, ks, tig, SAW, ah[mt]);
                fragA(Al, warp_m*32+mt*16+g, bw, ks, tig, SAW, al[mt]);
            }
            #pragma unroll
            for (int nt=0;nt<8;nt++){
                int nb=(warp_n*64+nt*8+g)*SB + ks*8 + tig;
                uint32_t bh0=Bh[nb], bh1=Bh[nb+4], bl0=Bl[nb], bl1=Bl[nb+4];
                #pragma unroll
                for (int mt=0;mt<2;mt++){
                    MMA_BF16(acc[mt][nt], ah[mt], bh0, bh1);
                    MMA_BF16(acc[mt][nt], ah[mt], bl0, bl1);
                    MMA_BF16(acc[mt][nt], al[mt], bh0, bh1);
                }
            }
        }
        __syncthreads();
    }
    #pragma unroll
    for (int mt=0;mt<2;mt++){
        int lm0 = warp_m*32+mt*16+g;
        #pragma unroll
        for (int nt=0;nt<8;nt++){
            int col = warp_n*64 + nt*8 + 2*tig;
            float bb0=__ldg(B2+col), bb1=__ldg(B2+col+1);
            float o0=fmaxf(acc[mt][nt][0]+bb0,0.f), o1=fmaxf(acc[mt][nt][1]+bb1,0.f);
            float o2=fmaxf(acc[mt][nt][2]+bb0,0.f), o3=fmaxf(acc[mt][nt][3]+bb1,0.f);
            int wcol = warp_n*32 + nt*4 + tig;
            pack2(o0,o1,&Ah[lm0*SAW+wcol],&Al[lm0*SAW+wcol]);
            pack2(o2,o3,&Ah[(lm0+8)*SAW+wcol],&Al[(lm0+8)*SAW+wcol]);
        }
    }
    __syncthreads();
    float acc3[8][4];
    #pragma unroll
    for (int b=0;b<8;b++){ acc3[b][0]=0.f; acc3[b][1]=0.f; acc3[b][2]=0.f; acc3[b][3]=0.f; }
    for (int k0=0;k0<128;k0+=32){
        stageB64(Bh,Bl,W3h,W3l,64,k0,tid);
        __syncthreads();
        int bw=k0>>1;
        #pragma unroll
        for (int ks=0;ks<2;ks++){
            uint32_t ah[4], al[4];
            fragA(Ah, wid*16+g, bw, ks, tig, SAW, ah);
            fragA(Al, wid*16+g, bw, ks, tig, SAW, al);
            #pragma unroll
            for (int nt=0;nt<8;nt++){
                int nb=(nt*8+g)*SB + ks*8 + tig;
                uint32_t bh0=Bh[nb], bh1=Bh[nb+4], bl0=Bl[nb], bl1=Bl[nb+4];
                MMA_BF16(acc3[nt], ah, bh0, bh1);
                MMA_BF16(acc3[nt], ah, bl0, bl1);
                MMA_BF16(acc3[nt], al, bh0, bh1);
            }
        }
        __syncthreads();
    }
    int rm0 = m0 + wid*16 + g, rm1 = rm0 + 8;
    #pragma unroll
    for (int nt=0;nt<8;nt++){
        int col = nt*8 + 2*tig;
        float bb0=__ldg(B3+col), bb1=__ldg(B3+col+1);
        if (rm0<NV) *(float2*)(Y+(size_t)rm0*64+col) = make_float2(acc3[nt][0]+bb0, acc3[nt][1]+bb1);
        if (rm1<NV) *(float2*)(Y+(size_t)rm1*64+col) = make_float2(acc3[nt][2]+bb0, acc3[nt][3]+bb1);
    }
}

// fused o-MLP
__global__ void __launch_bounds__(256,2)
k_fused_o(const int* __restrict__ vgid,
          const uint32_t* __restrict__ Wh, const uint32_t* __restrict__ Wl,
          const float* __restrict__ Bias,
          const float* __restrict__ ow2, const float* __restrict__ ob2)
{
    __shared__ uint32_t Ah[128*SB], Al[128*SB], Bh[64*SB], Bl[64*SB];
    int tid = threadIdx.x, lane = tid&31, wid = tid>>5;
    int g = lane>>2, tig = lane&3;
    int m0 = blockIdx.x*128;
    if (blockIdx.x==0 && tid==0) d_allsat = 1;
    int done = d_done;

    float acc[8][4];
    #pragma unroll
    for (int b=0;b<8;b++){ acc[b][0]=0.f; acc[b][1]=0.f; acc[b][2]=0.f; acc[b][3]=0.f; }

    int m = tid>>1, q = tid&1, gm = m0+m;
    float rs = 0.f; const float* mrow = nullptr;
    if (gm < NV){
        int gg = vgid[gm];
        rs = rsqrtf(d_varred[gg]+1e-6f)*0.25f;
        mrow = &d_mean[gg*64];
    }

    for (int k0=0; k0<64; k0+=32){
        #pragma unroll
        for (int h=0; h<4; h++){
            int c = k0 + (q*4+h)*4;
            float4 v = {0.f,0.f,0.f,0.f};
            if (gm < NV){
                float4 vv = *(const float4*)(d_variables + (size_t)gm*64 + c);
                if (done) v = vv;
                else {
                    float4 u = *(const float4*)(d_uout + (size_t)gm*64 + c);
                    v.x = (u.x - mrow[c  ])*rs + 0.1f*vv.x;
                    v.y = (u.y - mrow[c+1])*rs + 0.1f*vv.y;
                    v.z = (u.z - mrow[c+2])*rs + 0.1f*vv.z;
                    v.w = (u.w - mrow[c+3])*rs + 0.1f*vv.w;
                    *(float4*)(d_variables + (size_t)gm*64 + c) = v;
                }
            }
            int kp = (q*4+h)*2;
            pack2(v.x,v.y,&Ah[m*SB+kp],  &Al[m*SB+kp]);
            pack2(v.z,v.w,&Ah[m*SB+kp+1],&Al[m*SB+kp+1]);
        }
        stageB64(Bh,Bl,Wh,Wl,32,k0,tid);
        __syncthreads();
        #pragma unroll
        for (int ks=0; ks<2; ks++){
            uint32_t ah[4], al[4];
            fragA(Ah, wid*16+g, 0, ks, tig, SB, ah);
            fragA(Al, wid*16+g, 0, ks, tig, SB, al);
            #pragma unroll
            for (int nt=0; nt<8; nt++){
                int nb = (nt*8+g)*SB + ks*8 + tig;
                uint32_t bh0=Bh[nb], bh1=Bh[nb+4], bl0=Bl[nb], bl1=Bl[nb+4];
                MMA_BF16(acc[nt], ah, bh0, bh1);
                MMA_BF16(acc[nt], ah, bl0, bl1);
                MMA_BF16(acc[nt], al, bh0, bh1);
            }
        }
        __syncthreads();
    }
    float p0=0.f, p1=0.f;
    #pragma unroll
    for (int nt=0; nt<8; nt++){
        int col = nt*8 + 2*tig;
        float bb0 = __ldg(Bias+col), bb1 = __ldg(Bias+col+1);
        float w0 = __ldg(ow2+col),  w1 = __ldg(ow2+col+1);
        float o0=fmaxf(acc[nt][0]+bb0,0.f), o1=fmaxf(acc[nt][1]+bb1,0.f);
        float o2=fmaxf(acc[nt][2]+bb0,0.f), o3=fmaxf(acc[nt][3]+bb1,0.f);
        p0 += o0*w0 + o1*w1;
        p1 += o2*w0 + o3*w1;
    }
    p0 += __shfl_xor_sync(0xffffffffu, p0, 1);
    p0 += __shfl_xor_sync(0xffffffffu, p0, 2);
    p1 += __shfl_xor_sync(0xffffffffu, p1, 1);
    p1 += __shfl_xor_sync(0xffffffffu, p1, 2);
    if (tig==0){
        float ob = __ldg(ob2);
        int rm0 = m0 + wid*16 + g, rm1 = rm0 + 8;
        if (rm0 < NV){
            float lg = p0 + ob;
            d_logits[rm0] = lg;
            if (!done) d_last_logits[rm0] = lg;
        }
        if (rm1 < NV){
            float lg = p1 + ob;
            d_logits[rm1] = lg;
            if (!done) d_last_logits[rm1] = lg;
        }
    }
}

// ---------------- per-round kernels ----------------
__global__ void k_clause_cval(const int* __restrict__ elit, const float* __restrict__ wsig){
    int gw = (blockIdx.x*blockDim.x + threadIdx.x)>>5;
    int lane = threadIdx.x & 31;
    if (gw >= NC) return;
    float w = wsig[gw];
    float2 acc = {0.f,0.f};
    #pragma unroll
    for (int j=0;j<3;j++){
        int l = elit[3*gw+j];
        int v = (l<NV)? l : l-NV;
        float sgn = (l<NV)? 1.f : -1.f;
        float2 qv = *(const float2*)(d_query + (size_t)v*64 + lane*2);
        acc.x += sp_f(sgn*qv.x);
        acc.y += sp_f(sgn*qv.y);
    }
    float2 cl = { expf(-w*acc.x), expf(-w*acc.y) };
    *(float2*)(d_closs + (size_t)gw*64 + lane*2) = cl;
}

__global__ void k_var_grad(const float* __restrict__ wsig){
    int gw = (blockIdx.x*blockDim.x + threadIdx.x)>>5;
    int lane = threadIdx.x & 31;
    if (gw >= NV) return;
    int v = gw;
    float2 ap={0.f,0.f}, an={0.f,0.f};
    int s0=d_csroff[v], e0=d_csroff[v+1];
    for (int i=s0;i<e0;i++){
        int c = d_csrclause[i];
        float w=wsig[c];
        float2 cl=*(const float2*)(d_closs+(size_t)c*64+lane*2);
        ap.x += w*cl.x; ap.y += w*cl.y;
    }
    int s1=d_csroff[NV+v], e1=d_csroff[NV+v+1];
    for (int i=s1;i<e1;i++){
        int c = d_csrclause[i];
        float w=wsig[c];
        float2 cl=*(const float2*)(d_closs+(size_t)c*64+lane*2);
        an.x += w*cl.x; an.y += w*cl.y;
    }
    float2 qv = *(const float2*)(d_query + (size_t)v*64 + lane*2);
    float vd = d_vdw[v];
    float2 gg;
    gg.x = (-ap.x*sigm(qv.x) + an.x*sigm(-qv.x)) * vd;
    gg.y = (-ap.y*sigm(qv.y) + an.y*sigm(-qv.y)) * vd;
    *(float2*)(d_unit + (size_t)v*256 + lane*2) = gg;
    float2 vv = *(const float2*)(d_variables + (size_t)v*64 + lane*2);
    *(float2*)(d_unit + (size_t)v*256 + 64 + lane*2) = vv;
}

__global__ void k_pn_c(){
    int g=blockIdx.x;
    int s=d_cstart[g], e=d_cstart[g+1];
    int f=threadIdx.x&63, grp=threadIdx.x>>6;
    float s1=0.f, s2=0.f;
    for (int r=s+grp; r<e; r+=4){
        float wr = d_cg_norm[r];
        float xv = d_cdata[(size_t)r*128 + 64 + f];
        float wx = wr*xv;
        s1 += wx; s2 += wx*xv;
    }
    __shared__ float r1[256], r2[256];
    __shared__ float smean[64];
    __shared__ float srs;
    r1[threadIdx.x]=s1; r2[threadIdx.x]=s2; __syncthreads();
    if (threadIdx.x<64){
        float S1 = r1[f]+r1[64+f]+r1[128+f]+r1[192+f];
        float S2 = r2[f]+r2[64+f]+r2[128+f]+r2[192+f];
        smean[f]=S1;
        r1[f] = S2 - S1*S1;
    }
    __syncthreads();
    if (threadIdx.x<32){
        float v = r1[threadIdx.x]+r1[threadIdx.x+32];
        for (int o=16;o;o>>=1) v += __shfl_down_sync(0xffffffffu, v, o);
        if (threadIdx.x==0) srs = rsqrtf(v*(1.f/64.f)+1e-6f)*0.25f;
    }
    __syncthreads();
    if (d_done) return;
    float rs = srs;
    int total = (e-s)*64;
    for (int idx=threadIdx.x; idx<total; idx+=256){
        int r = s + (idx>>6);
        int ff = idx&63;
        float xc = d_cdata[(size_t)r*128 + 64 + ff] - smean[ff];
        size_t o = (size_t)r*64 + ff;
        d_clause_state[o] = xc*rs + 0.1f*d_clause_state[o];
    }
}

__global__ void k_pn_stats_v(){
    int g=blockIdx.x;
    int s=d_vstart[g], e=d_vstart[g+1];
    int f=threadIdx.x&63, grp=threadIdx.x>>6;
    float s1=0.f, s2=0.f;
    for (int r=s+grp; r<e; r+=4){
        float wr = d_vg_norm[r];
        float xv = d_uout[(size_t)r*64+f];
        float wx = wr*xv;
        s1 += wx; s2 += wx*xv;
    }
    __shared__ float r1[256], r2[256];
    r1[threadIdx.x]=s1; r2[threadIdx.x]=s2; __syncthreads();
    if (threadIdx.x<64){
        float S1 = r1[f]+r1[64+f]+r1[128+f]+r1[192+f];
        float S2 = r2[f]+r2[64+f]+r2[128+f]+r2[192+f];
        d_mean[g*64+f]=S1;
        r1[f] = S2 - S1*S1;
    }
    __syncthreads();
    if (threadIdx.x<32){
        float v = r1[threadIdx.x]+r1[threadIdx.x+32];
        for (int o=16;o;o>>=1) v += __shfl_down_sync(0xffffffffu, v, o);
        if (threadIdx.x==0) d_varred[g]=v*(1.f/64.f);
    }
}

__global__ void k_var_loss(const float* __restrict__ wsig){
    int gw = (blockIdx.x*blockDim.x + threadIdx.x)>>5;
    int lane = threadIdx.x & 31;
    if (gw >= NV) return;
    int v = gw;
    float2 ap={0.f,0.f}, an={0.f,0.f};
    int s0=d_csroff[v], e0=d_csroff[v+1];
    for (int i=s0;i<e0;i++){
        int c = d_csrclause[i];
        float w=wsig[c];
        float2 cl=*(const float2*)(d_cdata+(size_t)c*128+lane*2);
        ap.x += w*cl.x; ap.y += w*cl.y;
    }
    int s1=d_csroff[NV+v], e1=d_csroff[NV+v+1];
    for (int i=s1;i<e1;i++){
        int c = d_csrclause[i];
        float w=wsig[c];
        float2 cl=*(const float2*)(d_cdata+(size_t)c*128+lane*2);
        an.x += w*cl.x; an.y += w*cl.y;
    }
    float dp = d_degw[v], dn = d_degw[NV+v];
    *(float2*)(d_unit + (size_t)v*256 + 128 + lane*2) = make_float2(ap.x*dp, ap.y*dp);
    *(float2*)(d_unit + (size_t)v*256 + 192 + lane*2) = make_float2(an.x*dn, an.y*dn);
}

// final clause loss + sat + folded finish (last-block ticket)
__global__ void k_final_clause(const int* __restrict__ elit, const float* __restrict__ wsig){
    __shared__ float sred[256];
    __shared__ int ssat[256];
    __shared__ int slast;
    int g = blockIdx.x;
    int s = d_cstart[g], e = d_cstart[g+1];
    float lsum=0.f; int sat=1;
    for (int c=s+threadIdx.x; c<e; c+=blockDim.x){
        float w = wsig[c];
        float cvs=0.f, csat=0.f;
        #pragma unroll
        for (int j=0;j<3;j++){
            int l = elit[3*c+j];
            int v = (l<NV)? l : l-NV;
            float sgn = (l<NV)? 1.f : -1.f;
            float lg = d_logits[v];
            cvs += sp_f(sgn*lg);
            float a = (lg>0.f)? 1.f : 0.f;
            float lit01 = (l<NV)? a : 1.f-a;
            csat += w*lit01;
        }
        float cv = expf(-w*cvs);
        float pc = cv * (-logf(1.f - cv + 1e-10f));
        lsum += pc*w;
        if (csat < 1.f) sat = 0;
    }
    sred[threadIdx.x]=lsum; ssat[threadIdx.x]=sat; __syncthreads();
    for (int o=128;o;o>>=1){
        if (threadIdx.x<o){ sred[threadIdx.x]+=sred[threadIdx.x+o]; ssat[threadIdx.x]&=ssat[threadIdx.x+o]; }
        __syncthreads();
    }
    if (threadIdx.x==0){
        d_pg[g]=sred[0];
        if (!ssat[0]) d_allsat = 0;
        __threadfence();
        slast = (atomicAdd(&d_fc_count,1) == NG-1);
    }
    __syncthreads();
    if (slast){
        __threadfence();
        int done0 = d_done;
        if (!done0 && threadIdx.x < NG)
            d_loss_sum[threadIdx.x] += sqrtf(d_pg[threadIdx.x]+1e-6f) - 0.001f;
        __syncthreads();
        if (threadIdx.x==0){
            if (!done0){
                d_step++;
                if (d_allsat) d_done = 1;
            }
            d_fc_count = 0;
        }
    }
}

__global__ void k_output(float* __restrict__ out, int n){
    int i = blockIdx.x*blockDim.x + threadIdx.x;
    if (i >= n) return;
    float v;
    if (i < NV)            v = d_last_logits[i];
    else if (i < NV+NG)    v = d_loss_sum[i-NV]*(1.f/(float)RNDS);
    else if (i == NV+NG)   v = (float)d_step;
    else                   v = 0.f;
    out[i] = v;
}

// ---------------- host ----------------
extern "C" void kernel_launch(void* const* d_in, const int* in_sizes, int n_in,
                              void* d_out, int out_size){
    const float* wsig   = (const float*)d_in[0];
    const float* wsp    = (const float*)d_in[1];
    const float* noise  = (const float*)d_in[2];
    const int*   elit   = (const int*)d_in[3];
    const int*   eclause= (const int*)d_in[4];
    const int*   cgid   = (const int*)d_in[5];
    const int*   vgid   = (const int*)d_in[6];
    const float* P[18];
    for (int i=0;i<18;i++) P[i]=(const float*)d_in[7+i];
    const float *qw1=P[0],*qb1=P[1],*qw2=P[2],*qb2=P[3];
    const float *cw1=P[4],*cb1=P[5],*cw2=P[6],*cb2=P[7];
    const float *uw1=P[8],*ub1=P[9],*uw2=P[10],*ub2=P[11],*uw3=P[12],*ub3=P[13];
    const float *ow1=P[14],*ob1=P[15],*ow2=P[16],*ob2=P[17];

    float *p_query,*p_cdata,*p_unit,*p_uout,*p_vars,*p_cs,*p_closs;
    uint32_t *p_wh, *p_wl;
    cudaGetSymbolAddress((void**)&p_query, d_query);
    cudaGetSymbolAddress((void**)&p_cdata, d_cdata);
    cudaGetSymbolAddress((void**)&p_unit,  d_unit);
    cudaGetSymbolAddress((void**)&p_uout,  d_uout);
    cudaGetSymbolAddress((void**)&p_vars,  d_variables);
    cudaGetSymbolAddress((void**)&p_cs,    d_clause_state);
    cudaGetSymbolAddress((void**)&p_closs, d_closs);
    cudaGetSymbolAddress((void**)&p_wh,    d_wh);
    cudaGetSymbolAddress((void**)&p_wl,    d_wl);

    const int GVg = CEILDIV(NV,128);   // 157
    const int GCg = CEILDIV(NC,128);   // 657

    const int OQ1=0, OQ2=3072, OC1=5120, OC2=13312, OU1=21504, OU2=37888, OU3=46080, OO1=50176;

    const int QSMEM = 19968*4;   // 79872 B
    const int CSMEM = 22528*4;   // 90112 B
    cudaFuncSetAttribute(k_qmlp, cudaFuncAttributeMaxDynamicSharedMemorySize, QSMEM);
    cudaFuncSetAttribute(k_cmlp, cudaFuncAttributeMaxDynamicSharedMemorySize, CSMEM);
    cudaFuncSetAttribute(k_umlp, cudaFuncAttributeMaxDynamicSharedMemorySize, CSMEM);

    // ---- init / precompute ----
    k_init<<<CEILDIV(2*NV,256),256>>>();
    k_init_state<<<CEILDIV(NC*64,256),256>>>();
    k_edge_scatter<<<CEILDIV(NE,256),256>>>(elit, eclause, wsig, wsp);
    k_scan_a<<<SCB,256>>>();
    k_scan_b<<<1,256>>>();
    k_scan_c<<<SCB,256>>>();
    k_fill<<<CEILDIV(NE,256),256>>>(elit);
    k_segmin<<<CEILDIV(NC,256),256>>>(cgid, vgid);
    k_segfix<<<1,32>>>();
    k_var_pre<<<CEILDIV(NV,256),256>>>(vgid);
    k_clause_pre<<<CEILDIV(NC,256),256>>>(cgid, wsig);
    k_norms<<<CEILDIV(NC,256),256>>>(cgid, vgid, wsig);

    // ---- pack weights ----
    k_pack_w<<<CEILDIV(64*48,256),256>>>(qw1,  68, 64, 96, p_wh+OQ1, p_wl+OQ1);
    k_pack_w<<<CEILDIV(64*32,256),256>>>(qw2,  64, 64, 64, p_wh+OQ2, p_wl+OQ2);
    k_pack_w<<<CEILDIV(128*64,256),256>>>(cw1, 128,128,128, p_wh+OC1, p_wl+OC1);
    k_pack_w<<<CEILDIV(128*64,256),256>>>(cw2, 128,128,128, p_wh+OC2, p_wl+OC2);
    k_pack_w<<<CEILDIV(128*128,256),256>>>(uw1,256,128,256, p_wh+OU1, p_wl+OU1);
    k_pack_w<<<CEILDIV(128*64,256),256>>>(uw2, 128,128,128, p_wh+OU2, p_wl+OU2);
    k_pack_w<<<CEILDIV(64*64,256),256>>>(uw3, 128, 64,128, p_wh+OU3, p_wl+OU3);
    k_pack_w<<<CEILDIV(64*32,256),256>>>(ow1,  64, 64, 64, p_wh+OO1, p_wl+OO1);

    // ---- rounds ----
    for (int t=0; t<RNDS; t++){
        const float* nt = noise + (size_t)t*NV*4;
        k_qmlp<<<GVg,256,QSMEM>>>(p_vars, nt, p_wh+OQ1, p_wl+OQ1, qb1,
                                  p_wh+OQ2, p_wl+OQ2, qb2, p_query);
        k_clause_cval<<<CEILDIV(NC*32,256),256>>>(elit, wsig);
        k_var_grad<<<CEILDIV(NV*32,256),256>>>(wsig);
        k_cmlp<<<GCg,256,CSMEM>>>(p_cs, p_closs, p_wh+OC1, p_wl+OC1, cb1,
                                  p_wh+OC2, p_wl+OC2, cb2, p_cdata);
        k_pn_c<<<NG,256>>>();
        k_var_loss<<<CEILDIV(NV*32,256),256>>>(wsig);
        k_umlp<<<GVg,256,CSMEM>>>(p_unit, p_wh+OU1, p_wl+OU1, ub1,
                                  p_wh+OU2, p_wl+OU2, ub2,
                                  p_wh+OU3, p_wl+OU3, ub3, p_uout);
        k_pn_stats_v<<<NG,256>>>();
        k_fused_o<<<GVg,256>>>(vgid, p_wh+OO1, p_wl+OO1, ob1, ow2, ob2);
        k_final_clause<<<NG,256>>>(elit, wsig);
    }

    k_output<<<CEILDIV(out_size>0?out_size:1,256),256>>>((float*)d_out, out_size);
}

// round 12
// speedup vs baseline: 1.0860x; 1.0016x over previous
#include <cuda_runtime.h>
#include <cuda_bf16.h>
#include <cstdint>

#define NV 20000
#define NC 84000
#define NG 200
#define NE 252000
#define RNDS 8
#define CEILDIV(a,b) (((a)+(b)-1)/(b))
#define SB 20    // staged-B row stride (words)
#define SAW 68   // full-width A row stride (words)
#define NL 40000          // 2*NV literals
#define SCB 157           // CEILDIV(NL,256)

// ---------------- scratch (device globals) ----------------
__device__ __align__(16) float d_variables[NV*64];
__device__ __align__(16) float d_clause_state[NC*64];
__device__ __align__(16) float d_query[NV*64];
__device__ __align__(16) float d_closs[NC*64];
__device__ __align__(16) float d_cdata[NC*128];
__device__ __align__(16) float d_unit[NV*256];
__device__ __align__(16) float d_uout[NV*64];
__device__ float d_logits[NV];
__device__ float d_last_logits[NV];

__device__ __align__(16) uint32_t d_wh[52224];
__device__ __align__(16) uint32_t d_wl[52224];

__device__ float d_var_sum[2*NV];
__device__ float d_lit_deg[2*NV];
__device__ float d_degw[2*NV];
__device__ float d_vdw[NV];
__device__ float d_vmask[NV];
__device__ float d_vg_norm[NV];
__device__ float d_cg_norm[NC];
__device__ float d_vmask_gsum[NG];
__device__ float d_wsig_gsum[NG];
__device__ float d_loss_sum[NG];
__device__ float d_pg[NG];
__device__ float d_mean[NG*64];
__device__ float d_varred[NG];

__device__ int d_counts[2*NV];
__device__ int d_csroff[2*NV+1];
__device__ int d_scanex[2*NV];
__device__ int d_bsum[SCB];
__device__ int d_boff[SCB];
__device__ int d_cursor[2*NV];
__device__ int d_csrclause[NE];
__device__ int d_cstart[NG+1];
__device__ int d_vstart[NG+1];
__device__ int d_done;
__device__ int d_allsat;
__device__ int d_step;
__device__ int d_fc_count;

// ---------------- helpers ----------------
__device__ __forceinline__ float sp_f(float x){ return fmaxf(x,0.f)+log1pf(expf(-fabsf(x))); }
__device__ __forceinline__ float sigm(float x){ return 1.f/(1.f+expf(-x)); }

__device__ __forceinline__ void pack2(float x0, float x1, uint32_t* ph, uint32_t* pl){
    __nv_bfloat16 h0 = __float2bfloat16_rn(x0);
    __nv_bfloat16 h1 = __float2bfloat16_rn(x1);
    float r0 = x0 - __bfloat162float(h0);
    float r1 = x1 - __bfloat162float(h1);
    __nv_bfloat16 l0 = __float2bfloat16_rn(r0);
    __nv_bfloat16 l1 = __float2bfloat16_rn(r1);
    *ph = ((uint32_t)__bfloat16_as_ushort(h1)<<16) | __bfloat16_as_ushort(h0);
    *pl = ((uint32_t)__bfloat16_as_ushort(l1)<<16) | __bfloat16_as_ushort(l0);
}

#define MMA_BF16(c, a, b0, b1) \
  asm volatile("mma.sync.aligned.m16n8k16.row.col.f32.bf16.bf16.f32 " \
    "{%0,%1,%2,%3}, {%4,%5,%6,%7}, {%8,%9}, {%0,%1,%2,%3};" \
    : "+f"((c)[0]), "+f"((c)[1]), "+f"((c)[2]), "+f"((c)[3]) \
    : "r"((a)[0]), "r"((a)[1]), "r"((a)[2]), "r"((a)[3]), "r"(b0), "r"(b1))

__device__ __forceinline__ void stageB128(uint32_t* Bh, uint32_t* Bl,
    const uint32_t* Wh, const uint32_t* Wl, int hw, int k0, int tid){
    int n = tid>>1, qq = tid&1;
    const uint4* sh = (const uint4*)(Wh + (size_t)n*hw + (k0>>1)) + qq*2;
    const uint4* sl = (const uint4*)(Wl + (size_t)n*hw + (k0>>1)) + qq*2;
    uint4 h0=sh[0], h1=sh[1], l0=sl[0], l1=sl[1];
    uint32_t* dh = &Bh[n*SB + qq*8];
    uint32_t* dl = &Bl[n*SB + qq*8];
    dh[0]=h0.x; dh[1]=h0.y; dh[2]=h0.z; dh[3]=h0.w;
    dh[4]=h1.x; dh[5]=h1.y; dh[6]=h1.z; dh[7]=h1.w;
    dl[0]=l0.x; dl[1]=l0.y; dl[2]=l0.z; dl[3]=l0.w;
    dl[4]=l1.x; dl[5]=l1.y; dl[6]=l1.z; dl[7]=l1.w;
}

__device__ __forceinline__ void stageB64(uint32_t* Bh, uint32_t* Bl,
    const uint32_t* Wh, const uint32_t* Wl, int hw, int k0, int tid){
    int n = tid>>2, qq = tid&3;
    const uint4* sh = (const uint4*)(Wh + (size_t)n*hw + (k0>>1)) + qq;
    const uint4* sl = (const uint4*)(Wl + (size_t)n*hw + (k0>>1)) + qq;
    uint4 h0=sh[0], l0=sl[0];
    uint32_t* dh = &Bh[n*SB + qq*4];
    uint32_t* dl = &Bl[n*SB + qq*4];
    dh[0]=h0.x; dh[1]=h0.y; dh[2]=h0.z; dh[3]=h0.w;
    dl[0]=l0.x; dl[1]=l0.y; dl[2]=l0.z; dl[3]=l0.w;
}

__device__ __forceinline__ void fragA(const uint32_t* A, int row, int bw, int ks, int tig,
                                      int saw, uint32_t* a){
    int r0 = row*saw + bw + ks*8 + tig;
    int r1 = r0 + 8*saw;
    a[0]=A[r0]; a[1]=A[r1]; a[2]=A[r0+4]; a[3]=A[r1+4];
}

// ---------------- init / precompute ----------------
__global__ void k_init(){
    int i = blockIdx.x*blockDim.x + threadIdx.x;
    if (i < 2*NV){ d_var_sum[i]=0.f; d_lit_deg[i]=0.f; d_counts[i]=0; d_cursor[i]=0; }
    if (i < NG){ d_vmask_gsum[i]=0.f; d_wsig_gsum[i]=0.f; d_loss_sum[i]=0.f; }
    if (i <= NG){ d_cstart[i]=NC; d_vstart[i]=NV; }
    if (i == 0){ d_done=0; d_allsat=1; d_step=0; d_fc_count=0; d_csroff[2*NV]=NE; }
}

__global__ void k_init_state(){
    int i = blockIdx.x*blockDim.x + threadIdx.x;
    if (i < NC*64) d_clause_state[i]=1.f;
    if (i < NV*64) d_variables[i]=1.f;
}

__global__ void k_edge_scatter(const int* __restrict__ elit, const int* __restrict__ eclause,
                               const float* __restrict__ wsig, const float* __restrict__ wsp){
    int e = blockIdx.x*blockDim.x + threadIdx.x;
    if (e >= NE) return;
    int c = eclause[e];
    int l = elit[e];
    float w = wsig[c];
    atomicAdd(&d_var_sum[l], w*wsp[c]);
    atomicAdd(&d_lit_deg[l], w);
    atomicAdd(&d_counts[l], 1);
}

__global__ void k_scan_a(){
    int tid = threadIdx.x, lane = tid&31, wid = tid>>5;
    int i = blockIdx.x*256 + tid;
    int v = (i < NL)? d_counts[i] : 0;
    int x = v;
    #pragma unroll
    for (int o=1;o<32;o<<=1){ int t=__shfl_up_sync(0xffffffffu, x, o); if (lane>=o) x+=t; }
    __shared__ int ws[8];
    if (lane==31) ws[wid]=x;
    __syncthreads();
    if (wid==0 && lane<8){
        int w = ws[lane];
        #pragma unroll
        for (int o=1;o<8;o<<=1){ int t=__shfl_up_sync(0xffu, w, o); if (lane>=o) w+=t; }
        ws[lane]=w;
    }
    __syncthreads();
    int ex = x - v + (wid>0? ws[wid-1]:0);
    if (i < NL) d_scanex[i] = ex;
    if (tid==255) d_bsum[blockIdx.x] = ex + v;
}
__global__ void k_scan_b(){
    int tid = threadIdx.x, lane = tid&31, wid = tid>>5;
    int v = (tid < SCB)? d_bsum[tid] : 0;
    int x = v;
    #pragma unroll
    for (int o=1;o<32;o<<=1){ int t=__shfl_up_sync(0xffffffffu, x, o); if (lane>=o) x+=t; }
    __shared__ int ws[8];
    if (lane==31) ws[wid]=x;
    __syncthreads();
    if (wid==0 && lane<8){
        int w = ws[lane];
        #pragma unroll
        for (int o=1;o<8;o<<=1){ int t=__shfl_up_sync(0xffu, w, o); if (lane>=o) w+=t; }
        ws[lane]=w;
    }
    __syncthreads();
    if (tid < SCB) d_boff[tid] = x - v + (wid>0? ws[wid-1]:0);
}
__global__ void k_scan_c(){
    int i = blockIdx.x*256 + threadIdx.x;
    if (i < NL) d_csroff[i] = d_scanex[i] + d_boff[blockIdx.x];
}

__global__ void k_fill(const int* __restrict__ elit){
    int e = blockIdx.x*blockDim.x + threadIdx.x;
    if (e >= NE) return;
    int l = elit[e];
    int p = atomicAdd(&d_cursor[l], 1);
    d_csrclause[d_csroff[l]+p] = e/3;
}

__global__ void k_segmin(const int* __restrict__ cgid, const int* __restrict__ vgid){
    int i = blockIdx.x*blockDim.x + threadIdx.x;
    if (i < NC) atomicMin(&d_cstart[cgid[i]], i);
    if (i < NV) atomicMin(&d_vstart[vgid[i]], i);
}

__global__ void k_segfix(){
    if (threadIdx.x==0){
        d_cstart[NG]=NC;
        for (int g=NG-1; g>=0; g--) d_cstart[g]=min(d_cstart[g], d_cstart[g+1]);
    }
    if (threadIdx.x==1){
        d_vstart[NG]=NV;
        for (int g=NG-1; g>=0; g--) d_vstart[g]=min(d_vstart[g], d_vstart[g+1]);
    }
}

__global__ void k_var_pre(const int* __restrict__ vgid){
    int v = blockIdx.x*blockDim.x + threadIdx.x;
    if (v >= NV) return;
    float m = 1.f - expf(-(d_var_sum[v] + d_var_sum[v+NV]));
    d_vmask[v] = m;
    atomicAdd(&d_vmask_gsum[vgid[v]], m);
    float dp = d_lit_deg[v], dn = d_lit_deg[v+NV];
    d_degw[v]    = rsqrtf(fmaxf(dp,1.f));
    d_degw[v+NV] = rsqrtf(fmaxf(dn,1.f));
    d_vdw[v]     = 4.f*rsqrtf(fmaxf(dp+dn,1.f));
}

__global__ void k_clause_pre(const int* __restrict__ cgid, const float* __restrict__ wsig){
    int c = blockIdx.x*blockDim.x + threadIdx.x;
    if (c >= NC) return;
    atomicAdd(&d_wsig_gsum[cgid[c]], wsig[c]);
}

__global__ void k_norms(const int* __restrict__ cgid, const int* __restrict__ vgid,
                        const float* __restrict__ wsig){
    int i = blockIdx.x*blockDim.x + threadIdx.x;
    if (i < NC){
        float s = d_wsig_gsum[cgid[i]];
        d_cg_norm[i] = wsig[i] * (s>0.f ? 1.f/s : 0.f);
    }
    if (i < NV){
        float s = d_vmask_gsum[vgid[i]];
        d_vg_norm[i] = d_vmask[i] * (s>0.f ? 1.f/s : 0.f);
    }
}

__global__ void k_pack_w(const float* __restrict__ W, int Ktrue, int N, int Kp,
                         uint32_t* __restrict__ Wh, uint32_t* __restrict__ Wl){
    int idx = blockIdx.x*blockDim.x + threadIdx.x;
    int hw = Kp>>1;
    if (idx >= N*hw) return;
    int n = idx/hw, kp = idx-n*hw;
    int k0 = 2*kp;
    float x0 = (k0   < Ktrue)? W[(size_t)k0*N+n]     : 0.f;
    float x1 = (k0+1 < Ktrue)? W[(size_t)(k0+1)*N+n] : 0.f;
    pack2(x0, x1, &Wh[idx], &Wl[idx]);
}

// ============== fused MLP kernels ==============

__global__ void __launch_bounds__(256,2)
k_qmlp(const float* __restrict__ X1, const float* __restrict__ X2,
       const uint32_t* __restrict__ W1h, const uint32_t* __restrict__ W1l, const float* __restrict__ B1,
       const uint32_t* __restrict__ W2h, const uint32_t* __restrict__ W2l, const float* __restrict__ B2,
       float* __restrict__ Y)
{
    extern __shared__ uint32_t sm[];
    uint32_t *Ah=sm, *Al=sm+8704, *Bh=sm+17408, *Bl=sm+18688;
    int tid=threadIdx.x, lane=tid&31, wid=tid>>5;
    int g=lane>>2, tig=lane&3;
    int m0=blockIdx.x*128;

    {
        int m=tid>>1, q=tid&1, gm=m0+m;
        #pragma unroll
        for (int h=0; h<12; h++){
            int c=(q*12+h)*4;
            float4 v={0.f,0.f,0.f,0.f};
            if (gm<NV){
                if (c<64) v=*(const float4*)(X1+(size_t)gm*64+c);
                else if (c<68) v=*(const float4*)(X2+(size_t)gm*4);
            }
            int w=m*SAW+(c>>1);
            pack2(v.x,v.y,&Ah[w],&Al[w]);
            pack2(v.z,v.w,&Ah[w+1],&Al[w+1]);
        }
    }
    float acc[8][4];
    #pragma unroll
    for (int b=0;b<8;b++){ acc[b][0]=0.f; acc[b][1]=0.f; acc[b][2]=0.f; acc[b][3]=0.f; }
    for (int k0=0;k0<96;k0+=32){
        stageB64(Bh,Bl,W1h,W1l,48,k0,tid);
        __syncthreads();
        int bw=k0>>1;
        #pragma unroll
        for (int ks=0;ks<2;ks++){
            uint32_t ah[4], al[4];
            fragA(Ah, wid*16+g, bw, ks, tig, SAW, ah);
            fragA(Al, wid*16+g, bw, ks, tig, SAW, al);
            #pragma unroll
            for (int nt=0;nt<8;nt++){
                int nb=(nt*8+g)*SB + ks*8 + tig;
                uint32_t bh0=Bh[nb], bh1=Bh[nb+4], bl0=Bl[nb], bl1=Bl[nb+4];
                MMA_BF16(acc[nt], ah, bh0, bh1);
                MMA_BF16(acc[nt], ah, bl0, bl1);
                MMA_BF16(acc[nt], al, bh0, bh1);
            }
        }
        __syncthreads();
    }
    {
        int lm0 = wid*16+g;
        #pragma unroll
        for (int nt=0;nt<8;nt++){
            int col = nt*8 + 2*tig;
            float bb0=__ldg(B1+col), bb1=__ldg(B1+col+1);
            float o0=fmaxf(acc[nt][0]+bb0,0.f), o1=fmaxf(acc[nt][1]+bb1,0.f);
            float o2=fmaxf(acc[nt][2]+bb0,0.f), o3=fmaxf(acc[nt][3]+bb1,0.f);
            int wcol = nt*4+tig;
            pack2(o0,o1,&Ah[lm0*SAW+wcol],&Al[lm0*SAW+wcol]);
            pack2(o2,o3,&Ah[(lm0+8)*SAW+wcol],&Al[(lm0+8)*SAW+wcol]);
        }
    }
    #pragma unroll
    for (int b=0;b<8;b++){ acc[b][0]=0.f; acc[b][1]=0.f; acc[b][2]=0.f; acc[b][3]=0.f; }
    __syncthreads();
    for (int k0=0;k0<64;k0+=32){
        stageB64(Bh,Bl,W2h,W2l,32,k0,tid);
        __syncthreads();
        int bw=k0>>1;
        #pragma unroll
        for (int ks=0;ks<2;ks++){
            uint32_t ah[4], al[4];
            fragA(Ah, wid*16+g, bw, ks, tig, SAW, ah);
            fragA(Al, wid*16+g, bw, ks, tig, SAW, al);
            #pragma unroll
            for (int nt=0;nt<8;nt++){
                int nb=(nt*8+g)*SB + ks*8 + tig;
                uint32_t bh0=Bh[nb], bh1=Bh[nb+4], bl0=Bl[nb], bl1=Bl[nb+4];
                MMA_BF16(acc[nt], ah, bh0, bh1);
                MMA_BF16(acc[nt], ah, bl0, bl1);
                MMA_BF16(acc[nt], al, bh0, bh1);
            }
        }
        __syncthreads();
    }
    int rm0 = m0 + wid*16 + g, rm1 = rm0 + 8;
    #pragma unroll
    for (int nt=0;nt<8;nt++){
        int col = nt*8 + 2*tig;
        float bb0=__ldg(B2+col), bb1=__ldg(B2+col+1);
        if (rm0<NV) *(float2*)(Y+(size_t)rm0*64+col) = make_float2(acc[nt][0]+bb0, acc[nt][1]+bb1);
        if (rm1<NV) *(float2*)(Y+(size_t)rm1*64+col) = make_float2(acc[nt][2]+bb0, acc[nt][3]+bb1);
    }
}

__global__ void __launch_bounds__(256,2)
k_cmlp(const float* __restrict__ X1, const float* __restrict__ X2,
       const uint32_t* __restrict__ W1h, const uint32_t* __restrict__ W1l, const float* __restrict__ B1,
       const uint32_t* __restrict__ W2h, const uint32_t* __restrict__ W2l, const float* __restrict__ B2,
       float* __restrict__ Y)
{
    extern __shared__ uint32_t sm[];
    uint32_t *Ah=sm, *Al=sm+8704, *Bh=sm+17408, *Bl=sm+19968;
    int tid=threadIdx.x, lane=tid&31, wid=tid>>5;
    int warp_m=wid>>1, warp_n=wid&1, g=lane>>2, tig=lane&3;
    int m0=blockIdx.x*128;

    {
        int m=tid>>1, q=tid&1, gm=m0+m;
        #pragma unroll
        for (int h=0; h<16; h++){
            int c=(q*16+h)*4;
            float4 v={0.f,0.f,0.f,0.f};
            if (gm<NC){
                if (c<64) v=*(const float4*)(X1+(size_t)gm*64+c);
                else {
                    v=*(const float4*)(X2+(size_t)gm*64+(c-64));
                    v.x*=4.f; v.y*=4.f; v.z*=4.f; v.w*=4.f;
                }
            }
            int w=m*SAW+(c>>1);
            pack2(v.x,v.y,&Ah[w],&Al[w]);
            pack2(v.z,v.w,&Ah[w+1],&Al[w+1]);
        }
    }
    float acc[2][8][4];
    #pragma unroll
    for (int a=0;a<2;a++)
        #pragma unroll
        for (int b=0;b<8;b++){ acc[a][b][0]=0.f; acc[a][b][1]=0.f; acc[a][b][2]=0.f; acc[a][b][3]=0.f; }
    for (int k0=0;k0<128;k0+=32){
        stageB128(Bh,Bl,W1h,W1l,64,k0,tid);
        __syncthreads();
        int bw=k0>>1;
        #pragma unroll
        for (int ks=0;ks<2;ks++){
            uint32_t ah[2][4], al[2][4];
            #pragma unroll
            for (int mt=0;mt<2;mt++){
                fragA(Ah, warp_m*32+mt*16+g, bw, ks, tig, SAW, ah[mt]);
                fragA(Al, warp_m*32+mt*16+g, bw, ks, tig, SAW, al[mt]);
            }
            #pragma unroll
            for (int nt=0;nt<8;nt++){
                int nb=(warp_n*64+nt*8+g)*SB + ks*8 + tig;
                uint32_t bh0=Bh[nb], bh1=Bh[nb+4], bl0=Bl[nb], bl1=Bl[nb+4];
                #pragma unroll
                for (int mt=0;mt<2;mt++){
                    MMA_BF16(acc[mt][nt], ah[mt], bh0, bh1);
                    MMA_BF16(acc[mt][nt], ah[mt], bl0, bl1);
                    MMA_BF16(acc[mt][nt], al[mt], bh0, bh1);
                }
            }
        }
        __syncthreads();
    }
    #pragma unroll
    for (int mt=0;mt<2;mt++){
        int lm0 = warp_m*32+mt*16+g;
        #pragma unroll
        for (int nt=0;nt<8;nt++){
            int col = warp_n*64 + nt*8 + 2*tig;
            float bb0=__ldg(B1+col), bb1=__ldg(B1+col+1);
            float o0=fmaxf(acc[mt][nt][0]+bb0,0.f), o1=fmaxf(acc[mt][nt][1]+bb1,0.f);
            float o2=fmaxf(acc[mt][nt][2]+bb0,0.f), o3=fmaxf(acc[mt][nt][3]+bb1,0.f);
            int wcol = warp_n*32 + nt*4 + tig;
            pack2(o0,o1,&Ah[lm0*SAW+wcol],&Al[lm0*SAW+wcol]);
            pack2(o2,o3,&Ah[(lm0+8)*SAW+wcol],&Al[(lm0+8)*SAW+wcol]);
            acc[mt][nt][0]=0.f; acc[mt][nt][1]=0.f; acc[mt][nt][2]=0.f; acc[mt][nt][3]=0.f;
        }
    }
    __syncthreads();
    for (int k0=0;k0<128;k0+=32){
        stageB128(Bh,Bl,W2h,W2l,64,k0,tid);
        __syncthreads();
        int bw=k0>>1;
        #pragma unroll
        for (int ks=0;ks<2;ks++){
            uint32_t ah[2][4], al[2][4];
            #pragma unroll
            for (int mt=0;mt<2;mt++){
                fragA(Ah, warp_m*32+mt*16+g, bw, ks, tig, SAW, ah[mt]);
                fragA(Al, warp_m*32+mt*16+g, bw, ks, tig, SAW, al[mt]);
            }
            #pragma unroll
            for (int nt=0;nt<8;nt++){
                int nb=(warp_n*64+nt*8+g)*SB + ks*8 + tig;
                uint32_t bh0=Bh[nb], bh1=Bh[nb+4], bl0=Bl[nb], bl1=Bl[nb+4];
                #pragma unroll
                for (int mt=0;mt<2;mt++){
                    MMA_BF16(acc[mt][nt], ah[mt], bh0, bh1);
                    MMA_BF16(acc[mt][nt], ah[mt], bl0, bl1);
                    MMA_BF16(acc[mt][nt], al[mt], bh0, bh1);
                }
            }
        }
        __syncthreads();
    }
    #pragma unroll
    for (int mt=0;mt<2;mt++){
        int rm0 = m0 + warp_m*32 + mt*16 + g, rm1 = rm0 + 8;
        #pragma unroll
        for (int nt=0;nt<8;nt++){
            int col = warp_n*64 + nt*8 + 2*tig;
            float bb0=__ldg(B2+col), bb1=__ldg(B2+col+1);
            if (rm0<NC) *(float2*)(Y+(size_t)rm0*128+col) = make_float2(acc[mt][nt][0]+bb0, acc[mt][nt][1]+bb1);
            if (rm1<NC) *(float2*)(Y+(size_t)rm1*128+col) = make_float2(acc[mt][nt][2]+bb0, acc[mt][nt][3]+bb1);
        }
    }
}

__global__ void __launch_bounds__(256,2)
k_umlp(const float* __restrict__ X1,
       const uint32_t* __restrict__ W1h, const uint32_t* __restrict__ W1l, const float* __restrict__ B1,
       const uint32_t* __restrict__ W2h, const uint32_t* __restrict__ W2l, const float* __restrict__ B2,
       const uint32_t* __restrict__ W3h, const uint32_t* __restrict__ W3l, const float* __restrict__ B3,
       float* __restrict__ Y)
{
    extern __shared__ uint32_t sm[];
    uint32_t *Ah=sm, *Al=sm+8704, *Bh=sm+17408, *Bl=sm+19968;
    int tid=threadIdx.x, lane=tid&31, wid=tid>>5;
    int warp_m=wid>>1, warp_n=wid&1, g=lane>>2, tig=lane&3;
    int m0=blockIdx.x*128;

    float acc[2][8][4];
    #pragma unroll
    for (int a=0;a<2;a++)
        #pragma unroll
        for (int b=0;b<8;b++){ acc[a][b][0]=0.f; acc[a][b][1]=0.f; acc[a][b][2]=0.f; acc[a][b][3]=0.f; }

    int m=tid>>1, q=tid&1, gm=m0+m;
    for (int k0=0;k0<256;k0+=32){
        #pragma unroll
        for (int h=0;h<4;h++){
            int c = k0 + (q*4+h)*4;
            float4 v={0.f,0.f,0.f,0.f};
            if (gm<NV) v=*(const float4*)(X1+(size_t)gm*256+c);
            int kp=(q*4+h)*2;
            pack2(v.x,v.y,&Ah[m*SAW+kp],  &Al[m*SAW+kp]);
            pack2(v.z,v.w,&Ah[m*SAW+kp+1],&Al[m*SAW+kp+1]);
        }
        stageB128(Bh,Bl,W1h,W1l,128,k0,tid);
        __syncthreads();
        #pragma unroll
        for (int ks=0;ks<2;ks++){
            uint32_t ah[2][4], al[2][4];
            #pragma unroll
            for (int mt=0;mt<2;mt++){
                fragA(Ah, warp_m*32+mt*16+g, 0, ks, tig, SAW, ah[mt]);
                fragA(Al, warp_m*32+mt*16+g, 0, ks, tig, SAW, al[mt]);
            }
            #pragma unroll
            for (int nt=0;nt<8;nt++){
                int nb=(warp_n*64+nt*8+g)*SB + ks*8 + tig;
                uint32_t bh0=Bh[nb], bh1=Bh[nb+4], bl0=Bl[nb], bl1=Bl[nb+4];
                #pragma unroll
                for (int mt=0;mt<2;mt++){
                    MMA_BF16(acc[mt][nt], ah[mt], bh0, bh1);
                    MMA_BF16(acc[mt][nt], ah[mt], bl0, bl1);
                    MMA_BF16(acc[mt][nt], al[mt], bh0, bh1);
                }
            }
        }
        __syncthreads();
    }
    #pragma unroll
    for (int mt=0;mt<2;mt++){
        int lm0 = warp_m*32+mt*16+g;
        #pragma unroll
        for (int nt=0;nt<8;nt++){
            int col = warp_n*64 + nt*8 + 2*tig;
            float bb0=__ldg(B1+col), bb1=__ldg(B1+col+1);
            float o0=fmaxf(acc[mt][nt][0]+bb0,0.f), o1=fmaxf(acc[mt][nt][1]+bb1,0.f);
            float o2=fmaxf(acc[mt][nt][2]+bb0,0.f), o3=fmaxf(acc[mt][nt][3]+bb1,0.f);
            int wcol = warp_n*32 + nt*4 + tig;
            pack2(o0,o1,&Ah[lm0*SAW+wcol],&Al[lm0*SAW+wcol]);
            pack2(o2,o3,&Ah[(lm0+8)*SAW+wcol],&Al[(lm0+8)*SAW+wcol]);
            acc[mt][nt][0]=0.f; acc[mt][nt][1]=0.f; acc[mt][nt][2]=0.f; acc[mt][nt][3]=0.f;
        }
    }
    __syncthreads();
    for (int k0=0;k0<128;k0+=32){
        stageB128(Bh,Bl,W2h,W2l,64,k0,tid);
        __syncthreads();
        int bw=k0>>1;
        #pragma unroll
        for (int ks=0;ks<2;ks++){
            uint32_t ah[2][4], al[2][4];
            #pragma unroll
            for (int mt=0;mt<2;mt++){
                fragA(Ah, warp_m*32+mt*16+g, bw, ks, tig, SAW, ah[mt]);
                fragA(Al, warp_m*32+mt*16+g, bw, ks, tig, SAW, al[mt]);
            }
            #pragma unroll
            for (int nt=0;nt<8;nt++){
                int nb=(warp_n*64+nt*8+g)*SB + ks*8 + tig;
                uint32_t bh0=Bh[nb], bh1=Bh[nb+4], bl0=Bl[nb], bl1=Bl[nb+4];
                #pragma unroll
                for (int mt=0;mt<2;mt++){
                    MMA_BF16(acc[mt][nt], ah[mt], bh0, bh1);
                    MMA_BF16(acc[mt][nt], ah[mt], bl0, bl1);
                    MMA_BF16(acc[mt][nt], al[mt], bh0, bh1);
                }
            }
        }
        __syncthreads();
    }
    #pragma unroll
    for (int mt=0;mt<2;mt++){
        int lm0 = warp_m*32+mt*16+g;
        #pragma unroll
        for (int nt=0;nt<8;nt++){
            int col = warp_n*64 + nt*8 + 2*tig;
            float bb0=__ldg(B2+col), bb1=__ldg(B2+col+1);
            float o0=fmaxf(acc[mt][nt][0]+bb0,0.f), o1=fmaxf(acc[mt][nt][1]+bb1,0.f);
            float o2=fmaxf(acc[mt][nt][2]+bb0,0.f), o3=fmaxf(acc[mt][nt][3]+bb1,0.f);
            int wcol = warp_n*32 + nt*4 + tig;
            pack2(o0,o1,&Ah[lm0*SAW+wcol],&Al[lm0*SAW+wcol]);
            pack2(o2,o3,&Ah[(lm0+8)*SAW+wcol],&Al[(lm0+8)*SAW+wcol]);
        }
    }
    __syncthreads();
    float acc3[8][4];
    #pragma unroll
    for (int b=0;b<8;b++){ acc3[b][0]=0.f; acc3[b][1]=0.f; acc3[b][2]=0.f; acc3[b][3]=0.f; }
    for (int k0=0;k0<128;k0+=32){
        stageB64(Bh,Bl,W3h,W3l,64,k0,tid);
        __syncthreads();
        int bw=k0>>1;
        #pragma unroll
        for (int ks=0;ks<2;ks++){
            uint32_t ah[4], al[4];
            fragA(Ah, wid*16+g, bw, ks, tig, SAW, ah);
            fragA(Al, wid*16+g, bw, ks, tig, SAW, al);
            #pragma unroll
            for (int nt=0;nt<8;nt++){
                int nb=(nt*8+g)*SB + ks*8 + tig;
                uint32_t bh0=Bh[nb], bh1=Bh[nb+4], bl0=Bl[nb], bl1=Bl[nb+4];
                MMA_BF16(acc3[nt], ah, bh0, bh1);
                MMA_BF16(acc3[nt], ah, bl0, bl1);
                MMA_BF16(acc3[nt], al, bh0, bh1);
            }
        }
        __syncthreads();
    }
    int rm0 = m0 + wid*16 + g, rm1 = rm0 + 8;
    #pragma unroll
    for (int nt=0;nt<8;nt++){
        int col = nt*8 + 2*tig;
        float bb0=__ldg(B3+col), bb1=__ldg(B3+col+1);
        if (rm0<NV) *(float2*)(Y+(size_t)rm0*64+col) = make_float2(acc3[nt][0]+bb0, acc3[nt][1]+bb1);
        if (rm1<NV) *(float2*)(Y+(size_t)rm1*64+col) = make_float2(acc3[nt][2]+bb0, acc3[nt][3]+bb1);
    }
}

__global__ void __launch_bounds__(256,2)
k_fused_o(const int* __restrict__ vgid,
          const uint32_t* __restrict__ Wh, const uint32_t* __restrict__ Wl,
          const float* __restrict__ Bias,
          const float* __restrict__ ow2, const float* __restrict__ ob2)
{
    __shared__ uint32_t Ah[128*SB], Al[128*SB], Bh[64*SB], Bl[64*SB];
    int tid = threadIdx.x, lane = tid&31, wid = tid>>5;
    int g = lane>>2, tig = lane&3;
    int m0 = blockIdx.x*128;
    if (blockIdx.x==0 && tid==0) d_allsat = 1;
    int done = d_done;

    float acc[8][4];
    #pragma unroll
    for (int b=0;b<8;b++){ acc[b][0]=0.f; acc[b][1]=0.f; acc[b][2]=0.f; acc[b][3]=0.f; }

    int m = tid>>1, q = tid&1, gm = m0+m;
    float rs = 0.f; const float* mrow = nullptr;
    if (gm < NV){
        int gg = vgid[gm];
        rs = rsqrtf(d_varred[gg]+1e-6f)*0.25f;
        mrow = &d_mean[gg*64];
    }

    for (int k0=0; k0<64; k0+=32){
        #pragma unroll
        for (int h=0; h<4; h++){
            int c = k0 + (q*4+h)*4;
            float4 v = {0.f,0.f,0.f,0.f};
            if (gm < NV){
                float4 vv = *(const float4*)(d_variables + (size_t)gm*64 + c);
                if (done) v = vv;
                else {
                    float4 u = *(const float4*)(d_uout + (size_t)gm*64 + c);
                    v.x = (u.x - mrow[c  ])*rs + 0.1f*vv.x;
                    v.y = (u.y - mrow[c+1])*rs + 0.1f*vv.y;
                    v.z = (u.z - mrow[c+2])*rs + 0.1f*vv.z;
                    v.w = (u.w - mrow[c+3])*rs + 0.1f*vv.w;
                    *(float4*)(d_variables + (size_t)gm*64 + c) = v;
                }
            }
            int kp = (q*4+h)*2;
            pack2(v.x,v.y,&Ah[m*SB+kp],  &Al[m*SB+kp]);
            pack2(v.z,v.w,&Ah[m*SB+kp+1],&Al[m*SB+kp+1]);
        }
        stageB64(Bh,Bl,Wh,Wl,32,k0,tid);
        __syncthreads();
        #pragma unroll
        for (int ks=0; ks<2; ks++){
            uint32_t ah[4], al[4];
            fragA(Ah, wid*16+g, 0, ks, tig, SB, ah);
            fragA(Al, wid*16+g, 0, ks, tig, SB, al);
            #pragma unroll
            for (int nt=0; nt<8; nt++){
                int nb = (nt*8+g)*SB + ks*8 + tig;
                uint32_t bh0=Bh[nb], bh1=Bh[nb+4], bl0=Bl[nb], bl1=Bl[nb+4];
                MMA_BF16(acc[nt], ah, bh0, bh1);
                MMA_BF16(acc[nt], ah, bl0, bl1);
                MMA_BF16(acc[nt], al, bh0, bh1);
            }
        }
        __syncthreads();
    }
    float p0=0.f, p1=0.f;
    #pragma unroll
    for (int nt=0; nt<8; nt++){
        int col = nt*8 + 2*tig;
        float bb0 = __ldg(Bias+col), bb1 = __ldg(Bias+col+1);
        float w0 = __ldg(ow2+col),  w1 = __ldg(ow2+col+1);
        float o0=fmaxf(acc[nt][0]+bb0,0.f), o1=fmaxf(acc[nt][1]+bb1,0.f);
        float o2=fmaxf(acc[nt][2]+bb0,0.f), o3=fmaxf(acc[nt][3]+bb1,0.f);
        p0 += o0*w0 + o1*w1;
        p1 += o2*w0 + o3*w1;
    }
    p0 += __shfl_xor_sync(0xffffffffu, p0, 1);
    p0 += __shfl_xor_sync(0xffffffffu, p0, 2);
    p1 += __shfl_xor_sync(0xffffffffu, p1, 1);
    p1 += __shfl_xor_sync(0xffffffffu, p1, 2);
    if (tig==0){
        float ob = __ldg(ob2);
        int rm0 = m0 + wid*16 + g, rm1 = rm0 + 8;
        if (rm0 < NV){
            float lg = p0 + ob;
            d_logits[rm0] = lg;
            if (!done) d_last_logits[rm0] = lg;
        }
        if (rm1 < NV){
            float lg = p1 + ob;
            d_logits[rm1] = lg;
            if (!done) d_last_logits[rm1] = lg;
        }
    }
}

// ---------------- per-round kernels ----------------
__global__ void k_clause_cval(const int* __restrict__ elit, const float* __restrict__ wsig){
    int gw = (blockIdx.x*blockDim.x + threadIdx.x)>>5;
    int lane = threadIdx.x & 31;
    if (gw >= NC) return;
    float w = wsig[gw];
    float2 acc = {0.f,0.f};
    #pragma unroll
    for (int j=0;j<3;j++){
        int l = elit[3*gw+j];
        int v = (l<NV)? l : l-NV;
        float sgn = (l<NV)? 1.f : -1.f;
        float2 qv = *(const float2*)(d_query + (size_t)v*64 + lane*2);
        acc.x += sp_f(sgn*qv.x);
        acc.y += sp_f(sgn*qv.y);
    }
    float2 cl = { expf(-w*acc.x), expf(-w*acc.y) };
    *(float2*)(d_closs + (size_t)gw*64 + lane*2) = cl;
}

__global__ void k_var_grad(const float* __restrict__ wsig){
    int gw = (blockIdx.x*blockDim.x + threadIdx.x)>>5;
    int lane = threadIdx.x & 31;
    if (gw >= NV) return;
    int v = gw;
    float2 ap={0.f,0.f}, an={0.f,0.f};
    int s0=d_csroff[v], e0=d_csroff[v+1];
    for (int i=s0;i<e0;i++){
        int c = d_csrclause[i];
        float w=wsig[c];
        float2 cl=*(const float2*)(d_closs+(size_t)c*64+lane*2);
        ap.x += w*cl.x; ap.y += w*cl.y;
    }
    int s1=d_csroff[NV+v], e1=d_csroff[NV+v+1];
    for (int i=s1;i<e1;i++){
        int c = d_csrclause[i];
        float w=wsig[c];
        float2 cl=*(const float2*)(d_closs+(size_t)c*64+lane*2);
        an.x += w*cl.x; an.y += w*cl.y;
    }
    float2 qv = *(const float2*)(d_query + (size_t)v*64 + lane*2);
    float vd = d_vdw[v];
    float2 gg;
    gg.x = (-ap.x*sigm(qv.x) + an.x*sigm(-qv.x)) * vd;
    gg.y = (-ap.y*sigm(qv.y) + an.y*sigm(-qv.y)) * vd;
    *(float2*)(d_unit + (size_t)v*256 + lane*2) = gg;
    float2 vv = *(const float2*)(d_variables + (size_t)v*64 + lane*2);
    *(float2*)(d_unit + (size_t)v*256 + 64 + lane*2) = vv;
}

__global__ void k_pn_c(){
    int g=blockIdx.x;
    int s=d_cstart[g], e=d_cstart[g+1];
    int f=threadIdx.x&63, grp=threadIdx.x>>6;
    float s1=0.f, s2=0.f;
    for (int r=s+grp; r<e; r+=4){
        float wr = d_cg_norm[r];
        float xv = d_cdata[(size_t)r*128 + 64 + f];
        float wx = wr*xv;
        s1 += wx; s2 += wx*xv;
    }
    __shared__ float r1[256], r2[256];
    __shared__ float smean[64];
    __shared__ float srs;
    r1[threadIdx.x]=s1; r2[threadIdx.x]=s2; __syncthreads();
    if (threadIdx.x<64){
        float S1 = r1[f]+r1[64+f]+r1[128+f]+r1[192+f];
        float S2 = r2[f]+r2[64+f]+r2[128+f]+r2[192+f];
        smean[f]=S1;
        r1[f] = S2 - S1*S1;
    }
    __syncthreads();
    if (threadIdx.x<32){
        float v = r1[threadIdx.x]+r1[threadIdx.x+32];
        for (int o=16;o;o>>=1) v += __shfl_down_sync(0xffffffffu, v, o);
        if (threadIdx.x==0) srs = rsqrtf(v*(1.f/64.f)+1e-6f)*0.25f;
    }
    __syncthreads();
    if (d_done) return;
    float rs = srs;
    int total = (e-s)*64;
    for (int idx=threadIdx.x; idx<total; idx+=256){
        int r = s + (idx>>6);
        int ff = idx&63;
        float xc = d_cdata[(size_t)r*128 + 64 + ff] - smean[ff];
        size_t o = (size_t)r*64 + ff;
        d_clause_state[o] = xc*rs + 0.1f*d_clause_state[o];
    }
}

__global__ void k_pn_stats_v(){
    int g=blockIdx.x;
    int s=d_vstart[g], e=d_vstart[g+1];
    int f=threadIdx.x&63, grp=threadIdx.x>>6;
    float s1=0.f, s2=0.f;
    for (int r=s+grp; r<e; r+=4){
        float wr = d_vg_norm[r];
        float xv = d_uout[(size_t)r*64+f];
        float wx = wr*xv;
        s1 += wx; s2 += wx*xv;
    }
    __shared__ float r1[256], r2[256];
    r1[threadIdx.x]=s1; r2[threadIdx.x]=s2; __syncthreads();
    if (threadIdx.x<64){
        float S1 = r1[f]+r1[64+f]+r1[128+f]+r1[192+f];
        float S2 = r2[f]+r2[64+f]+r2[128+f]+r2[192+f];
        d_mean[g*64+f]=S1;
        r1[f] = S2 - S1*S1;
    }
    __syncthreads();
    if (threadIdx.x<32){
        float v = r1[threadIdx.x]+r1[threadIdx.x+32];
        for (int o=16;o;o>>=1) v += __shfl_down_sync(0xffffffffu, v, o);
        if (threadIdx.x==0) d_varred[g]=v*(1.f/64.f);
    }
}

__global__ void k_var_loss(const float* __restrict__ wsig){
    int gw = (blockIdx.x*blockDim.x + threadIdx.x)>>5;
    int lane = threadIdx.x & 31;
    if (gw >= NV) return;
    int v = gw;
    float2 ap={0.f,0.f}, an={0.f,0.f};
    int s0=d_csroff[v], e0=d_csroff[v+1];
    for (int i=s0;i<e0;i++){
        int c = d_csrclause[i];
        float w=wsig[c];
        float2 cl=*(const float2*)(d_cdata+(size_t)c*128+lane*2);
        ap.x += w*cl.x; ap.y += w*cl.y;
    }
    int s1=d_csroff[NV+v], e1=d_csroff[NV+v+1];
    for (int i=s1;i<e1;i++){
        int c = d_csrclause[i];
        float w=wsig[c];
        float2 cl=*(const float2*)(d_cdata+(size_t)c*128+lane*2);
        an.x += w*cl.x; an.y += w*cl.y;
    }
    float dp = d_degw[v], dn = d_degw[NV+v];
    *(float2*)(d_unit + (size_t)v*256 + 128 + lane*2) = make_float2(ap.x*dp, ap.y*dp);
    *(float2*)(d_unit + (size_t)v*256 + 192 + lane*2) = make_float2(an.x*dn, an.y*dn);
}

__global__ void k_final_clause(const int* __restrict__ elit, const float* __restrict__ wsig){
    __shared__ float sred[256];
    __shared__ int ssat[256];
    __shared__ int slast;
    int g = blockIdx.x;
    int s = d_cstart[g], e = d_cstart[g+1];
    float lsum=0.f; int sat=1;
    for (int c=s+threadIdx.x; c<e; c+=blockDim.x){
        float w = wsig[c];
        float cvs=0.f, csat=0.f;
        #pragma unroll
        for (int j=0;j<3;j++){
            int l = elit[3*c+j];
            int v = (l<NV)? l : l-NV;
            float sgn = (l<NV)? 1.f : -1.f;
            float lg = d_logits[v];
            cvs += sp_f(sgn*lg);
            float a = (lg>0.f)? 1.f : 0.f;
            float lit01 = (l<NV)? a : 1.f-a;
            csat += w*lit01;
        }
        float cv = expf(-w*cvs);
        float pc = cv * (-logf(1.f - cv + 1e-10f));
        lsum += pc*w;
        if (csat < 1.f) sat = 0;
    }
    sred[threadIdx.x]=lsum; ssat[threadIdx.x]=sat; __syncthreads();
    for (int o=128;o;o>>=1){
        if (threadIdx.x<o){ sred[threadIdx.x]+=sred[threadIdx.x+o]; ssat[threadIdx.x]&=ssat[threadIdx.x+o]; }
        __syncthreads();
    }
    if (threadIdx.x==0){
        d_pg[g]=sred[0];
        if (!ssat[0]) d_allsat = 0;
        __threadfence();
        slast = (atomicAdd(&d_fc_count,1) == NG-1);
    }
    __syncthreads();
    if (slast){
        __threadfence();
        int done0 = d_done;
        if (!done0 && threadIdx.x < NG)
            d_loss_sum[threadIdx.x] += sqrtf(d_pg[threadIdx.x]+1e-6f) - 0.001f;
        __syncthreads();
        if (threadIdx.x==0){
            if (!done0){
                d_step++;
                if (d_allsat) d_done = 1;
            }
            d_fc_count = 0;
        }
    }
}

__global__ void k_output(float* __restrict__ out, int n){
    int i = blockIdx.x*blockDim.x + threadIdx.x;
    if (i >= n) return;
    float v;
    if (i < NV)            v = d_last_logits[i];
    else if (i < NV+NG)    v = d_loss_sum[i-NV]*(1.f/(float)RNDS);
    else if (i == NV+NG)   v = (float)d_step;
    else                   v = 0.f;
    out[i] = v;
}

// ---------------- host ----------------
extern "C" void kernel_launch(void* const* d_in, const int* in_sizes, int n_in,
                              void* d_out, int out_size){
    const float* wsig   = (const float*)d_in[0];
    const float* wsp    = (const float*)d_in[1];
    const float* noise  = (const float*)d_in[2];
    const int*   elit   = (const int*)d_in[3];
    const int*   eclause= (const int*)d_in[4];
    const int*   cgid   = (const int*)d_in[5];
    const int*   vgid   = (const int*)d_in[6];
    const float* P[18];
    for (int i=0;i<18;i++) P[i]=(const float*)d_in[7+i];
    const float *qw1=P[0],*qb1=P[1],*qw2=P[2],*qb2=P[3];
    const float *cw1=P[4],*cb1=P[5],*cw2=P[6],*cb2=P[7];
    const float *uw1=P[8],*ub1=P[9],*uw2=P[10],*ub2=P[11],*uw3=P[12],*ub3=P[13];
    const float *ow1=P[14],*ob1=P[15],*ow2=P[16],*ob2=P[17];

    float *p_query,*p_cdata,*p_unit,*p_uout,*p_vars,*p_cs,*p_closs;
    uint32_t *p_wh, *p_wl;
    cudaGetSymbolAddress((void**)&p_query, d_query);
    cudaGetSymbolAddress((void**)&p_cdata, d_cdata);
    cudaGetSymbolAddress((void**)&p_unit,  d_unit);
    cudaGetSymbolAddress((void**)&p_uout,  d_uout);
    cudaGetSymbolAddress((void**)&p_vars,  d_variables);
    cudaGetSymbolAddress((void**)&p_cs,    d_clause_state);
    cudaGetSymbolAddress((void**)&p_closs, d_closs);
    cudaGetSymbolAddress((void**)&p_wh,    d_wh);
    cudaGetSymbolAddress((void**)&p_wl,    d_wl);

    const int GVg = CEILDIV(NV,128);   // 157
    const int GCg = CEILDIV(NC,128);   // 657

    const int OQ1=0, OQ2=3072, OC1=5120, OC2=13312, OU1=21504, OU2=37888, OU3=46080, OO1=50176;

    const int QSMEM = 19968*4;
    const int CSMEM = 22528*4;
    cudaFuncSetAttribute(k_qmlp, cudaFuncAttributeMaxDynamicSharedMemorySize, QSMEM);
    cudaFuncSetAttribute(k_cmlp, cudaFuncAttributeMaxDynamicSharedMemorySize, CSMEM);
    cudaFuncSetAttribute(k_umlp, cudaFuncAttributeMaxDynamicSharedMemorySize, CSMEM);

    // side stream + events (created once; graph capture records identical nodes each call)
    static cudaStream_t s2 = nullptr;
    static cudaEvent_t evA=nullptr, evB=nullptr, evC=nullptr, evD=nullptr, evF=nullptr, evFin=nullptr;
    if (!s2){
        cudaStreamCreateWithFlags(&s2, cudaStreamNonBlocking);
        cudaEventCreateWithFlags(&evA,  cudaEventDisableTiming);
        cudaEventCreateWithFlags(&evB,  cudaEventDisableTiming);
        cudaEventCreateWithFlags(&evC,  cudaEventDisableTiming);
        cudaEventCreateWithFlags(&evD,  cudaEventDisableTiming);
        cudaEventCreateWithFlags(&evF,  cudaEventDisableTiming);
        cudaEventCreateWithFlags(&evFin,cudaEventDisableTiming);
    }

    // ---- init / precompute (main stream) ----
    k_init<<<CEILDIV(2*NV,256),256>>>();
    k_init_state<<<CEILDIV(NC*64,256),256>>>();
    k_edge_scatter<<<CEILDIV(NE,256),256>>>(elit, eclause, wsig, wsp);
    k_scan_a<<<SCB,256>>>();
    k_scan_b<<<1,256>>>();
    k_scan_c<<<SCB,256>>>();
    k_fill<<<CEILDIV(NE,256),256>>>(elit);
    k_segmin<<<CEILDIV(NC,256),256>>>(cgid, vgid);
    k_segfix<<<1,32>>>();
    k_var_pre<<<CEILDIV(NV,256),256>>>(vgid);
    k_clause_pre<<<CEILDIV(NC,256),256>>>(cgid, wsig);
    k_norms<<<CEILDIV(NC,256),256>>>(cgid, vgid, wsig);

    // ---- pack weights ----
    k_pack_w<<<CEILDIV(64*48,256),256>>>(qw1,  68, 64, 96, p_wh+OQ1, p_wl+OQ1);
    k_pack_w<<<CEILDIV(64*32,256),256>>>(qw2,  64, 64, 64, p_wh+OQ2, p_wl+OQ2);
    k_pack_w<<<CEILDIV(128*64,256),256>>>(cw1, 128,128,128, p_wh+OC1, p_wl+OC1);
    k_pack_w<<<CEILDIV(128*64,256),256>>>(cw2, 128,128,128, p_wh+OC2, p_wl+OC2);
    k_pack_w<<<CEILDIV(128*128,256),256>>>(uw1,256,128,256, p_wh+OU1, p_wl+OU1);
    k_pack_w<<<CEILDIV(128*64,256),256>>>(uw2, 128,128,128, p_wh+OU2, p_wl+OU2);
    k_pack_w<<<CEILDIV(64*64,256),256>>>(uw3, 128, 64,128, p_wh+OU3, p_wl+OU3);
    k_pack_w<<<CEILDIV(64*32,256),256>>>(ow1,  64, 64, 64, p_wh+OO1, p_wl+OO1);

    // seed join-event so the first wait is capture-legal
    cudaEventRecord(evFin, 0);

    // ---- rounds (fork/join overlap on s2) ----
    for (int t=0; t<RNDS; t++){
        const float* nt = noise + (size_t)t*NV*4;
        k_qmlp<<<GVg,256,QSMEM>>>(p_vars, nt, p_wh+OQ1, p_wl+OQ1, qb1,
                                  p_wh+OQ2, p_wl+OQ2, qb2, p_query);
        k_clause_cval<<<CEILDIV(NC*32,256),256>>>(elit, wsig);
        cudaEventRecord(evA, 0);
        // side: var_grad (needs closs only) overlaps cmlp
        cudaStreamWaitEvent(s2, evA, 0);
        k_var_grad<<<CEILDIV(NV*32,256),256,0,s2>>>(wsig);
        cudaEventRecord(evB, s2);
        // main: cmlp (needs closs + clause_state)
        k_cmlp<<<GCg,256,CSMEM>>>(p_cs, p_closs, p_wh+OC1, p_wl+OC1, cb1,
                                  p_wh+OC2, p_wl+OC2, cb2, p_cdata);
        cudaEventRecord(evC, 0);
        // side: var_loss (needs cdata) overlaps pn_c
        cudaStreamWaitEvent(s2, evC, 0);
        k_var_loss<<<CEILDIV(NV*32,256),256,0,s2>>>(wsig);
        cudaEventRecord(evD, s2);
        // main: join prev-round final (d_done readers start at pn_c), then pn_c
        cudaStreamWaitEvent(0, evFin, 0);
        k_pn_c<<<NG,256>>>();
        // join var_grad + var_loss before umlp (unit fully written)
        cudaStreamWaitEvent(0, evB, 0);
        cudaStreamWaitEvent(0, evD, 0);
        k_umlp<<<GVg,256,CSMEM>>>(p_unit, p_wh+OU1, p_wl+OU1, ub1,
                                  p_wh+OU2, p_wl+OU2, ub2,
                                  p_wh+OU3, p_wl+OU3, ub3, p_uout);
        k_pn_stats_v<<<NG,256>>>();
        k_fused_o<<<GVg,256>>>(vgid, p_wh+OO1, p_wl+OO1, ob1, ow2, ob2);
        cudaEventRecord(evF, 0);
        // side: final_clause overlaps next round's front (qmlp/cval/vgrad/cmlp)
        cudaStreamWaitEvent(s2, evF, 0);
        k_final_clause<<<NG,256,0,s2>>>(elit, wsig);
        cudaEventRecord(evFin, s2);
    }

    cudaStreamWaitEvent(0, evFin, 0);
    k_output<<<CEILDIV(out_size>0?out_size:1,256),256>>>((float*)d_out, out_size);
}

// round 13
// speedup vs baseline: 1.1135x; 1.0253x over previous
#include <cuda_runtime.h>
#include <cuda_bf16.h>
#include <cstdint>

#define NV 20000
#define NC 84000
#define NG 200
#define NE 252000
#define RNDS 8
#define CEILDIV(a,b) (((a)+(b)-1)/(b))
#define SB 20    // staged-B row stride (words)
#define SAW 68   // full-width A row stride (words)
#define NL 40000          // 2*NV literals
#define SCB 157           // CEILDIV(NL,256)
#define VGB 2500          // warp-per-variable blocks (8 warps each)

// ---------------- scratch (device globals) ----------------
__device__ __align__(16) float d_variables[NV*64];
__device__ __align__(16) float d_clause_state[NC*64];
__device__ __align__(16) float d_query[NV*64];
__device__ __align__(16) float d_closs[NC*64];
__device__ __align__(16) float d_cdata[NC*128];
__device__ __align__(16) float d_unit[NV*256];
__device__ __align__(16) float d_uout[NV*64];
__device__ float d_logits[NV];
__device__ float d_last_logits[NV];

__device__ __align__(16) uint32_t d_wh[52224];
__device__ __align__(16) uint32_t d_wl[52224];

__device__ float d_var_sum[2*NV];
__device__ float d_lit_deg[2*NV];
__device__ float d_degw[2*NV];
__device__ float d_vdw[NV];
__device__ float d_vmask[NV];
__device__ float d_vg_norm[NV];
__device__ float d_cg_norm[NC];
__device__ float d_vmask_gsum[NG];
__device__ float d_wsig_gsum[NG];
__device__ float d_loss_sum[NG];
__device__ float d_pg[NG];
__device__ float d_mean[NG*64];
__device__ float d_varred[NG];

__device__ int d_counts[2*NV];
__device__ int d_csroff[2*NV+1];
__device__ int d_scanex[2*NV];
__device__ int d_bsum[SCB];
__device__ int d_boff[SCB];
__device__ int d_cursor[2*NV];
__device__ int d_csrclause[NE];
__device__ int d_cstart[NG+1];
__device__ int d_vstart[NG+1];
__device__ int d_done;
__device__ int d_allsat;
__device__ int d_step;
__device__ int d_fc_count;

// ---------------- helpers ----------------
__device__ __forceinline__ float sp_f(float x){ return fmaxf(x,0.f)+log1pf(expf(-fabsf(x))); }
__device__ __forceinline__ float sigm(float x){ return 1.f/(1.f+expf(-x)); }

__device__ __forceinline__ void pack2(float x0, float x1, uint32_t* ph, uint32_t* pl){
    __nv_bfloat16 h0 = __float2bfloat16_rn(x0);
    __nv_bfloat16 h1 = __float2bfloat16_rn(x1);
    float r0 = x0 - __bfloat162float(h0);
    float r1 = x1 - __bfloat162float(h1);
    __nv_bfloat16 l0 = __float2bfloat16_rn(r0);
    __nv_bfloat16 l1 = __float2bfloat16_rn(r1);
    *ph = ((uint32_t)__bfloat16_as_ushort(h1)<<16) | __bfloat16_as_ushort(h0);
    *pl = ((uint32_t)__bfloat16_as_ushort(l1)<<16) | __bfloat16_as_ushort(l0);
}

#define MMA_BF16(c, a, b0, b1) \
  asm volatile("mma.sync.aligned.m16n8k16.row.col.f32.bf16.bf16.f32 " \
    "{%0,%1,%2,%3}, {%4,%5,%6,%7}, {%8,%9}, {%0,%1,%2,%3};" \
    : "+f"((c)[0]), "+f"((c)[1]), "+f"((c)[2]), "+f"((c)[3]) \
    : "r"((a)[0]), "r"((a)[1]), "r"((a)[2]), "r"((a)[3]), "r"(b0), "r"(b1))

__device__ __forceinline__ void stageB128(uint32_t* Bh, uint32_t* Bl,
    const uint32_t* Wh, const uint32_t* Wl, int hw, int k0, int tid){
    int n = tid>>1, qq = tid&1;
    const uint4* sh = (const uint4*)(Wh + (size_t)n*hw + (k0>>1)) + qq*2;
    const uint4* sl = (const uint4*)(Wl + (size_t)n*hw + (k0>>1)) + qq*2;
    uint4 h0=sh[0], h1=sh[1], l0=sl[0], l1=sl[1];
    uint32_t* dh = &Bh[n*SB + qq*8];
    uint32_t* dl = &Bl[n*SB + qq*8];
    dh[0]=h0.x; dh[1]=h0.y; dh[2]=h0.z; dh[3]=h0.w;
    dh[4]=h1.x; dh[5]=h1.y; dh[6]=h1.z; dh[7]=h1.w;
    dl[0]=l0.x; dl[1]=l0.y; dl[2]=l0.z; dl[3]=l0.w;
    dl[4]=l1.x; dl[5]=l1.y; dl[6]=l1.z; dl[7]=l1.w;
}

__device__ __forceinline__ void stageB64(uint32_t* Bh, uint32_t* Bl,
    const uint32_t* Wh, const uint32_t* Wl, int hw, int k0, int tid){
    int n = tid>>2, qq = tid&3;
    const uint4* sh = (const uint4*)(Wh + (size_t)n*hw + (k0>>1)) + qq;
    const uint4* sl = (const uint4*)(Wl + (size_t)n*hw + (k0>>1)) + qq;
    uint4 h0=sh[0], l0=sl[0];
    uint32_t* dh = &Bh[n*SB + qq*4];
    uint32_t* dl = &Bl[n*SB + qq*4];
    dh[0]=h0.x; dh[1]=h0.y; dh[2]=h0.z; dh[3]=h0.w;
    dl[0]=l0.x; dl[1]=l0.y; dl[2]=l0.z; dl[3]=l0.w;
}

__device__ __forceinline__ void fragA(const uint32_t* A, int row, int bw, int ks, int tig,
                                      int saw, uint32_t* a){
    int r0 = row*saw + bw + ks*8 + tig;
    int r1 = r0 + 8*saw;
    a[0]=A[r0]; a[1]=A[r1]; a[2]=A[r0+4]; a[3]=A[r1+4];
}

// ---------------- init / precompute ----------------
__global__ void k_init(){
    int i = blockIdx.x*blockDim.x + threadIdx.x;
    if (i < 2*NV){ d_var_sum[i]=0.f; d_lit_deg[i]=0.f; d_counts[i]=0; d_cursor[i]=0; }
    if (i < NG){ d_vmask_gsum[i]=0.f; d_wsig_gsum[i]=0.f; d_loss_sum[i]=0.f; }
    if (i <= NG){ d_cstart[i]=NC; d_vstart[i]=NV; }
    if (i == 0){ d_done=0; d_allsat=1; d_step=0; d_fc_count=0; d_csroff[2*NV]=NE; }
}

__global__ void k_init_state(){
    int i = blockIdx.x*blockDim.x + threadIdx.x;
    if (i < NC*64) d_clause_state[i]=1.f;
    if (i < NV*64) d_variables[i]=1.f;
}

__global__ void k_edge_scatter(const int* __restrict__ elit, const int* __restrict__ eclause,
                               const float* __restrict__ wsig, const float* __restrict__ wsp){
    int e = blockIdx.x*blockDim.x + threadIdx.x;
    if (e >= NE) return;
    int c = eclause[e];
    int l = elit[e];
    float w = wsig[c];
    atomicAdd(&d_var_sum[l], w*wsp[c]);
    atomicAdd(&d_lit_deg[l], w);
    atomicAdd(&d_counts[l], 1);
}

__global__ void k_scan_a(){
    int tid = threadIdx.x, lane = tid&31, wid = tid>>5;
    int i = blockIdx.x*256 + tid;
    int v = (i < NL)? d_counts[i] : 0;
    int x = v;
    #pragma unroll
    for (int o=1;o<32;o<<=1){ int t=__shfl_up_sync(0xffffffffu, x, o); if (lane>=o) x+=t; }
    __shared__ int ws[8];
    if (lane==31) ws[wid]=x;
    __syncthreads();
    if (wid==0 && lane<8){
        int w = ws[lane];
        #pragma unroll
        for (int o=1;o<8;o<<=1){ int t=__shfl_up_sync(0xffu, w, o); if (lane>=o) w+=t; }
        ws[lane]=w;
    }
    __syncthreads();
    int ex = x - v + (wid>0? ws[wid-1]:0);
    if (i < NL) d_scanex[i] = ex;
    if (tid==255) d_bsum[blockIdx.x] = ex + v;
}
__global__ void k_scan_b(){
    int tid = threadIdx.x, lane = tid&31, wid = tid>>5;
    int v = (tid < SCB)? d_bsum[tid] : 0;
    int x = v;
    #pragma unroll
    for (int o=1;o<32;o<<=1){ int t=__shfl_up_sync(0xffffffffu, x, o); if (lane>=o) x+=t; }
    __shared__ int ws[8];
    if (lane==31) ws[wid]=x;
    __syncthreads();
    if (wid==0 && lane<8){
        int w = ws[lane];
        #pragma unroll
        for (int o=1;o<8;o<<=1){ int t=__shfl_up_sync(0xffu, w, o); if (lane>=o) w+=t; }
        ws[lane]=w;
    }
    __syncthreads();
    if (tid < SCB) d_boff[tid] = x - v + (wid>0? ws[wid-1]:0);
}
__global__ void k_scan_c(){
    int i = blockIdx.x*256 + threadIdx.x;
    if (i < NL) d_csroff[i] = d_scanex[i] + d_boff[blockIdx.x];
}

__global__ void k_fill(const int* __restrict__ elit){
    int e = blockIdx.x*blockDim.x + threadIdx.x;
    if (e >= NE) return;
    int l = elit[e];
    int p = atomicAdd(&d_cursor[l], 1);
    d_csrclause[d_csroff[l]+p] = e/3;
}

__global__ void k_segmin(const int* __restrict__ cgid, const int* __restrict__ vgid){
    int i = blockIdx.x*blockDim.x + threadIdx.x;
    if (i < NC) atomicMin(&d_cstart[cgid[i]], i);
    if (i < NV) atomicMin(&d_vstart[vgid[i]], i);
}

__global__ void k_segfix(){
    if (threadIdx.x==0){
        d_cstart[NG]=NC;
        for (int g=NG-1; g>=0; g--) d_cstart[g]=min(d_cstart[g], d_cstart[g+1]);
    }
    if (threadIdx.x==1){
        d_vstart[NG]=NV;
        for (int g=NG-1; g>=0; g--) d_vstart[g]=min(d_vstart[g], d_vstart[g+1]);
    }
}

__global__ void k_var_pre(const int* __restrict__ vgid){
    int v = blockIdx.x*blockDim.x + threadIdx.x;
    if (v >= NV) return;
    float m = 1.f - expf(-(d_var_sum[v] + d_var_sum[v+NV]));
    d_vmask[v] = m;
    atomicAdd(&d_vmask_gsum[vgid[v]], m);
    float dp = d_lit_deg[v], dn = d_lit_deg[v+NV];
    d_degw[v]    = rsqrtf(fmaxf(dp,1.f));
    d_degw[v+NV] = rsqrtf(fmaxf(dn,1.f));
    d_vdw[v]     = 4.f*rsqrtf(fmaxf(dp+dn,1.f));
}

__global__ void k_clause_pre(const int* __restrict__ cgid, const float* __restrict__ wsig){
    int c = blockIdx.x*blockDim.x + threadIdx.x;
    if (c >= NC) return;
    atomicAdd(&d_wsig_gsum[cgid[c]], wsig[c]);
}

__global__ void k_norms(const int* __restrict__ cgid, const int* __restrict__ vgid,
                        const float* __restrict__ wsig){
    int i = blockIdx.x*blockDim.x + threadIdx.x;
    if (i < NC){
        float s = d_wsig_gsum[cgid[i]];
        d_cg_norm[i] = wsig[i] * (s>0.f ? 1.f/s : 0.f);
    }
    if (i < NV){
        float s = d_vmask_gsum[vgid[i]];
        d_vg_norm[i] = d_vmask[i] * (s>0.f ? 1.f/s : 0.f);
    }
}

__global__ void k_pack_w(const float* __restrict__ W, int Ktrue, int N, int Kp,
                         uint32_t* __restrict__ Wh, uint32_t* __restrict__ Wl){
    int idx = blockIdx.x*blockDim.x + threadIdx.x;
    int hw = Kp>>1;
    if (idx >= N*hw) return;
    int n = idx/hw, kp = idx-n*hw;
    int k0 = 2*kp;
    float x0 = (k0   < Ktrue)? W[(size_t)k0*N+n]     : 0.f;
    float x1 = (k0+1 < Ktrue)? W[(size_t)(k0+1)*N+n] : 0.f;
    pack2(x0, x1, &Wh[idx], &Wl[idx]);
}

// ============== fused MLP kernels ==============

__global__ void __launch_bounds__(256,2)
k_qmlp(const float* __restrict__ X1, const float* __restrict__ X2,
       const uint32_t* __restrict__ W1h, const uint32_t* __restrict__ W1l, const float* __restrict__ B1,
       const uint32_t* __restrict__ W2h, const uint32_t* __restrict__ W2l, const float* __restrict__ B2,
       float* __restrict__ Y)
{
    extern __shared__ uint32_t sm[];
    uint32_t *Ah=sm, *Al=sm+8704, *Bh=sm+17408, *Bl=sm+18688;
    int tid=threadIdx.x, lane=tid&31, wid=tid>>5;
    int g=lane>>2, tig=lane&3;
    int m0=blockIdx.x*128;

    {
        int m=tid>>1, q=tid&1, gm=m0+m;
        #pragma unroll
        for (int h=0; h<12; h++){
            int c=(q*12+h)*4;
            float4 v={0.f,0.f,0.f,0.f};
            if (gm<NV){
                if (c<64) v=*(const float4*)(X1+(size_t)gm*64+c);
                else if (c<68) v=*(const float4*)(X2+(size_t)gm*4);
            }
            int w=m*SAW+(c>>1);
            pack2(v.x,v.y,&Ah[w],&Al[w]);
            pack2(v.z,v.w,&Ah[w+1],&Al[w+1]);
        }
    }
    float acc[8][4];
    #pragma unroll
    for (int b=0;b<8;b++){ acc[b][0]=0.f; acc[b][1]=0.f; acc[b][2]=0.f; acc[b][3]=0.f; }
    for (int k0=0;k0<96;k0+=32){
        stageB64(Bh,Bl,W1h,W1l,48,k0,tid);
        __syncthreads();
        int bw=k0>>1;
        #pragma unroll
        for (int ks=0;ks<2;ks++){
            uint32_t ah[4], al[4];
            fragA(Ah, wid*16+g, bw, ks, tig, SAW, ah);
            fragA(Al, wid*16+g, bw, ks, tig, SAW, al);
            #pragma unroll
            for (int nt=0;nt<8;nt++){
                int nb=(nt*8+g)*SB + ks*8 + tig;
                uint32_t bh0=Bh[nb], bh1=Bh[nb+4], bl0=Bl[nb], bl1=Bl[nb+4];
                MMA_BF16(acc[nt], ah, bh0, bh1);
                MMA_BF16(acc[nt], ah, bl0, bl1);
                MMA_BF16(acc[nt], al, bh0, bh1);
            }
        }
        __syncthreads();
    }
    {
        int lm0 = wid*16+g;
        #pragma unroll
        for (int nt=0;nt<8;nt++){
            int col = nt*8 + 2*tig;
            float bb0=__ldg(B1+col), bb1=__ldg(B1+col+1);
            float o0=fmaxf(acc[nt][0]+bb0,0.f), o1=fmaxf(acc[nt][1]+bb1,0.f);
            float o2=fmaxf(acc[nt][2]+bb0,0.f), o3=fmaxf(acc[nt][3]+bb1,0.f);
            int wcol = nt*4+tig;
            pack2(o0,o1,&Ah[lm0*SAW+wcol],&Al[lm0*SAW+wcol]);
            pack2(o2,o3,&Ah[(lm0+8)*SAW+wcol],&Al[(lm0+8)*SAW+wcol]);
        }
    }
    #pragma unroll
    for (int b=0;b<8;b++){ acc[b][0]=0.f; acc[b][1]=0.f; acc[b][2]=0.f; acc[b][3]=0.f; }
    __syncthreads();
    for (int k0=0;k0<64;k0+=32){
        stageB64(Bh,Bl,W2h,W2l,32,k0,tid);
        __syncthreads();
        int bw=k0>>1;
        #pragma unroll
        for (int ks=0;ks<2;ks++){
            uint32_t ah[4], al[4];
            fragA(Ah, wid*16+g, bw, ks, tig, SAW, ah);
            fragA(Al, wid*16+g, bw, ks, tig, SAW, al);
            #pragma unroll
            for (int nt=0;nt<8;nt++){
                int nb=(nt*8+g)*SB + ks*8 + tig;
                uint32_t bh0=Bh[nb], bh1=Bh[nb+4], bl0=Bl[nb], bl1=Bl[nb+4];
                MMA_BF16(acc[nt], ah, bh0, bh1);
                MMA_BF16(acc[nt], ah, bl0, bl1);
                MMA_BF16(acc[nt], al, bh0, bh1);
            }
        }
        __syncthreads();
    }
    int rm0 = m0 + wid*16 + g, rm1 = rm0 + 8;
    #pragma unroll
    for (int nt=0;nt<8;nt++){
        int col = nt*8 + 2*tig;
        float bb0=__ldg(B2+col), bb1=__ldg(B2+col+1);
        if (rm0<NV) *(float2*)(Y+(size_t)rm0*64+col) = make_float2(acc[nt][0]+bb0, acc[nt][1]+bb1);
        if (rm1<NV) *(float2*)(Y+(size_t)rm1*64+col) = make_float2(acc[nt][2]+bb0, acc[nt][3]+bb1);
    }
}

__global__ void __launch_bounds__(256,2)
k_cmlp(const float* __restrict__ X1, const float* __restrict__ X2,
       const uint32_t* __restrict__ W1h, const uint32_t* __restrict__ W1l, const float* __restrict__ B1,
       const uint32_t* __restrict__ W2h, const uint32_t* __restrict__ W2l, const float* __restrict__ B2,
       float* __restrict__ Y)
{
    extern __shared__ uint32_t sm[];
    uint32_t *Ah=sm, *Al=sm+8704, *Bh=sm+17408, *Bl=sm+19968;
    int tid=threadIdx.x, lane=tid&31, wid=tid>>5;
    int warp_m=wid>>1, warp_n=wid&1, g=lane>>2, tig=lane&3;
    int m0=blockIdx.x*128;

    {
        int m=tid>>1, q=tid&1, gm=m0+m;
        #pragma unroll
        for (int h=0; h<16; h++){
            int c=(q*16+h)*4;
            float4 v={0.f,0.f,0.f,0.f};
            if (gm<NC){
                if (c<64) v=*(const float4*)(X1+(size_t)gm*64+c);
                else {
                    v=*(const float4*)(X2+(size_t)gm*64+(c-64));
                    v.x*=4.f; v.y*=4.f; v.z*=4.f; v.w*=4.f;
                }
            }
            int w=m*SAW+(c>>1);
            pack2(v.x,v.y,&Ah[w],&Al[w]);
            pack2(v.z,v.w,&Ah[w+1],&Al[w+1]);
        }
    }
    float acc[2][8][4];
    #pragma unroll
    for (int a=0;a<2;a++)
        #pragma unroll
        for (int b=0;b<8;b++){ acc[a][b][0]=0.f; acc[a][b][1]=0.f; acc[a][b][2]=0.f; acc[a][b][3]=0.f; }
    for (int k0=0;k0<128;k0+=32){
        stageB128(Bh,Bl,W1h,W1l,64,k0,tid);
        __syncthreads();
        int bw=k0>>1;
        #pragma unroll
        for (int ks=0;ks<2;ks++){
            uint32_t ah[2][4], al[2][4];
            #pragma unroll
            for (int mt=0;mt<2;mt++){
                fragA(Ah, warp_m*32+mt*16+g, bw, ks, tig, SAW, ah[mt]);
                fragA(Al, warp_m*32+mt*16+g, bw, ks, tig, SAW, al[mt]);
            }
            #pragma unroll
            for (int nt=0;nt<8;nt++){
                int nb=(warp_n*64+nt*8+g)*SB + ks*8 + tig;
                uint32_t bh0=Bh[nb], bh1=Bh[nb+4], bl0=Bl[nb], bl1=Bl[nb+4];
                #pragma unroll
                for (int mt=0;mt<2;mt++){
                    MMA_BF16(acc[mt][nt], ah[mt], bh0, bh1);
                    MMA_BF16(acc[mt][nt], ah[mt], bl0, bl1);
                    MMA_BF16(acc[mt][nt], al[mt], bh0, bh1);
                }
            }
        }
        __syncthreads();
    }
    #pragma unroll
    for (int mt=0;mt<2;mt++){
        int lm0 = warp_m*32+mt*16+g;
        #pragma unroll
        for (int nt=0;nt<8;nt++){
            int col = warp_n*64 + nt*8 + 2*tig;
            float bb0=__ldg(B1+col), bb1=__ldg(B1+col+1);
            float o0=fmaxf(acc[mt][nt][0]+bb0,0.f), o1=fmaxf(acc[mt][nt][1]+bb1,0.f);
            float o2=fmaxf(acc[mt][nt][2]+bb0,0.f), o3=fmaxf(acc[mt][nt][3]+bb1,0.f);
            int wcol = warp_n*32 + nt*4 + tig;
            pack2(o0,o1,&Ah[lm0*SAW+wcol],&Al[lm0*SAW+wcol]);
            pack2(o2,o3,&Ah[(lm0+8)*SAW+wcol],&Al[(lm0+8)*SAW+wcol]);
            acc[mt][nt][0]=0.f; acc[mt][nt][1]=0.f; acc[mt][nt][2]=0.f; acc[mt][nt][3]=0.f;
        }
    }
    __syncthreads();
    for (int k0=0;k0<128;k0+=32){
        stageB128(Bh,Bl,W2h,W2l,64,k0,tid);
        __syncthreads();
        int bw=k0>>1;
        #pragma unroll
        for (int ks=0;ks<2;ks++){
            uint32_t ah[2][4], al[2][4];
            #pragma unroll
            for (int mt=0;mt<2;mt++){
                fragA(Ah, warp_m*32+mt*16+g, bw, ks, tig, SAW, ah[mt]);
                fragA(Al, warp_m*32+mt*16+g, bw, ks, tig, SAW, al[mt]);
            }
            #pragma unroll
            for (int nt=0;nt<8;nt++){
                int nb=(warp_n*64+nt*8+g)*SB + ks*8 + tig;
                uint32_t bh0=Bh[nb], bh1=Bh[nb+4], bl0=Bl[nb], bl1=Bl[nb+4];
                #pragma unroll
                for (int mt=0;mt<2;mt++){
                    MMA_BF16(acc[mt][nt], ah[mt], bh0, bh1);
                    MMA_BF16(acc[mt][nt], ah[mt], bl0, bl1);
                    MMA_BF16(acc[mt][nt], al[mt], bh0, bh1);
                }
            }
        }
        __syncthreads();
    }
    #pragma unroll
    for (int mt=0;mt<2;mt++){
        int rm0 = m0 + warp_m*32 + mt*16 + g, rm1 = rm0 + 8;
        #pragma unroll
        for (int nt=0;nt<8;nt++){
            int col = warp_n*64 + nt*8 + 2*tig;
            float bb0=__ldg(B2+col), bb1=__ldg(B2+col+1);
            if (rm0<NC) *(float2*)(Y+(size_t)rm0*128+col) = make_float2(acc[mt][nt][0]+bb0, acc[mt][nt][1]+bb1);
            if (rm1<NC) *(float2*)(Y+(size_t)rm1*128+col) = make_float2(acc[mt][nt][2]+bb0, acc[mt][nt][3]+bb1);
        }
    }
}

__global__ void __launch_bounds__(256,2)
k_umlp(const float* __restrict__ X1,
       const uint32_t* __restrict__ W1h, const uint32_t* __restrict__ W1l, const float* __restrict__ B1,
       const uint32_t* __restrict__ W2h, const uint32_t* __restrict__ W2l, const float* __restrict__ B2,
       const uint32_t* __restrict__ W3h, const uint32_t* __restrict__ W3l, const float* __restrict__ B3,
       float* __restrict__ Y)
{
    extern __shared__ uint32_t sm[];
    uint32_t *Ah=sm, *Al=sm+8704, *Bh=sm+17408, *Bl=sm+19968;
    int tid=threadIdx.x, lane=tid&31, wid=tid>>5;
    int warp_m=wid>>1, warp_n=wid&1, g=lane>>2, tig=lane&3;
    int m0=blockIdx.x*128;

    float acc[2][8][4];
    #pragma unroll
    for (int a=0;a<2;a++)
        #pragma unroll
        for (int b=0;b<8;b++){ acc[a][b][0]=0.f; acc[a][b][1]=0.f; acc[a][b][2]=0.f; acc[a][b][3]=0.f; }

    int m=tid>>1, q=tid&1, gm=m0+m;
    for (int k0=0;k0<256;k0+=32){
        #pragma unroll
        for (int h=0;h<4;h++){
            int c = k0 + (q*4+h)*4;
            float4 v={0.f,0.f,0.f,0.f};
            if (gm<NV) v=*(const float4*)(X1+(size_t)gm*256+c);
            int kp=(q*4+h)*2;
            pack2(v.x,v.y,&Ah[m*SAW+kp],  &Al[m*SAW+kp]);
            pack2(v.z,v.w,&Ah[m*SAW+kp+1],&Al[m*SAW+kp+1]);
        }
        stageB128(Bh,Bl,W1h,W1l,128,k0,tid);
        __syncthreads();
        #pragma unroll
        for (int ks=0;ks<2;ks++){
            uint32_t ah[2][4], al[2][4];
            #pragma unroll
            for (int mt=0;mt<2;mt++){
                fragA(Ah, warp_m*32+mt*16+g, 0, ks, tig, SAW, ah[mt]);
                fragA(Al, warp_m*32+mt*16+g, 0, ks, tig, SAW, al[mt]);
            }
            #pragma unroll
            for (int nt=0;nt<8;nt++){
                int nb=(warp_n*64+nt*8+g)*SB + ks*8 + tig;
                uint32_t bh0=Bh[nb], bh1=Bh[nb+4], bl0=Bl[nb], bl1=Bl[nb+4];
                #pragma unroll
                for (int mt=0;mt<2;mt++){
                    MMA_BF16(acc[mt][nt], ah[mt], bh0, bh1);
                    MMA_BF16(acc[mt][nt], ah[mt], bl0, bl1);
                    MMA_BF16(acc[mt][nt], al[mt], bh0, bh1);
                }
            }
        }
        __syncthreads();
    }
    #pragma unroll
    for (int mt=0;mt<2;mt++){
        int lm0 = warp_m*32+mt*16+g;
        #pragma unroll
        for (int nt=0;nt<8;nt++){
            int col = warp_n*64 + nt*8 + 2*tig;
            float bb0=__ldg(B1+col), bb1=__ldg(B1+col+1);
            float o0=fmaxf(acc[mt][nt][0]+bb0,0.f), o1=fmaxf(acc[mt][nt][1]+bb1,0.f);
            float o2=fmaxf(acc[mt][nt][2]+bb0,0.f), o3=fmaxf(acc[mt][nt][3]+bb1,0.f);
            int wcol = warp_n*32 + nt*4 + tig;
            pack2(o0,o1,&Ah[lm0*SAW+wcol],&Al[lm0*SAW+wcol]);
            pack2(o2,o3,&Ah[(lm0+8)*SAW+wcol],&Al[(lm0+8)*SAW+wcol]);
            acc[mt][nt][0]=0.f; acc[mt][nt][1]=0.f; acc[mt][nt][2]=0.f; acc[mt][nt][3]=0.f;
        }
    }
    __syncthreads();
    for (int k0=0;k0<128;k0+=32){
        stageB128(Bh,Bl,W2h,W2l,64,k0,tid);
        __syncthreads();
        int bw=k0>>1;
        #pragma unroll
        for (int ks=0;ks<2;ks++){
            uint32_t ah[2][4], al[2][4];
            #pragma unroll
            for (int mt=0;mt<2;mt++){
                fragA(Ah, warp_m*32+mt*16+g, bw, ks, tig, SAW, ah[mt]);
                fragA(Al, warp_m*32+mt*16+g, bw, ks, tig, SAW, al[mt]);
            }
            #pragma unroll
            for (int nt=0;nt<8;nt++){
                int nb=(warp_n*64+nt*8+g)*SB + ks*8 + tig;
                uint32_t bh0=Bh[nb], bh1=Bh[nb+4], bl0=Bl[nb], bl1=Bl[nb+4];
                #pragma unroll
                for (int mt=0;mt<2;mt++){
                    MMA_BF16(acc[mt][nt], ah[mt], bh0, bh1);
                    MMA_BF16(acc[mt][nt], ah[mt], bl0, bl1);
                    MMA_BF16(acc[mt][nt], al[mt], bh0, bh1);
                }
            }
        }
        __syncthreads();
    }
    #pragma unroll
    for (int mt=0;mt<2;mt++){
        int lm0 = warp_m*32+mt*16+g;
        #pragma unroll
        for (int nt=0;nt<8;nt++){
            int col = warp_n*64 + nt*8 + 2*tig;
            float bb0=__ldg(B2+col), bb1=__ldg(B2+col+1);
            float o0=fmaxf(acc[mt][nt][0]+bb0,0.f), o1=fmaxf(acc[mt][nt][1]+bb1,0.f);
            float o2=fmaxf(acc[mt][nt][2]+bb0,0.f), o3=fmaxf(acc[mt][nt][3]+bb1,0.f);
            int wcol = warp_n*32 + nt*4 + tig;
            pack2(o0,o1,&Ah[lm0*SAW+wcol],&Al[lm0*SAW+wcol]);
            pack2(o2,o3,&Ah[(lm0+8)*SAW+wcol],&Al[(lm0+8)*SAW+wcol]);
        }
    }
    __syncthreads();
    float acc3[8][4];
    #pragma unroll
    for (int b=0;b<8;b++){ acc3[b][0]=0.f; acc3[b][1]=0.f; acc3[b][2]=0.f; acc3[b][3]=0.f; }
    for (int k0=0;k0<128;k0+=32){
        stageB64(Bh,Bl,W3h,W3l,64,k0,tid);
        __syncthreads();
        int bw=k0>>1;
        #pragma unroll
        for (int ks=0;ks<2;ks++){
            uint32_t ah[4], al[4];
            fragA(Ah, wid*16+g, bw, ks, tig, SAW, ah);
            fragA(Al, wid*16+g, bw, ks, tig, SAW, al);
            #pragma unroll
            for (int nt=0;nt<8;nt++){
                int nb=(nt*8+g)*SB + ks*8 + tig;
                uint32_t bh0=Bh[nb], bh1=Bh[nb+4], bl0=Bl[nb], bl1=Bl[nb+4];
                MMA_BF16(acc3[nt], ah, bh0, bh1);
                MMA_BF16(acc3[nt], ah, bl0, bl1);
                MMA_BF16(acc3[nt], al, bh0, bh1);
            }
        }
        __syncthreads();
    }
    int rm0 = m0 + wid*16 + g, rm1 = rm0 + 8;
    #pragma unroll
    for (int nt=0;nt<8;nt++){
        int col = nt*8 + 2*tig;
        float bb0=__ldg(B3+col), bb1=__ldg(B3+col+1);
        if (rm0<NV) *(float2*)(Y+(size_t)rm0*64+col) = make_float2(acc3[nt][0]+bb0, acc3[nt][1]+bb1);
        if (rm1<NV) *(float2*)(Y+(size_t)rm1*64+col) = make_float2(acc3[nt][2]+bb0, acc3[nt][3]+bb1);
    }
}

__global__ void __launch_bounds__(256,2)
k_fused_o(const int* __restrict__ vgid,
          const uint32_t* __restrict__ Wh, const uint32_t* __restrict__ Wl,
          const float* __restrict__ Bias,
          const float* __restrict__ ow2, const float* __restrict__ ob2)
{
    __shared__ uint32_t Ah[128*SB], Al[128*SB], Bh[64*SB], Bl[64*SB];
    int tid = threadIdx.x, lane = tid&31, wid = tid>>5;
    int g = lane>>2, tig = lane&3;
    int m0 = blockIdx.x*128;
    if (blockIdx.x==0 && tid==0) d_allsat = 1;
    int done = d_done;

    float acc[8][4];
    #pragma unroll
    for (int b=0;b<8;b++){ acc[b][0]=0.f; acc[b][1]=0.f; acc[b][2]=0.f; acc[b][3]=0.f; }

    int m = tid>>1, q = tid&1, gm = m0+m;
    float rs = 0.f; const float* mrow = nullptr;
    if (gm < NV){
        int gg = vgid[gm];
        rs = rsqrtf(d_varred[gg]+1e-6f)*0.25f;
        mrow = &d_mean[gg*64];
    }

    for (int k0=0; k0<64; k0+=32){
        #pragma unroll
        for (int h=0; h<4; h++){
            int c = k0 + (q*4+h)*4;
            float4 v = {0.f,0.f,0.f,0.f};
            if (gm < NV){
                float4 vv = *(const float4*)(d_variables + (size_t)gm*64 + c);
                if (done) v = vv;
                else {
                    float4 u = *(const float4*)(d_uout + (size_t)gm*64 + c);
                    v.x = (u.x - mrow[c  ])*rs + 0.1f*vv.x;
                    v.y = (u.y - mrow[c+1])*rs + 0.1f*vv.y;
                    v.z = (u.z - mrow[c+2])*rs + 0.1f*vv.z;
                    v.w = (u.w - mrow[c+3])*rs + 0.1f*vv.w;
                    *(float4*)(d_variables + (size_t)gm*64 + c) = v;
                }
            }
            int kp = (q*4+h)*2;
            pack2(v.x,v.y,&Ah[m*SB+kp],  &Al[m*SB+kp]);
            pack2(v.z,v.w,&Ah[m*SB+kp+1],&Al[m*SB+kp+1]);
        }
        stageB64(Bh,Bl,Wh,Wl,32,k0,tid);
        __syncthreads();
        #pragma unroll
        for (int ks=0; ks<2; ks++){
            uint32_t ah[4], al[4];
            fragA(Ah, wid*16+g, 0, ks, tig, SB, ah);
            fragA(Al, wid*16+g, 0, ks, tig, SB, al);
            #pragma unroll
            for (int nt=0; nt<8; nt++){
                int nb = (nt*8+g)*SB + ks*8 + tig;
                uint32_t bh0=Bh[nb], bh1=Bh[nb+4], bl0=Bl[nb], bl1=Bl[nb+4];
                MMA_BF16(acc[nt], ah, bh0, bh1);
                MMA_BF16(acc[nt], ah, bl0, bl1);
                MMA_BF16(acc[nt], al, bh0, bh1);
            }
        }
        __syncthreads();
    }
    float p0=0.f, p1=0.f;
    #pragma unroll
    for (int nt=0; nt<8; nt++){
        int col = nt*8 + 2*tig;
        float bb0 = __ldg(Bias+col), bb1 = __ldg(Bias+col+1);
        float w0 = __ldg(ow2+col),  w1 = __ldg(ow2+col+1);
        float o0=fmaxf(acc[nt][0]+bb0,0.f), o1=fmaxf(acc[nt][1]+bb1,0.f);
        float o2=fmaxf(acc[nt][2]+bb0,0.f), o3=fmaxf(acc[nt][3]+bb1,0.f);
        p0 += o0*w0 + o1*w1;
        p1 += o2*w0 + o3*w1;
    }
    p0 += __shfl_xor_sync(0xffffffffu, p0, 1);
    p0 += __shfl_xor_sync(0xffffffffu, p0, 2);
    p1 += __shfl_xor_sync(0xffffffffu, p1, 1);
    p1 += __shfl_xor_sync(0xffffffffu, p1, 2);
    if (tig==0){
        float ob = __ldg(ob2);
        int rm0 = m0 + wid*16 + g, rm1 = rm0 + 8;
        if (rm0 < NV){
            float lg = p0 + ob;
            d_logits[rm0] = lg;
            if (!done) d_last_logits[rm0] = lg;
        }
        if (rm1 < NV){
            float lg = p1 + ob;
            d_logits[rm1] = lg;
            if (!done) d_last_logits[rm1] = lg;
        }
    }
}

// ---------------- per-round kernels ----------------
__global__ void k_clause_cval(const int* __restrict__ elit, const float* __restrict__ wsig){
    int gw = (blockIdx.x*blockDim.x + threadIdx.x)>>5;
    int lane = threadIdx.x & 31;
    if (gw >= NC) return;
    float w = wsig[gw];
    float2 acc = {0.f,0.f};
    #pragma unroll
    for (int j=0;j<3;j++){
        int l = elit[3*gw+j];
        int v = (l<NV)? l : l-NV;
        float sgn = (l<NV)? 1.f : -1.f;
        float2 qv = *(const float2*)(d_query + (size_t)v*64 + lane*2);
        acc.x += sp_f(sgn*qv.x);
        acc.y += sp_f(sgn*qv.y);
    }
    float2 cl = { expf(-w*acc.x), expf(-w*acc.y) };
    *(float2*)(d_closs + (size_t)gw*64 + lane*2) = cl;
}

// UNION (no dynamic smem, matched resources):
//   blocks [0,NG): clause pair_norm (stats + apply)
//   blocks [NG, NG+VGB): merged var_grad + var_loss (single CSR walk)
__global__ void k_pnc_vg(const float* __restrict__ wsig){
    __shared__ float r1[256], r2[256];
    __shared__ float smean[64];
    __shared__ float srs;
    int tid=threadIdx.x, lane=tid&31, wid=tid>>5;

    if (blockIdx.x >= NG){
        // ---- merged var_grad + var_loss ----
        int v = (blockIdx.x-NG)*8 + wid;
        if (v >= NV) return;
        float2 apc={0.f,0.f}, anc={0.f,0.f};   // closs accumulators
        float2 apd={0.f,0.f}, andv={0.f,0.f};  // cdata accumulators
        int s0=d_csroff[v], e0=d_csroff[v+1];
        for (int i=s0;i<e0;i++){
            int c = d_csrclause[i];
            float w = wsig[c];
            float2 cl = *(const float2*)(d_closs + (size_t)c*64  + lane*2);
            float2 cd = *(const float2*)(d_cdata + (size_t)c*128 + lane*2);
            apc.x += w*cl.x; apc.y += w*cl.y;
            apd.x += w*cd.x; apd.y += w*cd.y;
        }
        int s1=d_csroff[NV+v], e1=d_csroff[NV+v+1];
        for (int i=s1;i<e1;i++){
            int c = d_csrclause[i];
            float w = wsig[c];
            float2 cl = *(const float2*)(d_closs + (size_t)c*64  + lane*2);
            float2 cd = *(const float2*)(d_cdata + (size_t)c*128 + lane*2);
            anc.x += w*cl.x; anc.y += w*cl.y;
            andv.x += w*cd.x; andv.y += w*cd.y;
        }
        float2 qv = *(const float2*)(d_query + (size_t)v*64 + lane*2);
        float vd = d_vdw[v];
        float2 gg;
        gg.x = (-apc.x*sigm(qv.x) + anc.x*sigm(-qv.x)) * vd;
        gg.y = (-apc.y*sigm(qv.y) + anc.y*sigm(-qv.y)) * vd;
        *(float2*)(d_unit + (size_t)v*256 + lane*2) = gg;
        float2 vv = *(const float2*)(d_variables + (size_t)v*64 + lane*2);
        *(float2*)(d_unit + (size_t)v*256 + 64 + lane*2) = vv;
        float dp = d_degw[v], dn = d_degw[NV+v];
        *(float2*)(d_unit + (size_t)v*256 + 128 + lane*2) = make_float2(apd.x*dp, apd.y*dp);
        *(float2*)(d_unit + (size_t)v*256 + 192 + lane*2) = make_float2(andv.x*dn, andv.y*dn);
        return;
    }

    // ---- clause pair_norm ----
    int g=blockIdx.x;
    int s=d_cstart[g], e=d_cstart[g+1];
    int f=tid&63, grp=tid>>6;
    float s1=0.f, s2=0.f;
    for (int r=s+grp; r<e; r+=4){
        float wr = d_cg_norm[r];
        float xv = d_cdata[(size_t)r*128 + 64 + f];
        float wx = wr*xv;
        s1 += wx; s2 += wx*xv;
    }
    r1[tid]=s1; r2[tid]=s2; __syncthreads();
    if (tid<64){
        float S1 = r1[f]+r1[64+f]+r1[128+f]+r1[192+f];
        float S2 = r2[f]+r2[64+f]+r2[128+f]+r2[192+f];
        smean[f]=S1;
        r1[f] = S2 - S1*S1;
    }
    __syncthreads();
    if (tid<32){
        float v = r1[tid]+r1[tid+32];
        for (int o=16;o;o>>=1) v += __shfl_down_sync(0xffffffffu, v, o);
        if (tid==0) srs = rsqrtf(v*(1.f/64.f)+1e-6f)*0.25f;
    }
    __syncthreads();
    if (d_done) return;
    float rs = srs;
    int total = (e-s)*64;
    for (int idx=tid; idx<total; idx+=256){
        int r = s + (idx>>6);
        int ff = idx&63;
        float xc = d_cdata[(size_t)r*128 + 64 + ff] - smean[ff];
        size_t o = (size_t)r*64 + ff;
        d_clause_state[o] = xc*rs + 0.1f*d_clause_state[o];
    }
}

__global__ void k_pn_stats_v(){
    int g=blockIdx.x;
    int s=d_vstart[g], e=d_vstart[g+1];
    int f=threadIdx.x&63, grp=threadIdx.x>>6;
    float s1=0.f, s2=0.f;
    for (int r=s+grp; r<e; r+=4){
        float wr = d_vg_norm[r];
        float xv = d_uout[(size_t)r*64+f];
        float wx = wr*xv;
        s1 += wx; s2 += wx*xv;
    }
    __shared__ float r1[256], r2[256];
    r1[threadIdx.x]=s1; r2[threadIdx.x]=s2; __syncthreads();
    if (threadIdx.x<64){
        float S1 = r1[f]+r1[64+f]+r1[128+f]+r1[192+f];
        float S2 = r2[f]+r2[64+f]+r2[128+f]+r2[192+f];
        d_mean[g*64+f]=S1;
        r1[f] = S2 - S1*S1;
    }
    __syncthreads();
    if (threadIdx.x<32){
        float v = r1[threadIdx.x]+r1[threadIdx.x+32];
        for (int o=16;o;o>>=1) v += __shfl_down_sync(0xffffffffu, v, o);
        if (threadIdx.x==0) d_varred[g]=v*(1.f/64.f);
    }
}

__global__ void k_final_clause(const int* __restrict__ elit, const float* __restrict__ wsig){
    __shared__ float sred[256];
    __shared__ int ssat[256];
    __shared__ int slast;
    int g = blockIdx.x;
    int s = d_cstart[g], e = d_cstart[g+1];
    float lsum=0.f; int sat=1;
    for (int c=s+threadIdx.x; c<e; c+=blockDim.x){
        float w = wsig[c];
        float cvs=0.f, csat=0.f;
        #pragma unroll
        for (int j=0;j<3;j++){
            int l = elit[3*c+j];
            int v = (l<NV)? l : l-NV;
            float sgn = (l<NV)? 1.f : -1.f;
            float lg = d_logits[v];
            cvs += sp_f(sgn*lg);
            float a = (lg>0.f)? 1.f : 0.f;
            float lit01 = (l<NV)? a : 1.f-a;
            csat += w*lit01;
        }
        float cv = expf(-w*cvs);
        float pc = cv * (-logf(1.f - cv + 1e-10f));
        lsum += pc*w;
        if (csat < 1.f) sat = 0;
    }
    sred[threadIdx.x]=lsum; ssat[threadIdx.x]=sat; __syncthreads();
    for (int o=128;o;o>>=1){
        if (threadIdx.x<o){ sred[threadIdx.x]+=sred[threadIdx.x+o]; ssat[threadIdx.x]&=ssat[threadIdx.x+o]; }
        __syncthreads();
    }
    if (threadIdx.x==0){
        d_pg[g]=sred[0];
        if (!ssat[0]) d_allsat = 0;
        __threadfence();
        slast = (atomicAdd(&d_fc_count,1) == NG-1);
    }
    __syncthreads();
    if (slast){
        __threadfence();
        int done0 = d_done;
        if (!done0 && threadIdx.x < NG)
            d_loss_sum[threadIdx.x] += sqrtf(d_pg[threadIdx.x]+1e-6f) - 0.001f;
        __syncthreads();
        if (threadIdx.x==0){
            if (!done0){
                d_step++;
                if (d_allsat) d_done = 1;
            }
            d_fc_count = 0;
        }
    }
}

__global__ void k_output(float* __restrict__ out, int n){
    int i = blockIdx.x*blockDim.x + threadIdx.x;
    if (i >= n) return;
    float v;
    if (i < NV)            v = d_last_logits[i];
    else if (i < NV+NG)    v = d_loss_sum[i-NV]*(1.f/(float)RNDS);
    else if (i == NV+NG)   v = (float)d_step;
    else                   v = 0.f;
    out[i] = v;
}

// ---------------- host ----------------
extern "C" void kernel_launch(void* const* d_in, const int* in_sizes, int n_in,
                              void* d_out, int out_size){
    const float* wsig   = (const float*)d_in[0];
    const float* wsp    = (const float*)d_in[1];
    const float* noise  = (const float*)d_in[2];
    const int*   elit   = (const int*)d_in[3];
    const int*   eclause= (const int*)d_in[4];
    const int*   cgid   = (const int*)d_in[5];
    const int*   vgid   = (const int*)d_in[6];
    const float* P[18];
    for (int i=0;i<18;i++) P[i]=(const float*)d_in[7+i];
    const float *qw1=P[0],*qb1=P[1],*qw2=P[2],*qb2=P[3];
    const float *cw1=P[4],*cb1=P[5],*cw2=P[6],*cb2=P[7];
    const float *uw1=P[8],*ub1=P[9],*uw2=P[10],*ub2=P[11],*uw3=P[12],*ub3=P[13];
    const float *ow1=P[14],*ob1=P[15],*ow2=P[16],*ob2=P[17];

    float *p_query,*p_cdata,*p_unit,*p_uout,*p_vars,*p_cs,*p_closs;
    uint32_t *p_wh, *p_wl;
    cudaGetSymbolAddress((void**)&p_query, d_query);
    cudaGetSymbolAddress((void**)&p_cdata, d_cdata);
    cudaGetSymbolAddress((void**)&p_unit,  d_unit);
    cudaGetSymbolAddress((void**)&p_uout,  d_uout);
    cudaGetSymbolAddress((void**)&p_vars,  d_variables);
    cudaGetSymbolAddress((void**)&p_cs,    d_clause_state);
    cudaGetSymbolAddress((void**)&p_closs, d_closs);
    cudaGetSymbolAddress((void**)&p_wh,    d_wh);
    cudaGetSymbolAddress((void**)&p_wl,    d_wl);

    const int GVg = CEILDIV(NV,128);   // 157
    const int GCg = CEILDIV(NC,128);   // 657

    const int OQ1=0, OQ2=3072, OC1=5120, OC2=13312, OU1=21504, OU2=37888, OU3=46080, OO1=50176;

    const int QSMEM = 19968*4;
    const int CSMEM = 22528*4;
    cudaFuncSetAttribute(k_qmlp, cudaFuncAttributeMaxDynamicSharedMemorySize, QSMEM);
    cudaFuncSetAttribute(k_cmlp, cudaFuncAttributeMaxDynamicSharedMemorySize, CSMEM);
    cudaFuncSetAttribute(k_umlp, cudaFuncAttributeMaxDynamicSharedMemorySize, CSMEM);

    // ---- init / precompute ----
    k_init<<<CEILDIV(2*NV,256),256>>>();
    k_init_state<<<CEILDIV(NC*64,256),256>>>();
    k_edge_scatter<<<CEILDIV(NE,256),256>>>(elit, eclause, wsig, wsp);
    k_scan_a<<<SCB,256>>>();
    k_scan_b<<<1,256>>>();
    k_scan_c<<<SCB,256>>>();
    k_fill<<<CEILDIV(NE,256),256>>>(elit);
    k_segmin<<<CEILDIV(NC,256),256>>>(cgid, vgid);
    k_segfix<<<1,32>>>();
    k_var_pre<<<CEILDIV(NV,256),256>>>(vgid);
    k_clause_pre<<<CEILDIV(NC,256),256>>>(cgid, wsig);
    k_norms<<<CEILDIV(NC,256),256>>>(cgid, vgid, wsig);

    // ---- pack weights ----
    k_pack_w<<<CEILDIV(64*48,256),256>>>(qw1,  68, 64, 96, p_wh+OQ1, p_wl+OQ1);
    k_pack_w<<<CEILDIV(64*32,256),256>>>(qw2,  64, 64, 64, p_wh+OQ2, p_wl+OQ2);
    k_pack_w<<<CEILDIV(128*64,256),256>>>(cw1, 128,128,128, p_wh+OC1, p_wl+OC1);
    k_pack_w<<<CEILDIV(128*64,256),256>>>(cw2, 128,128,128, p_wh+OC2, p_wl+OC2);
    k_pack_w<<<CEILDIV(128*128,256),256>>>(uw1,256,128,256, p_wh+OU1, p_wl+OU1);
    k_pack_w<<<CEILDIV(128*64,256),256>>>(uw2, 128,128,128, p_wh+OU2, p_wl+OU2);
    k_pack_w<<<CEILDIV(64*64,256),256>>>(uw3, 128, 64,128, p_wh+OU3, p_wl+OU3);
    k_pack_w<<<CEILDIV(64*32,256),256>>>(ow1,  64, 64, 64, p_wh+OO1, p_wl+OO1);

    // ---- rounds (8 kernels each, single stream, zero event nodes) ----
    for (int t=0; t<RNDS; t++){
        const float* nt = noise + (size_t)t*NV*4;
        k_qmlp<<<GVg,256,QSMEM>>>(p_vars, nt, p_wh+OQ1, p_wl+OQ1, qb1,
                                  p_wh+OQ2, p_wl+OQ2, qb2, p_query);
        k_clause_cval<<<CEILDIV(NC*32,256),256>>>(elit, wsig);
        k_cmlp<<<GCg,256,CSMEM>>>(p_cs, p_closs, p_wh+OC1, p_wl+OC1, cb1,
                                  p_wh+OC2, p_wl+OC2, cb2, p_cdata);
        k_pnc_vg<<<NG+VGB,256>>>(wsig);
        k_umlp<<<GVg,256,CSMEM>>>(p_unit, p_wh+OU1, p_wl+OU1, ub1,
                                  p_wh+OU2, p_wl+OU2, ub2,
                                  p_wh+OU3, p_wl+OU3, ub3, p_uout);
        k_pn_stats_v<<<NG,256>>>();
        k_fused_o<<<GVg,256>>>(vgid, p_wh+OO1, p_wl+OO1, ob1, ow2, ob2);
        k_final_clause<<<NG,256>>>(elit, wsig);
    }

    k_output<<<CEILDIV(out_size>0?out_size:1,256),256>>>((float*)d_out, out_size);
}